// round 3
// baseline (speedup 1.0000x reference)
#include <cuda_runtime.h>

// ---------------- problem constants ----------------
#define TOK    4096        // BATCH*SEQLEN
#define DMODEL 2048
#define DINNER 4096
#define NH     64
#define HD     64
#define NST    128
#define CDIM   4352        // DINNER + 2*NST
#define DPROJ  8512        // 2*DINNER + 2*NST + NH
#define SEQ    2048
#define CK     256         // chunk length
#define NCC    16          // BATCH * (SEQ/CK) total chunks

// ---------------- scratch (device globals; no allocation) ----------------
__device__ __align__(16) float g_zx  [(size_t)TOK*DPROJ];
__device__ __align__(16) float g_xbc [(size_t)TOK*CDIM];
__device__ __align__(16) float g_Ct  [(size_t)NST*TOK];
__device__ __align__(16) float g_dtv [(size_t)TOK*NH];
__device__ __align__(16) float g_dacs[(size_t)NCC*NH*CK];
__device__ __align__(16) float g_cb  [(size_t)NCC*CK*CK];
__device__ __align__(16) float g_st  [(size_t)NCC*NH*HD*NST];
__device__ __align__(16) float g_pv  [(size_t)NCC*NH*HD*NST];
__device__ __align__(16) float g_y   [(size_t)TOK*DINNER];

// ---------------- tf32 helpers ----------------
__device__ __forceinline__ unsigned f2tf(float x) {
    unsigned r; asm("cvt.rna.tf32.f32 %0, %1;" : "=r"(r) : "f"(x)); return r;
}
__device__ __forceinline__ void mma_tf32(float& c0, float& c1, float& c2, float& c3,
                                         unsigned a0, unsigned a1, unsigned a2, unsigned a3,
                                         unsigned b0, unsigned b1) {
    asm volatile("mma.sync.aligned.m16n8k8.row.col.f32.tf32.tf32.f32 "
                 "{%0,%1,%2,%3}, {%4,%5,%6,%7}, {%8,%9}, {%0,%1,%2,%3};"
                 : "+f"(c0), "+f"(c1), "+f"(c2), "+f"(c3)
                 : "r"(a0), "r"(a1), "r"(a2), "r"(a3), "r"(b0), "r"(b1));
}

// ============ big GEMM: BM=256, BN=64, BK=16, double-buffered ============
// C[m,n] = sum_k A[m,k] * B[n,k].  smem layout [k][m] / [k][n], strides ≡ 8 mod 32
// => STS scatter and all fragment LDS are bank-conflict-free.
#define KSTR 264   // 256 + 8
#define BSTR 72    // 64 + 8
__global__ __launch_bounds__(256) void gemm_big(
    const float* __restrict__ A, const float* __restrict__ B, float* __restrict__ C,
    int K, int lda, int ldb, int ldc)
{
    __shared__ unsigned As[2][16 * KSTR];
    __shared__ unsigned Bs[2][16 * BSTR];

    int tid  = threadIdx.x;
    int wid  = tid >> 5, lane = tid & 31;
    int g    = lane >> 2, tig = lane & 3;
    int wm   = wid & 3, wn = wid >> 2;            // 4 m-warps x 2 n-warps; warp tile 64x32
    int m0   = blockIdx.y * 256, n0 = blockIdx.x * 64;

    int bRow = tid >> 2, bCol = (tid & 3) * 4;
    const float* aptr = A + (long)(m0 + tid) * lda;
    const float* bptr = B + (long)(n0 + bRow) * ldb + bCol;

    float acc[4][4][4];
#pragma unroll
    for (int i = 0; i < 4; i++)
#pragma unroll
        for (int j = 0; j < 4; j++)
#pragma unroll
            for (int r = 0; r < 4; r++) acc[i][j][r] = 0.f;

    float4 ra[4]; float4 rb;
#pragma unroll
    for (int q = 0; q < 4; q++) ra[q] = *(const float4*)(aptr + q * 4);
    rb = *(const float4*)(bptr);

    // store prologue tile to stage 0
    {
        unsigned* as = &As[0][tid];
#pragma unroll
        for (int q = 0; q < 4; q++) {
            as[(q*4+0)*KSTR] = f2tf(ra[q].x); as[(q*4+1)*KSTR] = f2tf(ra[q].y);
            as[(q*4+2)*KSTR] = f2tf(ra[q].z); as[(q*4+3)*KSTR] = f2tf(ra[q].w);
        }
        Bs[0][(bCol+0)*BSTR + bRow] = f2tf(rb.x);
        Bs[0][(bCol+1)*BSTR + bRow] = f2tf(rb.y);
        Bs[0][(bCol+2)*BSTR + bRow] = f2tf(rb.z);
        Bs[0][(bCol+3)*BSTR + bRow] = f2tf(rb.w);
    }
    __syncthreads();

    int cur = 0;
    for (int k0 = 0; k0 < K; k0 += 16) {
        bool nxt = (k0 + 16) < K;
        if (nxt) {
#pragma unroll
            for (int q = 0; q < 4; q++) ra[q] = *(const float4*)(aptr + k0 + 16 + q * 4);
            rb = *(const float4*)(bptr + k0 + 16);
        }

        // compute from stage cur
        const unsigned* Ac = As[cur];
        const unsigned* Bc = Bs[cur];
#pragma unroll
        for (int ks = 0; ks < 2; ks++) {
            int kb = ks * 8;
            unsigned bf[4][2];
#pragma unroll
            for (int nt = 0; nt < 4; nt++) {
                int n = wn * 32 + nt * 8 + g;
                bf[nt][0] = Bc[(kb + tig)     * BSTR + n];
                bf[nt][1] = Bc[(kb + tig + 4) * BSTR + n];
            }
#pragma unroll
            for (int mt = 0; mt < 4; mt++) {
                int mr0 = wm * 64 + mt * 16 + g;
                unsigned a0 = Ac[(kb + tig)     * KSTR + mr0];
                unsigned a1 = Ac[(kb + tig)     * KSTR + mr0 + 8];
                unsigned a2 = Ac[(kb + tig + 4) * KSTR + mr0];
                unsigned a3 = Ac[(kb + tig + 4) * KSTR + mr0 + 8];
#pragma unroll
                for (int nt = 0; nt < 4; nt++)
                    mma_tf32(acc[mt][nt][0], acc[mt][nt][1], acc[mt][nt][2], acc[mt][nt][3],
                             a0, a1, a2, a3, bf[nt][0], bf[nt][1]);
            }
        }

        if (nxt) {
            int s = cur ^ 1;
            unsigned* as = &As[s][tid];
#pragma unroll
            for (int q = 0; q < 4; q++) {
                as[(q*4+0)*KSTR] = f2tf(ra[q].x); as[(q*4+1)*KSTR] = f2tf(ra[q].y);
                as[(q*4+2)*KSTR] = f2tf(ra[q].z); as[(q*4+3)*KSTR] = f2tf(ra[q].w);
            }
            Bs[s][(bCol+0)*BSTR + bRow] = f2tf(rb.x);
            Bs[s][(bCol+1)*BSTR + bRow] = f2tf(rb.y);
            Bs[s][(bCol+2)*BSTR + bRow] = f2tf(rb.z);
            Bs[s][(bCol+3)*BSTR + bRow] = f2tf(rb.w);
        }
        __syncthreads();
        cur ^= 1;
    }

    // epilogue
#pragma unroll
    for (int mt = 0; mt < 4; mt++) {
#pragma unroll
        for (int nt = 0; nt < 4; nt++) {
            int row = m0 + wm * 64 + mt * 16 + g;
            int col = n0 + wn * 32 + nt * 8 + tig * 2;
            *(float2*)(C + (long)row * ldc + col)       = make_float2(acc[mt][nt][0], acc[mt][nt][1]);
            *(float2*)(C + (long)(row + 8) * ldc + col) = make_float2(acc[mt][nt][2], acc[mt][nt][3]);
        }
    }
}

// ============ small batched GEMM (CB): BM=128, BN=64, BK=16, reg-prefetch ============
#define ASTR 20
__global__ __launch_bounds__(256) void gemm_tf32(
    const float* __restrict__ A, const float* __restrict__ B, float* __restrict__ C,
    int K, int lda, int ldb, int ldc, long aB, long bB, long cB)
{
    const float* Ab = A + (long)blockIdx.z * aB;
    const float* Bb = B + (long)blockIdx.z * bB;
    float*       Cb = C + (long)blockIdx.z * cB;

    __shared__ unsigned As[128 * ASTR];
    __shared__ unsigned Bs[64 * ASTR];

    int tid  = threadIdx.x;
    int wid  = tid >> 5, lane = tid & 31;
    int g    = lane >> 2, tig = lane & 3;
    int wm   = wid & 3, wn = wid >> 2;
    int m0   = blockIdx.y * 128, n0 = blockIdx.x * 64;

    int aRow = tid >> 1, aCol = (tid & 1) * 8;
    int bRow = tid >> 2, bCol = (tid & 3) * 4;
    const float* aptr = Ab + (long)(m0 + aRow) * lda + aCol;
    const float* bptr = Bb + (long)(n0 + bRow) * ldb + bCol;

    float acc[2][4][4];
#pragma unroll
    for (int i = 0; i < 2; i++)
#pragma unroll
        for (int j = 0; j < 4; j++)
#pragma unroll
            for (int r = 0; r < 4; r++) acc[i][j][r] = 0.f;

    float4 ra0 = *(const float4*)(aptr);
    float4 ra1 = *(const float4*)(aptr + 4);
    float4 rb  = *(const float4*)(bptr);

    for (int k0 = 0; k0 < K; k0 += 16) {
        unsigned* as = As + aRow * ASTR + aCol;
        as[0] = f2tf(ra0.x); as[1] = f2tf(ra0.y); as[2] = f2tf(ra0.z); as[3] = f2tf(ra0.w);
        as[4] = f2tf(ra1.x); as[5] = f2tf(ra1.y); as[6] = f2tf(ra1.z); as[7] = f2tf(ra1.w);
        unsigned* bs = Bs + bRow * ASTR + bCol;
        bs[0] = f2tf(rb.x); bs[1] = f2tf(rb.y); bs[2] = f2tf(rb.z); bs[3] = f2tf(rb.w);
        __syncthreads();

        if (k0 + 16 < K) {
            ra0 = *(const float4*)(aptr + k0 + 16);
            ra1 = *(const float4*)(aptr + k0 + 20);
            rb  = *(const float4*)(bptr + k0 + 16);
        }

#pragma unroll
        for (int ks = 0; ks < 2; ks++) {
            int kb = ks * 8;
            unsigned bf[4][2];
#pragma unroll
            for (int nt = 0; nt < 4; nt++) {
                const unsigned* bp = Bs + (wn * 32 + nt * 8 + g) * ASTR + kb;
                bf[nt][0] = bp[tig]; bf[nt][1] = bp[tig + 4];
            }
#pragma unroll
            for (int mt = 0; mt < 2; mt++) {
                const unsigned* ap0 = As + (wm * 32 + mt * 16 + g) * ASTR + kb;
                const unsigned* ap1 = ap0 + 8 * ASTR;
                unsigned a0 = ap0[tig], a2 = ap0[tig + 4];
                unsigned a1 = ap1[tig], a3 = ap1[tig + 4];
#pragma unroll
                for (int nt = 0; nt < 4; nt++)
                    mma_tf32(acc[mt][nt][0], acc[mt][nt][1], acc[mt][nt][2], acc[mt][nt][3],
                             a0, a1, a2, a3, bf[nt][0], bf[nt][1]);
            }
        }
        __syncthreads();
    }

#pragma unroll
    for (int mt = 0; mt < 2; mt++) {
#pragma unroll
        for (int nt = 0; nt < 4; nt++) {
            int row = m0 + wm * 32 + mt * 16 + g;
            int col = n0 + wn * 32 + nt * 8 + tig * 2;
            *(float2*)(Cb + (long)row * ldc + col)       = make_float2(acc[mt][nt][0], acc[mt][nt][1]);
            *(float2*)(Cb + (long)(row + 8) * ldc + col) = make_float2(acc[mt][nt][2], acc[mt][nt][3]);
        }
    }
}

// ---------------- dt = softplus(raw + bias) ----------------
__global__ void k_dt(const float* __restrict__ zx, const float* __restrict__ dt_bias,
                     float* __restrict__ dt)
{
    int i = blockIdx.x * 256 + threadIdx.x;
    if (i >= TOK * NH) return;
    int t = i >> 6, h = i & 63;
    float v = zx[(long)t * DPROJ + (DINNER + CDIM) + h] + dt_bias[h];
    dt[i] = (v > 20.f) ? v : log1pf(expf(v));
}

// ---------------- causal conv1d(width 4) + bias + silu; also emit C^T ----------------
__global__ void k_conv(const float* __restrict__ zx, const float* __restrict__ w,
                       const float* __restrict__ bias, float* __restrict__ xbc,
                       float* __restrict__ Ct)
{
    long i = (long)blockIdx.x * 256 + threadIdx.x;
    if (i >= (long)TOK * CDIM) return;
    int t = (int)(i / CDIM), c = (int)(i % CDIM);
    int l = t & (SEQ - 1);
    float acc = bias[c];
#pragma unroll
    for (int k = 0; k < 4; k++) {
        int lt = l - 3 + k;
        if (lt >= 0)
            acc = fmaf(w[c * 4 + k], zx[(long)(t - 3 + k) * DPROJ + DINNER + c], acc);
    }
    float s = acc / (1.f + expf(-acc));
    xbc[i] = s;
    int n = c - (DINNER + NST);
    if (n >= 0) Ct[(long)n * TOK + t] = s;
}

// ---------------- per-(chunk,head) cumsum of dt*A ----------------
__global__ void k_dacs(const float* __restrict__ dt, const float* __restrict__ Alog,
                       float* __restrict__ dacs)
{
    int cc = blockIdx.x >> 6, h = blockIdx.x & 63;
    int s = threadIdx.x;
    int t = cc * CK + s;
    float a = -expf(Alog[h]);
    float v = dt[t * NH + h] * a;
    __shared__ float sm[CK];
    sm[s] = v; __syncthreads();
    for (int off = 1; off < CK; off <<= 1) {
        float tv = (s >= off) ? sm[s - off] : 0.f;
        __syncthreads();
        sm[s] += tv;
        __syncthreads();
    }
    dacs[(blockIdx.x << 8) + s] = sm[s];
}

// ---------------- chunk states ----------------
__global__ __launch_bounds__(256) void k_states(const float* __restrict__ xbc,
        const float* __restrict__ dt, const float* __restrict__ dacs, float* __restrict__ st)
{
    int cc = blockIdx.x >> 6, h = blockIdx.x & 63;
    int tb = cc * CK;
    const float* dA = dacs + (blockIdx.x << 8);
    float dlast = dA[CK - 1];
    int tid = threadIdx.x;
    int p = tid & 63, ng = tid >> 6;

    float acc[32];
#pragma unroll
    for (int j = 0; j < 32; j++) acc[j] = 0.f;

    __shared__ float sx[32][64];
    __shared__ float sb[32][128];
    for (int s0 = 0; s0 < CK; s0 += 32) {
        for (int i = tid; i < 32 * 64; i += 256) {
            int sl = i >> 6, pp = i & 63;
            int t = tb + s0 + sl;
            sx[sl][pp] = xbc[(long)t * CDIM + h * HD + pp] * dt[t * NH + h];
        }
        for (int i = tid; i < 32 * 128; i += 256) {
            int sl = i >> 7, nn = i & 127;
            int t = tb + s0 + sl;
            sb[sl][nn] = xbc[(long)t * CDIM + DINNER + nn] * __expf(dlast - dA[s0 + sl]);
        }
        __syncthreads();
#pragma unroll 4
        for (int sl = 0; sl < 32; sl++) {
            float a = sx[sl][p];
#pragma unroll
            for (int j = 0; j < 32; j++) acc[j] = fmaf(a, sb[sl][ng * 32 + j], acc[j]);
        }
        __syncthreads();
    }
    float* o = st + ((long)blockIdx.x << 13) + p * NST + ng * 32;
#pragma unroll
    for (int j = 0; j < 32; j += 4)
        *(float4*)(o + j) = make_float4(acc[j], acc[j + 1], acc[j + 2], acc[j + 3]);
}

// ---------------- sequential chunk scan ----------------
__global__ void k_scan(const float* __restrict__ st, const float* __restrict__ dacs,
                       float* __restrict__ pv)
{
    int b = blockIdx.x >> 6, h = blockIdx.x & 63;
    int tid = threadIdx.x;
    float carry[32];
#pragma unroll
    for (int j = 0; j < 32; j++) carry[j] = 0.f;
    for (int c = 0; c < 8; c++) {
        int cc = b * 8 + c;
        long base = ((long)(cc * 64 + h)) << 13;
        float dec = __expf(dacs[((cc * 64 + h) << 8) + CK - 1]);
#pragma unroll
        for (int j = 0; j < 32; j++) {
            long e = base + tid + j * 256;
            pv[e] = carry[j];
            carry[j] = carry[j] * dec + st[e];
        }
    }
}

// ---------------- Y = Y_diag + Y_off + D*x, gated by silu(z) ----------------
__global__ __launch_bounds__(256) void k_y(const float* __restrict__ xbc,
        const float* __restrict__ zx, const float* __restrict__ dt,
        const float* __restrict__ dacs, const float* __restrict__ cb,
        const float* __restrict__ Ct, const float* __restrict__ pv,
        const float* __restrict__ Dsk, float* __restrict__ y)
{
    int cc = blockIdx.x >> 6, h = blockIdx.x & 63;
    int l = threadIdx.x;
    int tb = cc * CK;
    int t = tb + l;
    const float* dA = dacs + (blockIdx.x << 8);
    float dAl = dA[l];

    float acc[64];
#pragma unroll
    for (int p = 0; p < 64; p++) acc[p] = 0.f;

    __shared__ float sbuf[64 * 128];
    __shared__ float sdas[64];
    const float* cbb = cb + ((long)cc << 16);

    for (int s0 = 0; s0 < CK; s0 += 64) {
        for (int i = threadIdx.x; i < 64 * 64; i += 256) {
            int sl = i >> 6, pp = i & 63;
            int ts = tb + s0 + sl;
            sbuf[sl * 64 + pp] = xbc[(long)ts * CDIM + h * HD + pp] * dt[ts * NH + h];
        }
        if (threadIdx.x < 64) sdas[threadIdx.x] = dA[s0 + threadIdx.x];
        __syncthreads();
        if (s0 <= l) {
            int smax = min(64, l - s0 + 1);
            for (int sl = 0; sl < smax; sl++) {
                float w = __expf(dAl - sdas[sl]) * cbb[((s0 + sl) << 8) + l];
                const float4* r4 = (const float4*)(sbuf + sl * 64);
#pragma unroll
                for (int p4 = 0; p4 < 16; p4++) {
                    float4 v = r4[p4];
                    acc[p4 * 4 + 0] = fmaf(w, v.x, acc[p4 * 4 + 0]);
                    acc[p4 * 4 + 1] = fmaf(w, v.y, acc[p4 * 4 + 1]);
                    acc[p4 * 4 + 2] = fmaf(w, v.z, acc[p4 * 4 + 2]);
                    acc[p4 * 4 + 3] = fmaf(w, v.w, acc[p4 * 4 + 3]);
                }
            }
        }
        __syncthreads();
    }

    const float* pvb = pv + ((long)blockIdx.x << 13);
    for (int i = threadIdx.x; i < 8192; i += 256) sbuf[i] = pvb[i];
    __syncthreads();
    float el = __expf(dAl);
    const float4* pb4 = (const float4*)sbuf;
    for (int n4 = 0; n4 < 32; n4++) {
        float c0 = Ct[(long)(n4 * 4 + 0) * TOK + t] * el;
        float c1 = Ct[(long)(n4 * 4 + 1) * TOK + t] * el;
        float c2 = Ct[(long)(n4 * 4 + 2) * TOK + t] * el;
        float c3 = Ct[(long)(n4 * 4 + 3) * TOK + t] * el;
#pragma unroll
        for (int p = 0; p < 64; p++) {
            float4 v = pb4[p * 32 + n4];
            acc[p] = fmaf(c0, v.x, fmaf(c1, v.y, fmaf(c2, v.z, fmaf(c3, v.w, acc[p]))));
        }
    }

    float dsk = Dsk[h];
    const float4* xr = (const float4*)(xbc + (long)t * CDIM + h * HD);
    const float4* zr = (const float4*)(zx + (long)t * DPROJ + h * HD);
    float4* yr = (float4*)(y + (long)t * DINNER + h * HD);
#pragma unroll
    for (int p4 = 0; p4 < 16; p4++) {
        float4 xv = xr[p4], zv = zr[p4], o;
        float yv;
        yv = acc[p4 * 4 + 0] + xv.x * dsk; o.x = yv * (zv.x / (1.f + expf(-zv.x)));
        yv = acc[p4 * 4 + 1] + xv.y * dsk; o.y = yv * (zv.y / (1.f + expf(-zv.y)));
        yv = acc[p4 * 4 + 2] + xv.z * dsk; o.z = yv * (zv.z / (1.f + expf(-zv.z)));
        yv = acc[p4 * 4 + 3] + xv.w * dsk; o.w = yv * (zv.w / (1.f + expf(-zv.w)));
        yr[p4] = o;
    }
}

// ---------------- RMSNorm ----------------
__global__ void k_rms(float* __restrict__ y, const float* __restrict__ nw)
{
    int t = blockIdx.x;
    float* row = y + (long)t * DINNER;
    float ss = 0.f;
    for (int i = threadIdx.x; i < DINNER; i += 256) { float v = row[i]; ss = fmaf(v, v, ss); }
    __shared__ float red[256];
    red[threadIdx.x] = ss; __syncthreads();
    for (int o = 128; o > 0; o >>= 1) {
        if (threadIdx.x < o) red[threadIdx.x] += red[threadIdx.x + o];
        __syncthreads();
    }
    float sc = rsqrtf(red[0] / (float)DINNER + 1e-5f);
    for (int i = threadIdx.x; i < DINNER; i += 256) row[i] = row[i] * sc * nw[i];
}

// ---------------- launch ----------------
extern "C" void kernel_launch(void* const* d_in, const int* in_sizes, int n_in,
                              void* d_out, int out_size)
{
    const float* u     = (const float*)d_in[0];
    const float* Win   = (const float*)d_in[1];
    const float* convw = (const float*)d_in[2];
    const float* convb = (const float*)d_in[3];
    const float* dtb   = (const float*)d_in[4];
    const float* Alog  = (const float*)d_in[5];
    const float* Dsk   = (const float*)d_in[6];
    const float* nw    = (const float*)d_in[7];
    const float* Wout  = (const float*)d_in[8];
    float* out = (float*)d_out;

    static float *zx = nullptr, *xbc, *Ct, *dt, *dacs, *cb, *st, *pv, *y;
    if (!zx) {
        cudaGetSymbolAddress((void**)&xbc,  g_xbc);
        cudaGetSymbolAddress((void**)&Ct,   g_Ct);
        cudaGetSymbolAddress((void**)&dt,   g_dtv);
        cudaGetSymbolAddress((void**)&dacs, g_dacs);
        cudaGetSymbolAddress((void**)&cb,   g_cb);
        cudaGetSymbolAddress((void**)&st,   g_st);
        cudaGetSymbolAddress((void**)&pv,   g_pv);
        cudaGetSymbolAddress((void**)&y,    g_y);
        cudaGetSymbolAddress((void**)&zx,   g_zx);
    }

    // 1) in_proj: zx = u @ Win^T   (M=4096, N=8512, K=2048)
    gemm_big<<<dim3(DPROJ / 64, TOK / 256, 1), 256>>>(u, Win, zx,
        DMODEL, DMODEL, DMODEL, DPROJ);

    // 2) dt softplus
    k_dt<<<(TOK * NH + 255) / 256, 256>>>(zx, dtb, dt);

    // 3) conv + silu (+ C^T)
    k_conv<<<(int)(((long)TOK * CDIM + 255) / 256), 256>>>(zx, convw, convb, xbc, Ct);

    // 4) dA cumsum
    k_dacs<<<NCC * NH, CK>>>(dt, Alog, dacs);

    // 5) CB^T[cc][s][l] = B[s]·C[l]   (batched)
    gemm_tf32<<<dim3(CK / 64, CK / 128, NCC), 256>>>(xbc + DINNER, xbc + DINNER + NST, cb,
        NST, CDIM, CDIM, CK, (long)CK * CDIM, (long)CK * CDIM, (long)CK * CK);

    // 6) chunk states
    k_states<<<NCC * NH, 256>>>(xbc, dt, dacs, st);

    // 7) inter-chunk scan
    k_scan<<<2 * NH, 256>>>(st, dacs, pv);

    // 8) Y_diag + Y_off + skip, gated
    k_y<<<NCC * NH, 256>>>(xbc, zx, dt, dacs, cb, Ct, pv, Dsk, y);

    // 9) RMSNorm
    k_rms<<<TOK, 256>>>(y, nw);

    // 10) out_proj: out = y @ Wout^T  (M=4096, N=2048, K=4096)
    gemm_big<<<dim3(DMODEL / 64, TOK / 256, 1), 256>>>(y, Wout, out,
        DINNER, DINNER, DINNER, DMODEL);
}

// round 4
// speedup vs baseline: 1.1664x; 1.1664x over previous
#include <cuda_runtime.h>

// ---------------- problem constants ----------------
#define TOK    4096        // BATCH*SEQLEN
#define DMODEL 2048
#define DINNER 4096
#define NH     64
#define HD     64
#define NST    128
#define CDIM   4352        // DINNER + 2*NST
#define DPROJ  8512        // 2*DINNER + 2*NST + NH
#define SEQ    2048
#define CK     256         // chunk length
#define NCC    16          // BATCH * (SEQ/CK) total chunks

// ---------------- scratch (device globals; no allocation) ----------------
__device__ __align__(16) float g_zx  [(size_t)TOK*DPROJ];
__device__ __align__(16) float g_xbc [(size_t)TOK*CDIM];
__device__ __align__(16) float g_Ct  [(size_t)NST*TOK];
__device__ __align__(16) float g_dtv [(size_t)TOK*NH];
__device__ __align__(16) float g_dacs[(size_t)NCC*NH*CK];
__device__ __align__(16) float g_cb  [(size_t)NCC*CK*CK];
__device__ __align__(16) float g_st  [(size_t)NCC*NH*HD*NST];
__device__ __align__(16) float g_pv  [(size_t)NCC*NH*HD*NST];
__device__ __align__(16) float g_y   [(size_t)TOK*DINNER];

// ---------------- tf32 helpers ----------------
__device__ __forceinline__ unsigned f2tf(float x) {
    unsigned r; asm("cvt.rna.tf32.f32 %0, %1;" : "=r"(r) : "f"(x)); return r;
}
__device__ __forceinline__ void mma_tf32(float& c0, float& c1, float& c2, float& c3,
                                         unsigned a0, unsigned a1, unsigned a2, unsigned a3,
                                         unsigned b0, unsigned b1) {
    asm volatile("mma.sync.aligned.m16n8k8.row.col.f32.tf32.tf32.f32 "
                 "{%0,%1,%2,%3}, {%4,%5,%6,%7}, {%8,%9}, {%0,%1,%2,%3};"
                 : "+f"(c0), "+f"(c1), "+f"(c2), "+f"(c3)
                 : "r"(a0), "r"(a1), "r"(a2), "r"(a3), "r"(b0), "r"(b1));
}

// ============ tf32 GEMM: BM=128, BN=64, BK=16, DOUBLE-BUFFERED ============
// C[m,n] = sum_k A[m,k]*B[n,k]. 256 threads (8 warps), warp tile 32x32.
// ~80 regs/thread + 30KB smem -> 2 CTAs/SM.
#define ASTR 20   // smem row stride (floats) — conflict-free for frag pattern
__global__ __launch_bounds__(256) void gemm_tf32(
    const float* __restrict__ A, const float* __restrict__ B, float* __restrict__ C,
    int K, int lda, int ldb, int ldc, long aB, long bB, long cB)
{
    const float* Ab = A + (long)blockIdx.z * aB;
    const float* Bb = B + (long)blockIdx.z * bB;
    float*       Cb = C + (long)blockIdx.z * cB;

    __shared__ unsigned As[2][128 * ASTR];
    __shared__ unsigned Bs[2][64 * ASTR];

    int tid  = threadIdx.x;
    int wid  = tid >> 5, lane = tid & 31;
    int g    = lane >> 2, tig = lane & 3;
    int wm   = wid & 3, wn = wid >> 2;          // 4 m-warps x 2 n-warps
    int m0   = blockIdx.y * 128, n0 = blockIdx.x * 64;

    int aRow = tid >> 1, aCol = (tid & 1) * 8;
    int bRow = tid >> 2, bCol = (tid & 3) * 4;
    const float* aptr = Ab + (long)(m0 + aRow) * lda + aCol;
    const float* bptr = Bb + (long)(n0 + bRow) * ldb + bCol;

    float acc[2][4][4];
#pragma unroll
    for (int i = 0; i < 2; i++)
#pragma unroll
        for (int j = 0; j < 4; j++)
#pragma unroll
            for (int r = 0; r < 4; r++) acc[i][j][r] = 0.f;

    // prologue: load tile 0 and store to stage 0
    float4 ra0 = *(const float4*)(aptr);
    float4 ra1 = *(const float4*)(aptr + 4);
    float4 rb  = *(const float4*)(bptr);
    {
        unsigned* as = As[0] + aRow * ASTR + aCol;
        as[0] = f2tf(ra0.x); as[1] = f2tf(ra0.y); as[2] = f2tf(ra0.z); as[3] = f2tf(ra0.w);
        as[4] = f2tf(ra1.x); as[5] = f2tf(ra1.y); as[6] = f2tf(ra1.z); as[7] = f2tf(ra1.w);
        unsigned* bs = Bs[0] + bRow * ASTR + bCol;
        bs[0] = f2tf(rb.x); bs[1] = f2tf(rb.y); bs[2] = f2tf(rb.z); bs[3] = f2tf(rb.w);
    }
    __syncthreads();

    int cur = 0;
    for (int k0 = 0; k0 < K; k0 += 16) {
        bool nxt = (k0 + 16) < K;
        if (nxt) {
            ra0 = *(const float4*)(aptr + k0 + 16);
            ra1 = *(const float4*)(aptr + k0 + 20);
            rb  = *(const float4*)(bptr + k0 + 16);
        }

        const unsigned* Ac = As[cur];
        const unsigned* Bc = Bs[cur];
#pragma unroll
        for (int ks = 0; ks < 2; ks++) {
            int kb = ks * 8;
            unsigned bf[4][2];
#pragma unroll
            for (int nt = 0; nt < 4; nt++) {
                const unsigned* bp = Bc + (wn * 32 + nt * 8 + g) * ASTR + kb;
                bf[nt][0] = bp[tig]; bf[nt][1] = bp[tig + 4];
            }
#pragma unroll
            for (int mt = 0; mt < 2; mt++) {
                const unsigned* ap0 = Ac + (wm * 32 + mt * 16 + g) * ASTR + kb;
                const unsigned* ap1 = ap0 + 8 * ASTR;
                unsigned a0 = ap0[tig], a2 = ap0[tig + 4];
                unsigned a1 = ap1[tig], a3 = ap1[tig + 4];
#pragma unroll
                for (int nt = 0; nt < 4; nt++)
                    mma_tf32(acc[mt][nt][0], acc[mt][nt][1], acc[mt][nt][2], acc[mt][nt][3],
                             a0, a1, a2, a3, bf[nt][0], bf[nt][1]);
            }
        }

        if (nxt) {
            int s = cur ^ 1;
            unsigned* as = As[s] + aRow * ASTR + aCol;
            as[0] = f2tf(ra0.x); as[1] = f2tf(ra0.y); as[2] = f2tf(ra0.z); as[3] = f2tf(ra0.w);
            as[4] = f2tf(ra1.x); as[5] = f2tf(ra1.y); as[6] = f2tf(ra1.z); as[7] = f2tf(ra1.w);
            unsigned* bs = Bs[s] + bRow * ASTR + bCol;
            bs[0] = f2tf(rb.x); bs[1] = f2tf(rb.y); bs[2] = f2tf(rb.z); bs[3] = f2tf(rb.w);
        }
        __syncthreads();
        cur ^= 1;
    }

    // epilogue
#pragma unroll
    for (int mt = 0; mt < 2; mt++) {
#pragma unroll
        for (int nt = 0; nt < 4; nt++) {
            int row = m0 + wm * 32 + mt * 16 + g;
            int col = n0 + wn * 32 + nt * 8 + tig * 2;
            *(float2*)(Cb + (long)row * ldc + col)       = make_float2(acc[mt][nt][0], acc[mt][nt][1]);
            *(float2*)(Cb + (long)(row + 8) * ldc + col) = make_float2(acc[mt][nt][2], acc[mt][nt][3]);
        }
    }
}

// ---------------- dt = softplus(raw + bias) ----------------
__global__ void k_dt(const float* __restrict__ zx, const float* __restrict__ dt_bias,
                     float* __restrict__ dt)
{
    int i = blockIdx.x * 256 + threadIdx.x;
    if (i >= TOK * NH) return;
    int t = i >> 6, h = i & 63;
    float v = zx[(long)t * DPROJ + (DINNER + CDIM) + h] + dt_bias[h];
    dt[i] = (v > 20.f) ? v : log1pf(expf(v));
}

// ---------------- causal conv1d(width 4) + bias + silu; also emit C^T ----------------
__global__ void k_conv(const float* __restrict__ zx, const float* __restrict__ w,
                       const float* __restrict__ bias, float* __restrict__ xbc,
                       float* __restrict__ Ct)
{
    long i = (long)blockIdx.x * 256 + threadIdx.x;
    if (i >= (long)TOK * CDIM) return;
    int t = (int)(i / CDIM), c = (int)(i % CDIM);
    int l = t & (SEQ - 1);
    float acc = bias[c];
#pragma unroll
    for (int k = 0; k < 4; k++) {
        int lt = l - 3 + k;
        if (lt >= 0)
            acc = fmaf(w[c * 4 + k], zx[(long)(t - 3 + k) * DPROJ + DINNER + c], acc);
    }
    float s = acc / (1.f + expf(-acc));
    xbc[i] = s;
    int n = c - (DINNER + NST);
    if (n >= 0) Ct[(long)n * TOK + t] = s;
}

// ---------------- per-(chunk,head) cumsum of dt*A ----------------
__global__ void k_dacs(const float* __restrict__ dt, const float* __restrict__ Alog,
                       float* __restrict__ dacs)
{
    int cc = blockIdx.x >> 6, h = blockIdx.x & 63;
    int s = threadIdx.x;
    int t = cc * CK + s;
    float a = -expf(Alog[h]);
    float v = dt[t * NH + h] * a;
    __shared__ float sm[CK];
    sm[s] = v; __syncthreads();
    for (int off = 1; off < CK; off <<= 1) {
        float tv = (s >= off) ? sm[s - off] : 0.f;
        __syncthreads();
        sm[s] += tv;
        __syncthreads();
    }
    dacs[(blockIdx.x << 8) + s] = sm[s];
}

// ---------------- chunk states ----------------
__global__ __launch_bounds__(256) void k_states(const float* __restrict__ xbc,
        const float* __restrict__ dt, const float* __restrict__ dacs, float* __restrict__ st)
{
    int cc = blockIdx.x >> 6, h = blockIdx.x & 63;
    int tb = cc * CK;
    const float* dA = dacs + (blockIdx.x << 8);
    float dlast = dA[CK - 1];
    int tid = threadIdx.x;
    int p = tid & 63, ng = tid >> 6;

    float acc[32];
#pragma unroll
    for (int j = 0; j < 32; j++) acc[j] = 0.f;

    __shared__ float sx[32][64];
    __shared__ float sb[32][128];
    for (int s0 = 0; s0 < CK; s0 += 32) {
        for (int i = tid; i < 32 * 64; i += 256) {
            int sl = i >> 6, pp = i & 63;
            int t = tb + s0 + sl;
            sx[sl][pp] = xbc[(long)t * CDIM + h * HD + pp] * dt[t * NH + h];
        }
        for (int i = tid; i < 32 * 128; i += 256) {
            int sl = i >> 7, nn = i & 127;
            int t = tb + s0 + sl;
            sb[sl][nn] = xbc[(long)t * CDIM + DINNER + nn] * __expf(dlast - dA[s0 + sl]);
        }
        __syncthreads();
#pragma unroll 4
        for (int sl = 0; sl < 32; sl++) {
            float a = sx[sl][p];
#pragma unroll
            for (int j = 0; j < 32; j++) acc[j] = fmaf(a, sb[sl][ng * 32 + j], acc[j]);
        }
        __syncthreads();
    }
    float* o = st + ((long)blockIdx.x << 13) + p * NST + ng * 32;
#pragma unroll
    for (int j = 0; j < 32; j += 4)
        *(float4*)(o + j) = make_float4(acc[j], acc[j + 1], acc[j + 2], acc[j + 3]);
}

// ---------------- sequential chunk scan ----------------
__global__ void k_scan(const float* __restrict__ st, const float* __restrict__ dacs,
                       float* __restrict__ pv)
{
    int b = blockIdx.x >> 6, h = blockIdx.x & 63;
    int tid = threadIdx.x;
    float carry[32];
#pragma unroll
    for (int j = 0; j < 32; j++) carry[j] = 0.f;
    for (int c = 0; c < 8; c++) {
        int cc = b * 8 + c;
        long base = ((long)(cc * 64 + h)) << 13;
        float dec = __expf(dacs[((cc * 64 + h) << 8) + CK - 1]);
#pragma unroll
        for (int j = 0; j < 32; j++) {
            long e = base + tid + j * 256;
            pv[e] = carry[j];
            carry[j] = carry[j] * dec + st[e];
        }
    }
}

// ---------------- Y = Y_diag + Y_off + D*x, gated by silu(z) ----------------
__global__ __launch_bounds__(256) void k_y(const float* __restrict__ xbc,
        const float* __restrict__ zx, const float* __restrict__ dt,
        const float* __restrict__ dacs, const float* __restrict__ cb,
        const float* __restrict__ Ct, const float* __restrict__ pv,
        const float* __restrict__ Dsk, float* __restrict__ y)
{
    int cc = blockIdx.x >> 6, h = blockIdx.x & 63;
    int l = threadIdx.x;
    int tb = cc * CK;
    int t = tb + l;
    const float* dA = dacs + (blockIdx.x << 8);
    float dAl = dA[l];

    float acc[64];
#pragma unroll
    for (int p = 0; p < 64; p++) acc[p] = 0.f;

    __shared__ float sbuf[64 * 128];
    __shared__ float sdas[64];
    const float* cbb = cb + ((long)cc << 16);

    for (int s0 = 0; s0 < CK; s0 += 64) {
        for (int i = threadIdx.x; i < 64 * 64; i += 256) {
            int sl = i >> 6, pp = i & 63;
            int ts = tb + s0 + sl;
            sbuf[sl * 64 + pp] = xbc[(long)ts * CDIM + h * HD + pp] * dt[ts * NH + h];
        }
        if (threadIdx.x < 64) sdas[threadIdx.x] = dA[s0 + threadIdx.x];
        __syncthreads();
        if (s0 <= l) {
            int smax = min(64, l - s0 + 1);
            for (int sl = 0; sl < smax; sl++) {
                float w = __expf(dAl - sdas[sl]) * cbb[((s0 + sl) << 8) + l];
                const float4* r4 = (const float4*)(sbuf + sl * 64);
#pragma unroll
                for (int p4 = 0; p4 < 16; p4++) {
                    float4 v = r4[p4];
                    acc[p4 * 4 + 0] = fmaf(w, v.x, acc[p4 * 4 + 0]);
                    acc[p4 * 4 + 1] = fmaf(w, v.y, acc[p4 * 4 + 1]);
                    acc[p4 * 4 + 2] = fmaf(w, v.z, acc[p4 * 4 + 2]);
                    acc[p4 * 4 + 3] = fmaf(w, v.w, acc[p4 * 4 + 3]);
                }
            }
        }
        __syncthreads();
    }

    const float* pvb = pv + ((long)blockIdx.x << 13);
    for (int i = threadIdx.x; i < 8192; i += 256) sbuf[i] = pvb[i];
    __syncthreads();
    float el = __expf(dAl);
    const float4* pb4 = (const float4*)sbuf;
    for (int n4 = 0; n4 < 32; n4++) {
        float c0 = Ct[(long)(n4 * 4 + 0) * TOK + t] * el;
        float c1 = Ct[(long)(n4 * 4 + 1) * TOK + t] * el;
        float c2 = Ct[(long)(n4 * 4 + 2) * TOK + t] * el;
        float c3 = Ct[(long)(n4 * 4 + 3) * TOK + t] * el;
#pragma unroll
        for (int p = 0; p < 64; p++) {
            float4 v = pb4[p * 32 + n4];
            acc[p] = fmaf(c0, v.x, fmaf(c1, v.y, fmaf(c2, v.z, fmaf(c3, v.w, acc[p]))));
        }
    }

    float dsk = Dsk[h];
    const float4* xr = (const float4*)(xbc + (long)t * CDIM + h * HD);
    const float4* zr = (const float4*)(zx + (long)t * DPROJ + h * HD);
    float4* yr = (float4*)(y + (long)t * DINNER + h * HD);
#pragma unroll
    for (int p4 = 0; p4 < 16; p4++) {
        float4 xv = xr[p4], zv = zr[p4], o;
        float yv;
        yv = acc[p4 * 4 + 0] + xv.x * dsk; o.x = yv * (zv.x / (1.f + expf(-zv.x)));
        yv = acc[p4 * 4 + 1] + xv.y * dsk; o.y = yv * (zv.y / (1.f + expf(-zv.y)));
        yv = acc[p4 * 4 + 2] + xv.z * dsk; o.z = yv * (zv.z / (1.f + expf(-zv.z)));
        yv = acc[p4 * 4 + 3] + xv.w * dsk; o.w = yv * (zv.w / (1.f + expf(-zv.w)));
        yr[p4] = o;
    }
}

// ---------------- RMSNorm ----------------
__global__ void k_rms(float* __restrict__ y, const float* __restrict__ nw)
{
    int t = blockIdx.x;
    float* row = y + (long)t * DINNER;
    float ss = 0.f;
    for (int i = threadIdx.x; i < DINNER; i += 256) { float v = row[i]; ss = fmaf(v, v, ss); }
    __shared__ float red[256];
    red[threadIdx.x] = ss; __syncthreads();
    for (int o = 128; o > 0; o >>= 1) {
        if (threadIdx.x < o) red[threadIdx.x] += red[threadIdx.x + o];
        __syncthreads();
    }
    float sc = rsqrtf(red[0] / (float)DINNER + 1e-5f);
    for (int i = threadIdx.x; i < DINNER; i += 256) row[i] = row[i] * sc * nw[i];
}

// ---------------- launch ----------------
extern "C" void kernel_launch(void* const* d_in, const int* in_sizes, int n_in,
                              void* d_out, int out_size)
{
    const float* u     = (const float*)d_in[0];
    const float* Win   = (const float*)d_in[1];
    const float* convw = (const float*)d_in[2];
    const float* convb = (const float*)d_in[3];
    const float* dtb   = (const float*)d_in[4];
    const float* Alog  = (const float*)d_in[5];
    const float* Dsk   = (const float*)d_in[6];
    const float* nw    = (const float*)d_in[7];
    const float* Wout  = (const float*)d_in[8];
    float* out = (float*)d_out;

    static float *zx = nullptr, *xbc, *Ct, *dt, *dacs, *cb, *st, *pv, *y;
    if (!zx) {
        cudaGetSymbolAddress((void**)&xbc,  g_xbc);
        cudaGetSymbolAddress((void**)&Ct,   g_Ct);
        cudaGetSymbolAddress((void**)&dt,   g_dtv);
        cudaGetSymbolAddress((void**)&dacs, g_dacs);
        cudaGetSymbolAddress((void**)&cb,   g_cb);
        cudaGetSymbolAddress((void**)&st,   g_st);
        cudaGetSymbolAddress((void**)&pv,   g_pv);
        cudaGetSymbolAddress((void**)&y,    g_y);
        cudaGetSymbolAddress((void**)&zx,   g_zx);
    }

    // 1) in_proj: zx = u @ Win^T   (M=4096, N=8512, K=2048)
    gemm_tf32<<<dim3(DPROJ / 64, TOK / 128, 1), 256>>>(u, Win, zx,
        DMODEL, DMODEL, DMODEL, DPROJ, 0, 0, 0);

    // 2) dt softplus
    k_dt<<<(TOK * NH + 255) / 256, 256>>>(zx, dtb, dt);

    // 3) conv + silu (+ C^T)
    k_conv<<<(int)(((long)TOK * CDIM + 255) / 256), 256>>>(zx, convw, convb, xbc, Ct);

    // 4) dA cumsum
    k_dacs<<<NCC * NH, CK>>>(dt, Alog, dacs);

    // 5) CB^T[cc][s][l] = B[s]·C[l]   (batched)
    gemm_tf32<<<dim3(CK / 64, CK / 128, NCC), 256>>>(xbc + DINNER, xbc + DINNER + NST, cb,
        NST, CDIM, CDIM, CK, (long)CK * CDIM, (long)CK * CDIM, (long)CK * CK);

    // 6) chunk states
    k_states<<<NCC * NH, 256>>>(xbc, dt, dacs, st);

    // 7) inter-chunk scan
    k_scan<<<2 * NH, 256>>>(st, dacs, pv);

    // 8) Y_diag + Y_off + skip, gated
    k_y<<<NCC * NH, 256>>>(xbc, zx, dt, dacs, cb, Ct, pv, Dsk, y);

    // 9) RMSNorm
    k_rms<<<TOK, 256>>>(y, nw);

    // 10) out_proj: out = y @ Wout^T  (M=4096, N=2048, K=4096)
    gemm_tf32<<<dim3(DMODEL / 64, TOK / 128, 1), 256>>>(y, Wout, out,
        DINNER, DINNER, DINNER, DMODEL, 0, 0, 0);
}

// round 6
// speedup vs baseline: 1.1970x; 1.0262x over previous
#include <cuda_runtime.h>

// ---------------- problem constants ----------------
#define TOK    4096        // BATCH*SEQLEN
#define DMODEL 2048
#define DINNER 4096
#define NH     64
#define HD     64
#define NST    128
#define CDIM   4352        // DINNER + 2*NST
#define DPROJ  8512        // 2*DINNER + 2*NST + NH
#define SEQ    2048
#define CK     256         // chunk length
#define NCC    16          // BATCH * (SEQ/CK) total chunks

// ---------------- scratch (device globals; no allocation) ----------------
__device__ __align__(16) float g_zx  [(size_t)TOK*DPROJ];
__device__ __align__(16) float g_xbc [(size_t)TOK*CDIM];
__device__ __align__(16) float g_Ct  [(size_t)NST*TOK];
__device__ __align__(16) float g_dtv [(size_t)TOK*NH];
__device__ __align__(16) float g_dacs[(size_t)NCC*NH*CK];
__device__ __align__(16) float g_cb  [(size_t)NCC*CK*CK];
__device__ __align__(16) float g_st  [(size_t)NCC*NH*HD*NST];
__device__ __align__(16) float g_pv  [(size_t)NCC*NH*HD*NST];
__device__ __align__(16) float g_y   [(size_t)TOK*DINNER];

// ---------------- helpers ----------------
__device__ __forceinline__ unsigned f2tf(float x) {
    unsigned r; asm("cvt.rna.tf32.f32 %0, %1;" : "=r"(r) : "f"(x)); return r;
}
__device__ __forceinline__ void mma_tf32(float& c0, float& c1, float& c2, float& c3,
                                         unsigned a0, unsigned a1, unsigned a2, unsigned a3,
                                         unsigned b0, unsigned b1) {
    asm volatile("mma.sync.aligned.m16n8k8.row.col.f32.tf32.tf32.f32 "
                 "{%0,%1,%2,%3}, {%4,%5,%6,%7}, {%8,%9}, {%0,%1,%2,%3};"
                 : "+f"(c0), "+f"(c1), "+f"(c2), "+f"(c3)
                 : "r"(a0), "r"(a1), "r"(a2), "r"(a3), "r"(b0), "r"(b1));
}
__device__ __forceinline__ float fsilu(float v) {
    return v * __fdividef(1.f, 1.f + __expf(-v));
}

// ---------------- tf32 tensor-core GEMM (round-2 proven config) ----------------
// BM=128, BN=64, BK=16, 256 threads, warp tile 32x32, reg-prefetch single buffer.
#define ASTR 20
__global__ __launch_bounds__(256) void gemm_tf32(
    const float* __restrict__ A, const float* __restrict__ B, float* __restrict__ C,
    int K, int lda, int ldb, int ldc, long aB, long bB, long cB)
{
    const float* Ab = A + (long)blockIdx.z * aB;
    const float* Bb = B + (long)blockIdx.z * bB;
    float*       Cb = C + (long)blockIdx.z * cB;

    __shared__ unsigned As[128 * ASTR];
    __shared__ unsigned Bs[64 * ASTR];

    int tid  = threadIdx.x;
    int wid  = tid >> 5, lane = tid & 31;
    int g    = lane >> 2, tig = lane & 3;
    int wm   = wid & 3, wn = wid >> 2;
    int m0   = blockIdx.y * 128, n0 = blockIdx.x * 64;

    int aRow = tid >> 1, aCol = (tid & 1) * 8;
    int bRow = tid >> 2, bCol = (tid & 3) * 4;
    const float* aptr = Ab + (long)(m0 + aRow) * lda + aCol;
    const float* bptr = Bb + (long)(n0 + bRow) * ldb + bCol;

    float acc[2][4][4];
#pragma unroll
    for (int i = 0; i < 2; i++)
#pragma unroll
        for (int j = 0; j < 4; j++)
#pragma unroll
            for (int r = 0; r < 4; r++) acc[i][j][r] = 0.f;

    float4 ra0 = *(const float4*)(aptr);
    float4 ra1 = *(const float4*)(aptr + 4);
    float4 rb  = *(const float4*)(bptr);

    for (int k0 = 0; k0 < K; k0 += 16) {
        unsigned* as = As + aRow * ASTR + aCol;
        as[0] = f2tf(ra0.x); as[1] = f2tf(ra0.y); as[2] = f2tf(ra0.z); as[3] = f2tf(ra0.w);
        as[4] = f2tf(ra1.x); as[5] = f2tf(ra1.y); as[6] = f2tf(ra1.z); as[7] = f2tf(ra1.w);
        unsigned* bs = Bs + bRow * ASTR + bCol;
        bs[0] = f2tf(rb.x); bs[1] = f2tf(rb.y); bs[2] = f2tf(rb.z); bs[3] = f2tf(rb.w);
        __syncthreads();

        if (k0 + 16 < K) {
            ra0 = *(const float4*)(aptr + k0 + 16);
            ra1 = *(const float4*)(aptr + k0 + 20);
            rb  = *(const float4*)(bptr + k0 + 16);
        }

#pragma unroll
        for (int ks = 0; ks < 2; ks++) {
            int kb = ks * 8;
            unsigned bf[4][2];
#pragma unroll
            for (int nt = 0; nt < 4; nt++) {
                const unsigned* bp = Bs + (wn * 32 + nt * 8 + g) * ASTR + kb;
                bf[nt][0] = bp[tig]; bf[nt][1] = bp[tig + 4];
            }
#pragma unroll
            for (int mt = 0; mt < 2; mt++) {
                const unsigned* ap0 = As + (wm * 32 + mt * 16 + g) * ASTR + kb;
                const unsigned* ap1 = ap0 + 8 * ASTR;
                unsigned a0 = ap0[tig], a2 = ap0[tig + 4];
                unsigned a1 = ap1[tig], a3 = ap1[tig + 4];
#pragma unroll
                for (int nt = 0; nt < 4; nt++)
                    mma_tf32(acc[mt][nt][0], acc[mt][nt][1], acc[mt][nt][2], acc[mt][nt][3],
                             a0, a1, a2, a3, bf[nt][0], bf[nt][1]);
            }
        }
        __syncthreads();
    }

#pragma unroll
    for (int mt = 0; mt < 2; mt++) {
#pragma unroll
        for (int nt = 0; nt < 4; nt++) {
            int row = m0 + wm * 32 + mt * 16 + g;
            int col = n0 + wn * 32 + nt * 8 + tig * 2;
            *(float2*)(Cb + (long)row * ldc + col)       = make_float2(acc[mt][nt][0], acc[mt][nt][1]);
            *(float2*)(Cb + (long)(row + 8) * ldc + col) = make_float2(acc[mt][nt][2], acc[mt][nt][3]);
        }
    }
}

// ---------------- dt = softplus(raw + bias) ----------------
__global__ void k_dt(const float* __restrict__ zx, const float* __restrict__ dt_bias,
                     float* __restrict__ dt)
{
    int i = blockIdx.x * 256 + threadIdx.x;
    if (i >= TOK * NH) return;
    int t = i >> 6, h = i & 63;
    float v = zx[(long)t * DPROJ + (DINNER + CDIM) + h] + dt_bias[h];
    dt[i] = (v > 20.f) ? v : log1pf(expf(v));
}

// ---------------- causal conv1d(width 4) + bias + silu; also emit C^T ----------------
__global__ void k_conv(const float* __restrict__ zx, const float* __restrict__ w,
                       const float* __restrict__ bias, float* __restrict__ xbc,
                       float* __restrict__ Ct)
{
    long i = (long)blockIdx.x * 256 + threadIdx.x;
    if (i >= (long)TOK * CDIM) return;
    int t = (int)(i / CDIM), c = (int)(i % CDIM);
    int l = t & (SEQ - 1);
    float acc = bias[c];
#pragma unroll
    for (int k = 0; k < 4; k++) {
        int lt = l - 3 + k;
        if (lt >= 0)
            acc = fmaf(w[c * 4 + k], zx[(long)(t - 3 + k) * DPROJ + DINNER + c], acc);
    }
    float s = fsilu(acc);
    xbc[i] = s;
    int n = c - (DINNER + NST);
    if (n >= 0) Ct[(long)n * TOK + t] = s;
}

// ---------------- per-(chunk,head) cumsum of dt*A ----------------
__global__ void k_dacs(const float* __restrict__ dt, const float* __restrict__ Alog,
                       float* __restrict__ dacs)
{
    int cc = blockIdx.x >> 6, h = blockIdx.x & 63;
    int s = threadIdx.x;
    int t = cc * CK + s;
    float a = -expf(Alog[h]);
    float v = dt[t * NH + h] * a;
    __shared__ float sm[CK];
    sm[s] = v; __syncthreads();
    for (int off = 1; off < CK; off <<= 1) {
        float tv = (s >= off) ? sm[s - off] : 0.f;
        __syncthreads();
        sm[s] += tv;
        __syncthreads();
    }
    dacs[(blockIdx.x << 8) + s] = sm[s];
}

// ---------------- chunk states: decay precomputed per-s (256 exps, not 32K) ----------------
__global__ __launch_bounds__(256) void k_states(const float* __restrict__ xbc,
        const float* __restrict__ dt, const float* __restrict__ dacs, float* __restrict__ st)
{
    int cc = blockIdx.x >> 6, h = blockIdx.x & 63;
    int tb = cc * CK;
    const float* dA = dacs + (blockIdx.x << 8);
    float dlast = dA[CK - 1];
    int tid = threadIdx.x;
    int p = tid & 63, ng = tid >> 6;

    __shared__ float sdecay[CK];
    if (tid < CK) sdecay[tid] = __expf(dlast - dA[tid]);

    float acc[32];
#pragma unroll
    for (int j = 0; j < 32; j++) acc[j] = 0.f;

    __shared__ float sx[32][64];
    __shared__ float sb[32][128];
    __syncthreads();
    for (int s0 = 0; s0 < CK; s0 += 32) {
        for (int i = tid; i < 32 * 64; i += 256) {
            int sl = i >> 6, pp = i & 63;
            int t = tb + s0 + sl;
            sx[sl][pp] = xbc[(long)t * CDIM + h * HD + pp] * dt[t * NH + h];
        }
        for (int i = tid; i < 32 * 128; i += 256) {
            int sl = i >> 7, nn = i & 127;
            int t = tb + s0 + sl;
            sb[sl][nn] = xbc[(long)t * CDIM + DINNER + nn] * sdecay[s0 + sl];
        }
        __syncthreads();
#pragma unroll 4
        for (int sl = 0; sl < 32; sl++) {
            float a = sx[sl][p];
            const float4* b4 = (const float4*)&sb[sl][ng * 32];
#pragma unroll
            for (int j4 = 0; j4 < 8; j4++) {
                float4 v = b4[j4];
                acc[j4 * 4 + 0] = fmaf(a, v.x, acc[j4 * 4 + 0]);
                acc[j4 * 4 + 1] = fmaf(a, v.y, acc[j4 * 4 + 1]);
                acc[j4 * 4 + 2] = fmaf(a, v.z, acc[j4 * 4 + 2]);
                acc[j4 * 4 + 3] = fmaf(a, v.w, acc[j4 * 4 + 3]);
            }
        }
        __syncthreads();
    }
    float* o = st + ((long)blockIdx.x << 13) + p * NST + ng * 32;
#pragma unroll
    for (int j = 0; j < 32; j += 4)
        *(float4*)(o + j) = make_float4(acc[j], acc[j + 1], acc[j + 2], acc[j + 3]);
}

// ---------------- sequential chunk scan ----------------
__global__ void k_scan(const float* __restrict__ st, const float* __restrict__ dacs,
                       float* __restrict__ pv)
{
    int b = blockIdx.x >> 6, h = blockIdx.x & 63;
    int tid = threadIdx.x;
    float carry[32];
#pragma unroll
    for (int j = 0; j < 32; j++) carry[j] = 0.f;
    for (int c = 0; c < 8; c++) {
        int cc = b * 8 + c;
        long base = ((long)(cc * 64 + h)) << 13;
        float dec = __expf(dacs[((cc * 64 + h) << 8) + CK - 1]);
#pragma unroll
        for (int j = 0; j < 32; j++) {
            long e = base + tid + j * 256;
            pv[e] = carry[j];
            carry[j] = carry[j] * dec + st[e];
        }
    }
}

// ---------------- Y = Y_diag + Y_off + D*x, gated by silu(z) ----------------
__global__ __launch_bounds__(256) void k_y(const float* __restrict__ xbc,
        const float* __restrict__ zx, const float* __restrict__ dt,
        const float* __restrict__ dacs, const float* __restrict__ cb,
        const float* __restrict__ Ct, const float* __restrict__ pv,
        const float* __restrict__ Dsk, float* __restrict__ y)
{
    int cc = blockIdx.x >> 6, h = blockIdx.x & 63;
    int l = threadIdx.x;
    int tb = cc * CK;
    int t = tb + l;
    const float* dA = dacs + (blockIdx.x << 8);
    float dAl = dA[l];

    float acc[64];
#pragma unroll
    for (int p = 0; p < 64; p++) acc[p] = 0.f;

    __shared__ float sbuf[64 * 128];
    __shared__ float sdas[64];
    const float* cbb = cb + ((long)cc << 16);

    for (int s0 = 0; s0 < CK; s0 += 64) {
        for (int i = threadIdx.x; i < 64 * 64; i += 256) {
            int sl = i >> 6, pp = i & 63;
            int ts = tb + s0 + sl;
            sbuf[sl * 64 + pp] = xbc[(long)ts * CDIM + h * HD + pp] * dt[ts * NH + h];
        }
        if (threadIdx.x < 64) sdas[threadIdx.x] = dA[s0 + threadIdx.x];
        __syncthreads();
        if (s0 <= l) {
            int smax = min(64, l - s0 + 1);
            for (int sl = 0; sl < smax; sl++) {
                float w = __expf(dAl - sdas[sl]) * cbb[((s0 + sl) << 8) + l];
                const float4* r4 = (const float4*)(sbuf + sl * 64);
#pragma unroll
                for (int p4 = 0; p4 < 16; p4++) {
                    float4 v = r4[p4];
                    acc[p4 * 4 + 0] = fmaf(w, v.x, acc[p4 * 4 + 0]);
                    acc[p4 * 4 + 1] = fmaf(w, v.y, acc[p4 * 4 + 1]);
                    acc[p4 * 4 + 2] = fmaf(w, v.z, acc[p4 * 4 + 2]);
                    acc[p4 * 4 + 3] = fmaf(w, v.w, acc[p4 * 4 + 3]);
                }
            }
        }
        __syncthreads();
    }

    const float* pvb = pv + ((long)blockIdx.x << 13);
    for (int i = threadIdx.x; i < 8192; i += 256) sbuf[i] = pvb[i];
    __syncthreads();
    float el = __expf(dAl);
    const float4* pb4 = (const float4*)sbuf;
    for (int n4 = 0; n4 < 32; n4++) {
        float c0 = Ct[(long)(n4 * 4 + 0) * TOK + t] * el;
        float c1 = Ct[(long)(n4 * 4 + 1) * TOK + t] * el;
        float c2 = Ct[(long)(n4 * 4 + 2) * TOK + t] * el;
        float c3 = Ct[(long)(n4 * 4 + 3) * TOK + t] * el;
#pragma unroll
        for (int p = 0; p < 64; p++) {
            float4 v = pb4[p * 32 + n4];
            acc[p] = fmaf(c0, v.x, fmaf(c1, v.y, fmaf(c2, v.z, fmaf(c3, v.w, acc[p]))));
        }
    }

    float dsk = Dsk[h];
    const float4* xr = (const float4*)(xbc + (long)t * CDIM + h * HD);
    const float4* zr = (const float4*)(zx + (long)t * DPROJ + h * HD);
    float4* yr = (float4*)(y + (long)t * DINNER + h * HD);
#pragma unroll
    for (int p4 = 0; p4 < 16; p4++) {
        float4 xv = xr[p4], zv = zr[p4], o;
        o.x = (acc[p4 * 4 + 0] + xv.x * dsk) * fsilu(zv.x);
        o.y = (acc[p4 * 4 + 1] + xv.y * dsk) * fsilu(zv.y);
        o.z = (acc[p4 * 4 + 2] + xv.z * dsk) * fsilu(zv.z);
        o.w = (acc[p4 * 4 + 3] + xv.w * dsk) * fsilu(zv.w);
        yr[p4] = o;
    }
}

// ---------------- RMSNorm ----------------
__global__ void k_rms(float* __restrict__ y, const float* __restrict__ nw)
{
    int t = blockIdx.x;
    float* row = y + (long)t * DINNER;
    float ss = 0.f;
    for (int i = threadIdx.x; i < DINNER; i += 256) { float v = row[i]; ss = fmaf(v, v, ss); }
    __shared__ float red[256];
    red[threadIdx.x] = ss; __syncthreads();
    for (int o = 128; o > 0; o >>= 1) {
        if (threadIdx.x < o) red[threadIdx.x] += red[threadIdx.x + o];
        __syncthreads();
    }
    float sc = rsqrtf(red[0] / (float)DINNER + 1e-5f);
    for (int i = threadIdx.x; i < DINNER; i += 256) row[i] = row[i] * sc * nw[i];
}

// ---------------- launch ----------------
extern "C" void kernel_launch(void* const* d_in, const int* in_sizes, int n_in,
                              void* d_out, int out_size)
{
    const float* u     = (const float*)d_in[0];
    const float* Win   = (const float*)d_in[1];
    const float* convw = (const float*)d_in[2];
    const float* convb = (const float*)d_in[3];
    const float* dtb   = (const float*)d_in[4];
    const float* Alog  = (const float*)d_in[5];
    const float* Dsk   = (const float*)d_in[6];
    const float* nw    = (const float*)d_in[7];
    const float* Wout  = (const float*)d_in[8];
    float* out = (float*)d_out;

    static float *zx = nullptr, *xbc, *Ct, *dt, *dacs, *cb, *st, *pv, *y;
    if (!zx) {
        cudaGetSymbolAddress((void**)&xbc,  g_xbc);
        cudaGetSymbolAddress((void**)&Ct,   g_Ct);
        cudaGetSymbolAddress((void**)&dt,   g_dtv);
        cudaGetSymbolAddress((void**)&dacs, g_dacs);
        cudaGetSymbolAddress((void**)&cb,   g_cb);
        cudaGetSymbolAddress((void**)&st,   g_st);
        cudaGetSymbolAddress((void**)&pv,   g_pv);
        cudaGetSymbolAddress((void**)&y,    g_y);
        cudaGetSymbolAddress((void**)&zx,   g_zx);
    }

    // 1) in_proj: zx = u @ Win^T   (M=4096, N=8512, K=2048)
    gemm_tf32<<<dim3(DPROJ / 64, TOK / 128, 1), 256>>>(u, Win, zx,
        DMODEL, DMODEL, DMODEL, DPROJ, 0, 0, 0);

    // 2) dt softplus
    k_dt<<<(TOK * NH + 255) / 256, 256>>>(zx, dtb, dt);

    // 3) conv + silu (+ C^T)
    k_conv<<<(int)(((long)TOK * CDIM + 255) / 256), 256>>>(zx, convw, convb, xbc, Ct);

    // 4) dA cumsum
    k_dacs<<<NCC * NH, CK>>>(dt, Alog, dacs);

    // 5) CB^T[cc][s][l] = B[s]·C[l]   (batched)
    gemm_tf32<<<dim3(CK / 64, CK / 128, NCC), 256>>>(xbc + DINNER, xbc + DINNER + NST, cb,
        NST, CDIM, CDIM, CK, (long)CK * CDIM, (long)CK * CDIM, (long)CK * CK);

    // 6) chunk states
    k_states<<<NCC * NH, 256>>>(xbc, dt, dacs, st);

    // 7) inter-chunk scan
    k_scan<<<2 * NH, 256>>>(st, dacs, pv);

    // 8) Y_diag + Y_off + skip, gated
    k_y<<<NCC * NH, 256>>>(xbc, zx, dt, dacs, cb, Ct, pv, Dsk, y);

    // 9) RMSNorm
    k_rms<<<TOK, 256>>>(y, nw);

    // 10) out_proj: out = y @ Wout^T  (M=4096, N=2048, K=4096)
    gemm_tf32<<<dim3(DMODEL / 64, TOK / 128, 1), 256>>>(y, Wout, out,
        DINNER, DINNER, DINNER, DMODEL, 0, 0, 0);
}

// round 7
// speedup vs baseline: 1.4662x; 1.2250x over previous
#include <cuda_runtime.h>
#include <cuda_fp16.h>

// ---------------- problem constants ----------------
#define TOK    4096        // BATCH*SEQLEN
#define DMODEL 2048
#define DINNER 4096
#define NH     64
#define HD     64
#define NST    128
#define CDIM   4352        // DINNER + 2*NST
#define DPROJ  8512        // 2*DINNER + 2*NST + NH
#define SEQ    2048
#define CK     256         // chunk length
#define NCC    16          // BATCH * (SEQ/CK) total chunks

// ---------------- scratch (device globals; no allocation) ----------------
__device__ __align__(16) float g_zx  [(size_t)TOK*DPROJ];
__device__ __align__(16) float g_xbc [(size_t)TOK*CDIM];
__device__ __align__(16) float g_Ct  [(size_t)NST*TOK];
__device__ __align__(16) float g_dtv [(size_t)TOK*NH];
__device__ __align__(16) float g_dacs[(size_t)NCC*NH*CK];
__device__ __align__(16) float g_cb  [(size_t)NCC*CK*CK];
__device__ __align__(16) float g_st  [(size_t)NCC*NH*HD*NST];
__device__ __align__(16) float g_pv  [(size_t)NCC*NH*HD*NST];
__device__ __align__(16) float g_y   [(size_t)TOK*DINNER];

// ---------------- helpers ----------------
__device__ __forceinline__ unsigned f2h2(float lo, float hi) {
    __half2 h = __floats2half2_rn(lo, hi);
    return *(unsigned*)&h;
}
__device__ __forceinline__ void mma_h16(float& c0, float& c1, float& c2, float& c3,
                                        unsigned a0, unsigned a1, unsigned a2, unsigned a3,
                                        unsigned b0, unsigned b1) {
    asm volatile("mma.sync.aligned.m16n8k16.row.col.f32.f16.f16.f32 "
                 "{%0,%1,%2,%3}, {%4,%5,%6,%7}, {%8,%9}, {%0,%1,%2,%3};"
                 : "+f"(c0), "+f"(c1), "+f"(c2), "+f"(c3)
                 : "r"(a0), "r"(a1), "r"(a2), "r"(a3), "r"(b0), "r"(b1));
}
__device__ __forceinline__ float fsilu(float v) {
    return v * __fdividef(1.f, 1.f + __expf(-v));
}

// ---------------- fp16 tensor-core GEMM: C[m,n] = sum_k A[m,k]*B[n,k] ----------------
// BM=128, BN=64, BK=16, 256 threads (8 warps), warp tile 32x32 via m16n8k16.
// smem rows hold 8 half2-u32 per 16 k; row stride 12 u32 -> conflict-free frags.
#define HSTR 12
__global__ __launch_bounds__(256) void gemm_h16(
    const float* __restrict__ A, const float* __restrict__ B, float* __restrict__ C,
    int K, int lda, int ldb, int ldc, long aB, long bB, long cB)
{
    const float* Ab = A + (long)blockIdx.z * aB;
    const float* Bb = B + (long)blockIdx.z * bB;
    float*       Cb = C + (long)blockIdx.z * cB;

    __shared__ unsigned As[128 * HSTR];
    __shared__ unsigned Bs[64 * HSTR];

    int tid  = threadIdx.x;
    int wid  = tid >> 5, lane = tid & 31;
    int g    = lane >> 2, tig = lane & 3;
    int wm   = wid & 3, wn = wid >> 2;          // 4 m-warps x 2 n-warps
    int m0   = blockIdx.y * 128, n0 = blockIdx.x * 64;

    int aRow = tid >> 1, aColF = (tid & 1) * 8;   // 8 floats -> 4 u32
    int bRow = tid >> 2, bColF = (tid & 3) * 4;   // 4 floats -> 2 u32
    const float* aptr = Ab + (long)(m0 + aRow) * lda + aColF;
    const float* bptr = Bb + (long)(n0 + bRow) * ldb + bColF;

    float acc[2][4][4];
#pragma unroll
    for (int i = 0; i < 2; i++)
#pragma unroll
        for (int j = 0; j < 4; j++)
#pragma unroll
            for (int r = 0; r < 4; r++) acc[i][j][r] = 0.f;

    float4 ra0 = *(const float4*)(aptr);
    float4 ra1 = *(const float4*)(aptr + 4);
    float4 rb  = *(const float4*)(bptr);

    for (int k0 = 0; k0 < K; k0 += 16) {
        unsigned* as = As + aRow * HSTR + (tid & 1) * 4;
        as[0] = f2h2(ra0.x, ra0.y); as[1] = f2h2(ra0.z, ra0.w);
        as[2] = f2h2(ra1.x, ra1.y); as[3] = f2h2(ra1.z, ra1.w);
        unsigned* bs = Bs + bRow * HSTR + (tid & 3) * 2;
        bs[0] = f2h2(rb.x, rb.y); bs[1] = f2h2(rb.z, rb.w);
        __syncthreads();

        if (k0 + 16 < K) {
            ra0 = *(const float4*)(aptr + k0 + 16);
            ra1 = *(const float4*)(aptr + k0 + 20);
            rb  = *(const float4*)(bptr + k0 + 16);
        }

        unsigned bf[4][2];
#pragma unroll
        for (int nt = 0; nt < 4; nt++) {
            const unsigned* bp = Bs + (wn * 32 + nt * 8 + g) * HSTR;
            bf[nt][0] = bp[tig]; bf[nt][1] = bp[tig + 4];
        }
#pragma unroll
        for (int mt = 0; mt < 2; mt++) {
            const unsigned* ap0 = As + (wm * 32 + mt * 16 + g) * HSTR;
            const unsigned* ap1 = ap0 + 8 * HSTR;
            unsigned a0 = ap0[tig], a2 = ap0[tig + 4];
            unsigned a1 = ap1[tig], a3 = ap1[tig + 4];
#pragma unroll
            for (int nt = 0; nt < 4; nt++)
                mma_h16(acc[mt][nt][0], acc[mt][nt][1], acc[mt][nt][2], acc[mt][nt][3],
                        a0, a1, a2, a3, bf[nt][0], bf[nt][1]);
        }
        __syncthreads();
    }

#pragma unroll
    for (int mt = 0; mt < 2; mt++) {
#pragma unroll
        for (int nt = 0; nt < 4; nt++) {
            int row = m0 + wm * 32 + mt * 16 + g;
            int col = n0 + wn * 32 + nt * 8 + tig * 2;
            *(float2*)(Cb + (long)row * ldc + col)       = make_float2(acc[mt][nt][0], acc[mt][nt][1]);
            *(float2*)(Cb + (long)(row + 8) * ldc + col) = make_float2(acc[mt][nt][2], acc[mt][nt][3]);
        }
    }
}

// ---------------- dt = softplus(raw + bias) ----------------
__global__ void k_dt(const float* __restrict__ zx, const float* __restrict__ dt_bias,
                     float* __restrict__ dt)
{
    int i = blockIdx.x * 256 + threadIdx.x;
    if (i >= TOK * NH) return;
    int t = i >> 6, h = i & 63;
    float v = zx[(long)t * DPROJ + (DINNER + CDIM) + h] + dt_bias[h];
    dt[i] = (v > 20.f) ? v : log1pf(expf(v));
}

// ---------------- causal conv1d(width 4) + bias + silu; also emit C^T ----------------
__global__ void k_conv(const float* __restrict__ zx, const float* __restrict__ w,
                       const float* __restrict__ bias, float* __restrict__ xbc,
                       float* __restrict__ Ct)
{
    long i = (long)blockIdx.x * 256 + threadIdx.x;
    if (i >= (long)TOK * CDIM) return;
    int t = (int)(i / CDIM), c = (int)(i % CDIM);
    int l = t & (SEQ - 1);
    float acc = bias[c];
#pragma unroll
    for (int k = 0; k < 4; k++) {
        int lt = l - 3 + k;
        if (lt >= 0)
            acc = fmaf(w[c * 4 + k], zx[(long)(t - 3 + k) * DPROJ + DINNER + c], acc);
    }
    float s = fsilu(acc);
    xbc[i] = s;
    int n = c - (DINNER + NST);
    if (n >= 0) Ct[(long)n * TOK + t] = s;
}

// ---------------- per-(chunk,head) cumsum of dt*A ----------------
__global__ void k_dacs(const float* __restrict__ dt, const float* __restrict__ Alog,
                       float* __restrict__ dacs)
{
    int cc = blockIdx.x >> 6, h = blockIdx.x & 63;
    int s = threadIdx.x;
    int t = cc * CK + s;
    float a = -expf(Alog[h]);
    float v = dt[t * NH + h] * a;
    __shared__ float sm[CK];
    sm[s] = v; __syncthreads();
    for (int off = 1; off < CK; off <<= 1) {
        float tv = (s >= off) ? sm[s - off] : 0.f;
        __syncthreads();
        sm[s] += tv;
        __syncthreads();
    }
    dacs[(blockIdx.x << 8) + s] = sm[s];
}

// ---------------- chunk states ----------------
__global__ __launch_bounds__(256) void k_states(const float* __restrict__ xbc,
        const float* __restrict__ dt, const float* __restrict__ dacs, float* __restrict__ st)
{
    int cc = blockIdx.x >> 6, h = blockIdx.x & 63;
    int tb = cc * CK;
    const float* dA = dacs + (blockIdx.x << 8);
    float dlast = dA[CK - 1];
    int tid = threadIdx.x;
    int p = tid & 63, ng = tid >> 6;

    __shared__ float sdecay[CK];
    if (tid < CK) sdecay[tid] = __expf(dlast - dA[tid]);

    float acc[32];
#pragma unroll
    for (int j = 0; j < 32; j++) acc[j] = 0.f;

    __shared__ float sx[32][64];
    __shared__ float sb[32][128];
    __syncthreads();
    for (int s0 = 0; s0 < CK; s0 += 32) {
        for (int i = tid; i < 32 * 64; i += 256) {
            int sl = i >> 6, pp = i & 63;
            int t = tb + s0 + sl;
            sx[sl][pp] = xbc[(long)t * CDIM + h * HD + pp] * dt[t * NH + h];
        }
        for (int i = tid; i < 32 * 128; i += 256) {
            int sl = i >> 7, nn = i & 127;
            int t = tb + s0 + sl;
            sb[sl][nn] = xbc[(long)t * CDIM + DINNER + nn] * sdecay[s0 + sl];
        }
        __syncthreads();
#pragma unroll 4
        for (int sl = 0; sl < 32; sl++) {
            float a = sx[sl][p];
            const float4* b4 = (const float4*)&sb[sl][ng * 32];
#pragma unroll
            for (int j4 = 0; j4 < 8; j4++) {
                float4 v = b4[j4];
                acc[j4 * 4 + 0] = fmaf(a, v.x, acc[j4 * 4 + 0]);
                acc[j4 * 4 + 1] = fmaf(a, v.y, acc[j4 * 4 + 1]);
                acc[j4 * 4 + 2] = fmaf(a, v.z, acc[j4 * 4 + 2]);
                acc[j4 * 4 + 3] = fmaf(a, v.w, acc[j4 * 4 + 3]);
            }
        }
        __syncthreads();
    }
    float* o = st + ((long)blockIdx.x << 13) + p * NST + ng * 32;
#pragma unroll
    for (int j = 0; j < 32; j += 4)
        *(float4*)(o + j) = make_float4(acc[j], acc[j + 1], acc[j + 2], acc[j + 3]);
}

// ---------------- sequential chunk scan ----------------
__global__ void k_scan(const float* __restrict__ st, const float* __restrict__ dacs,
                       float* __restrict__ pv)
{
    int b = blockIdx.x >> 6, h = blockIdx.x & 63;
    int tid = threadIdx.x;
    float carry[32];
#pragma unroll
    for (int j = 0; j < 32; j++) carry[j] = 0.f;
    for (int c = 0; c < 8; c++) {
        int cc = b * 8 + c;
        long base = ((long)(cc * 64 + h)) << 13;
        float dec = __expf(dacs[((cc * 64 + h) << 8) + CK - 1]);
#pragma unroll
        for (int j = 0; j < 32; j++) {
            long e = base + tid + j * 256;
            pv[e] = carry[j];
            carry[j] = carry[j] * dec + st[e];
        }
    }
}

// ---------------- Y = Y_diag + Y_off + D*x, gated by silu(z) ----------------
__global__ __launch_bounds__(256) void k_y(const float* __restrict__ xbc,
        const float* __restrict__ zx, const float* __restrict__ dt,
        const float* __restrict__ dacs, const float* __restrict__ cb,
        const float* __restrict__ Ct, const float* __restrict__ pv,
        const float* __restrict__ Dsk, float* __restrict__ y)
{
    int cc = blockIdx.x >> 6, h = blockIdx.x & 63;
    int l = threadIdx.x;
    int tb = cc * CK;
    int t = tb + l;
    const float* dA = dacs + (blockIdx.x << 8);
    float dAl = dA[l];

    float acc[64];
#pragma unroll
    for (int p = 0; p < 64; p++) acc[p] = 0.f;

    __shared__ float sbuf[64 * 128];
    __shared__ float sdas[64];
    const float* cbb = cb + ((long)cc << 16);

    for (int s0 = 0; s0 < CK; s0 += 64) {
        for (int i = threadIdx.x; i < 64 * 64; i += 256) {
            int sl = i >> 6, pp = i & 63;
            int ts = tb + s0 + sl;
            sbuf[sl * 64 + pp] = xbc[(long)ts * CDIM + h * HD + pp] * dt[ts * NH + h];
        }
        if (threadIdx.x < 64) sdas[threadIdx.x] = dA[s0 + threadIdx.x];
        __syncthreads();
        if (s0 <= l) {
            int smax = min(64, l - s0 + 1);
            for (int sl = 0; sl < smax; sl++) {
                float w = __expf(dAl - sdas[sl]) * cbb[((s0 + sl) << 8) + l];
                const float4* r4 = (const float4*)(sbuf + sl * 64);
#pragma unroll
                for (int p4 = 0; p4 < 16; p4++) {
                    float4 v = r4[p4];
                    acc[p4 * 4 + 0] = fmaf(w, v.x, acc[p4 * 4 + 0]);
                    acc[p4 * 4 + 1] = fmaf(w, v.y, acc[p4 * 4 + 1]);
                    acc[p4 * 4 + 2] = fmaf(w, v.z, acc[p4 * 4 + 2]);
                    acc[p4 * 4 + 3] = fmaf(w, v.w, acc[p4 * 4 + 3]);
                }
            }
        }
        __syncthreads();
    }

    const float* pvb = pv + ((long)blockIdx.x << 13);
    for (int i = threadIdx.x; i < 8192; i += 256) sbuf[i] = pvb[i];
    __syncthreads();
    float el = __expf(dAl);
    const float4* pb4 = (const float4*)sbuf;
    for (int n4 = 0; n4 < 32; n4++) {
        float c0 = Ct[(long)(n4 * 4 + 0) * TOK + t] * el;
        float c1 = Ct[(long)(n4 * 4 + 1) * TOK + t] * el;
        float c2 = Ct[(long)(n4 * 4 + 2) * TOK + t] * el;
        float c3 = Ct[(long)(n4 * 4 + 3) * TOK + t] * el;
#pragma unroll
        for (int p = 0; p < 64; p++) {
            float4 v = pb4[p * 32 + n4];
            acc[p] = fmaf(c0, v.x, fmaf(c1, v.y, fmaf(c2, v.z, fmaf(c3, v.w, acc[p]))));
        }
    }

    float dsk = Dsk[h];
    const float4* xr = (const float4*)(xbc + (long)t * CDIM + h * HD);
    const float4* zr = (const float4*)(zx + (long)t * DPROJ + h * HD);
    float4* yr = (float4*)(y + (long)t * DINNER + h * HD);
#pragma unroll
    for (int p4 = 0; p4 < 16; p4++) {
        float4 xv = xr[p4], zv = zr[p4], o;
        o.x = (acc[p4 * 4 + 0] + xv.x * dsk) * fsilu(zv.x);
        o.y = (acc[p4 * 4 + 1] + xv.y * dsk) * fsilu(zv.y);
        o.z = (acc[p4 * 4 + 2] + xv.z * dsk) * fsilu(zv.z);
        o.w = (acc[p4 * 4 + 3] + xv.w * dsk) * fsilu(zv.w);
        yr[p4] = o;
    }
}

// ---------------- RMSNorm ----------------
__global__ void k_rms(float* __restrict__ y, const float* __restrict__ nw)
{
    int t = blockIdx.x;
    float* row = y + (long)t * DINNER;
    float ss = 0.f;
    for (int i = threadIdx.x; i < DINNER; i += 256) { float v = row[i]; ss = fmaf(v, v, ss); }
    __shared__ float red[256];
    red[threadIdx.x] = ss; __syncthreads();
    for (int o = 128; o > 0; o >>= 1) {
        if (threadIdx.x < o) red[threadIdx.x] += red[threadIdx.x + o];
        __syncthreads();
    }
    float sc = rsqrtf(red[0] / (float)DINNER + 1e-5f);
    for (int i = threadIdx.x; i < DINNER; i += 256) row[i] = row[i] * sc * nw[i];
}

// ---------------- launch ----------------
extern "C" void kernel_launch(void* const* d_in, const int* in_sizes, int n_in,
                              void* d_out, int out_size)
{
    const float* u     = (const float*)d_in[0];
    const float* Win   = (const float*)d_in[1];
    const float* convw = (const float*)d_in[2];
    const float* convb = (const float*)d_in[3];
    const float* dtb   = (const float*)d_in[4];
    const float* Alog  = (const float*)d_in[5];
    const float* Dsk   = (const float*)d_in[6];
    const float* nw    = (const float*)d_in[7];
    const float* Wout  = (const float*)d_in[8];
    float* out = (float*)d_out;

    static float *zx = nullptr, *xbc, *Ct, *dt, *dacs, *cb, *st, *pv, *y;
    if (!zx) {
        cudaGetSymbolAddress((void**)&xbc,  g_xbc);
        cudaGetSymbolAddress((void**)&Ct,   g_Ct);
        cudaGetSymbolAddress((void**)&dt,   g_dtv);
        cudaGetSymbolAddress((void**)&dacs, g_dacs);
        cudaGetSymbolAddress((void**)&cb,   g_cb);
        cudaGetSymbolAddress((void**)&st,   g_st);
        cudaGetSymbolAddress((void**)&pv,   g_pv);
        cudaGetSymbolAddress((void**)&y,    g_y);
        cudaGetSymbolAddress((void**)&zx,   g_zx);
    }

    // 1) in_proj: zx = u @ Win^T   (M=4096, N=8512, K=2048)
    gemm_h16<<<dim3(DPROJ / 64, TOK / 128, 1), 256>>>(u, Win, zx,
        DMODEL, DMODEL, DMODEL, DPROJ, 0, 0, 0);

    // 2) dt softplus
    k_dt<<<(TOK * NH + 255) / 256, 256>>>(zx, dtb, dt);

    // 3) conv + silu (+ C^T)
    k_conv<<<(int)(((long)TOK * CDIM + 255) / 256), 256>>>(zx, convw, convb, xbc, Ct);

    // 4) dA cumsum
    k_dacs<<<NCC * NH, CK>>>(dt, Alog, dacs);

    // 5) CB^T[cc][s][l] = B[s]·C[l]   (batched)
    gemm_h16<<<dim3(CK / 64, CK / 128, NCC), 256>>>(xbc + DINNER, xbc + DINNER + NST, cb,
        NST, CDIM, CDIM, CK, (long)CK * CDIM, (long)CK * CDIM, (long)CK * CK);

    // 6) chunk states
    k_states<<<NCC * NH, 256>>>(xbc, dt, dacs, st);

    // 7) inter-chunk scan
    k_scan<<<2 * NH, 256>>>(st, dacs, pv);

    // 8) Y_diag + Y_off + skip, gated
    k_y<<<NCC * NH, 256>>>(xbc, zx, dt, dacs, cb, Ct, pv, Dsk, y);

    // 9) RMSNorm
    k_rms<<<TOK, 256>>>(y, nw);

    // 10) out_proj: out = y @ Wout^T  (M=4096, N=2048, K=4096)
    gemm_h16<<<dim3(DMODEL / 64, TOK / 128, 1), 256>>>(y, Wout, out,
        DINNER, DINNER, DINNER, DMODEL, 0, 0, 0);
}

// round 8
// speedup vs baseline: 1.6913x; 1.1535x over previous
#include <cuda_runtime.h>
#include <cuda_fp16.h>

// ---------------- problem constants ----------------
#define TOK    4096        // BATCH*SEQLEN
#define DMODEL 2048
#define DINNER 4096
#define NH     64
#define HD     64
#define NST    128
#define CDIM   4352        // DINNER + 2*NST
#define DPROJ  8512        // 2*DINNER + 2*NST + NH
#define SEQ    2048
#define CK     256         // chunk length
#define NCC    16          // BATCH * (SEQ/CK) total chunks

// ---------------- scratch (device globals; no allocation) ----------------
__device__ __align__(16) float g_zx  [(size_t)TOK*DPROJ];
__device__ __align__(16) float g_xbc [(size_t)TOK*CDIM];
__device__ __align__(16) float g_dtv [(size_t)TOK*NH];
__device__ __align__(16) float g_dacs[(size_t)NCC*NH*CK];
__device__ __align__(16) float g_cb  [(size_t)NCC*CK*CK];
__device__ __align__(16) float g_st  [(size_t)NCC*NH*HD*NST];
__device__ __align__(16) float g_pv  [(size_t)NCC*NH*HD*NST];
__device__ __align__(16) float g_y   [(size_t)TOK*DINNER];

// ---------------- helpers ----------------
__device__ __forceinline__ unsigned f2h2(float lo, float hi) {
    __half2 h = __floats2half2_rn(lo, hi);
    return *(unsigned*)&h;
}
__device__ __forceinline__ void mma_h16(float& c0, float& c1, float& c2, float& c3,
                                        unsigned a0, unsigned a1, unsigned a2, unsigned a3,
                                        unsigned b0, unsigned b1) {
    asm volatile("mma.sync.aligned.m16n8k16.row.col.f32.f16.f16.f32 "
                 "{%0,%1,%2,%3}, {%4,%5,%6,%7}, {%8,%9}, {%0,%1,%2,%3};"
                 : "+f"(c0), "+f"(c1), "+f"(c2), "+f"(c3)
                 : "r"(a0), "r"(a1), "r"(a2), "r"(a3), "r"(b0), "r"(b1));
}
__device__ __forceinline__ float fsilu(float v) {
    return v * __fdividef(1.f, 1.f + __expf(-v));
}

// ---------------- fp16 tensor-core GEMM: C[m,n] = sum_k A[m,k]*B[n,k] ----------------
#define HSTR 12
__global__ __launch_bounds__(256) void gemm_h16(
    const float* __restrict__ A, const float* __restrict__ B, float* __restrict__ C,
    int K, int lda, int ldb, int ldc, long aB, long bB, long cB)
{
    const float* Ab = A + (long)blockIdx.z * aB;
    const float* Bb = B + (long)blockIdx.z * bB;
    float*       Cb = C + (long)blockIdx.z * cB;

    __shared__ unsigned As[128 * HSTR];
    __shared__ unsigned Bs[64 * HSTR];

    int tid  = threadIdx.x;
    int wid  = tid >> 5, lane = tid & 31;
    int g    = lane >> 2, tig = lane & 3;
    int wm   = wid & 3, wn = wid >> 2;
    int m0   = blockIdx.y * 128, n0 = blockIdx.x * 64;

    int aRow = tid >> 1, aColF = (tid & 1) * 8;
    int bRow = tid >> 2, bColF = (tid & 3) * 4;
    const float* aptr = Ab + (long)(m0 + aRow) * lda + aColF;
    const float* bptr = Bb + (long)(n0 + bRow) * ldb + bColF;

    float acc[2][4][4];
#pragma unroll
    for (int i = 0; i < 2; i++)
#pragma unroll
        for (int j = 0; j < 4; j++)
#pragma unroll
            for (int r = 0; r < 4; r++) acc[i][j][r] = 0.f;

    float4 ra0 = *(const float4*)(aptr);
    float4 ra1 = *(const float4*)(aptr + 4);
    float4 rb  = *(const float4*)(bptr);

    for (int k0 = 0; k0 < K; k0 += 16) {
        unsigned* as = As + aRow * HSTR + (tid & 1) * 4;
        as[0] = f2h2(ra0.x, ra0.y); as[1] = f2h2(ra0.z, ra0.w);
        as[2] = f2h2(ra1.x, ra1.y); as[3] = f2h2(ra1.z, ra1.w);
        unsigned* bs = Bs + bRow * HSTR + (tid & 3) * 2;
        bs[0] = f2h2(rb.x, rb.y); bs[1] = f2h2(rb.z, rb.w);
        __syncthreads();

        if (k0 + 16 < K) {
            ra0 = *(const float4*)(aptr + k0 + 16);
            ra1 = *(const float4*)(aptr + k0 + 20);
            rb  = *(const float4*)(bptr + k0 + 16);
        }

        unsigned bf[4][2];
#pragma unroll
        for (int nt = 0; nt < 4; nt++) {
            const unsigned* bp = Bs + (wn * 32 + nt * 8 + g) * HSTR;
            bf[nt][0] = bp[tig]; bf[nt][1] = bp[tig + 4];
        }
#pragma unroll
        for (int mt = 0; mt < 2; mt++) {
            const unsigned* ap0 = As + (wm * 32 + mt * 16 + g) * HSTR;
            const unsigned* ap1 = ap0 + 8 * HSTR;
            unsigned a0 = ap0[tig], a2 = ap0[tig + 4];
            unsigned a1 = ap1[tig], a3 = ap1[tig + 4];
#pragma unroll
            for (int nt = 0; nt < 4; nt++)
                mma_h16(acc[mt][nt][0], acc[mt][nt][1], acc[mt][nt][2], acc[mt][nt][3],
                        a0, a1, a2, a3, bf[nt][0], bf[nt][1]);
        }
        __syncthreads();
    }

#pragma unroll
    for (int mt = 0; mt < 2; mt++) {
#pragma unroll
        for (int nt = 0; nt < 4; nt++) {
            int row = m0 + wm * 32 + mt * 16 + g;
            int col = n0 + wn * 32 + nt * 8 + tig * 2;
            *(float2*)(Cb + (long)row * ldc + col)       = make_float2(acc[mt][nt][0], acc[mt][nt][1]);
            *(float2*)(Cb + (long)(row + 8) * ldc + col) = make_float2(acc[mt][nt][2], acc[mt][nt][3]);
        }
    }
}

// ---------------- dt = softplus(raw + bias) ----------------
__global__ void k_dt(const float* __restrict__ zx, const float* __restrict__ dt_bias,
                     float* __restrict__ dt)
{
    int i = blockIdx.x * 256 + threadIdx.x;
    if (i >= TOK * NH) return;
    int t = i >> 6, h = i & 63;
    float v = zx[(long)t * DPROJ + (DINNER + CDIM) + h] + dt_bias[h];
    dt[i] = (v > 20.f) ? v : log1pf(expf(v));
}

// ---------------- causal conv1d(width 4) + bias + silu ----------------
__global__ void k_conv(const float* __restrict__ zx, const float* __restrict__ w,
                       const float* __restrict__ bias, float* __restrict__ xbc)
{
    long i = (long)blockIdx.x * 256 + threadIdx.x;
    if (i >= (long)TOK * CDIM) return;
    int t = (int)(i / CDIM), c = (int)(i % CDIM);
    int l = t & (SEQ - 1);
    float acc = bias[c];
#pragma unroll
    for (int k = 0; k < 4; k++) {
        int lt = l - 3 + k;
        if (lt >= 0)
            acc = fmaf(w[c * 4 + k], zx[(long)(t - 3 + k) * DPROJ + DINNER + c], acc);
    }
    xbc[i] = fsilu(acc);
}

// ---------------- per-(chunk,head) cumsum of dt*A ----------------
__global__ void k_dacs(const float* __restrict__ dt, const float* __restrict__ Alog,
                       float* __restrict__ dacs)
{
    int cc = blockIdx.x >> 6, h = blockIdx.x & 63;
    int s = threadIdx.x;
    int t = cc * CK + s;
    float a = -expf(Alog[h]);
    float v = dt[t * NH + h] * a;
    __shared__ float sm[CK];
    sm[s] = v; __syncthreads();
    for (int off = 1; off < CK; off <<= 1) {
        float tv = (s >= off) ? sm[s - off] : 0.f;
        __syncthreads();
        sm[s] += tv;
        __syncthreads();
    }
    dacs[(blockIdx.x << 8) + s] = sm[s];
}

// ---------------- chunk states ----------------
__global__ __launch_bounds__(256) void k_states(const float* __restrict__ xbc,
        const float* __restrict__ dt, const float* __restrict__ dacs, float* __restrict__ st)
{
    int cc = blockIdx.x >> 6, h = blockIdx.x & 63;
    int tb = cc * CK;
    const float* dA = dacs + (blockIdx.x << 8);
    float dlast = dA[CK - 1];
    int tid = threadIdx.x;
    int p = tid & 63, ng = tid >> 6;

    __shared__ float sdecay[CK];
    if (tid < CK) sdecay[tid] = __expf(dlast - dA[tid]);

    float acc[32];
#pragma unroll
    for (int j = 0; j < 32; j++) acc[j] = 0.f;

    __shared__ float sx[32][64];
    __shared__ float sb[32][128];
    __syncthreads();
    for (int s0 = 0; s0 < CK; s0 += 32) {
        for (int i = tid; i < 32 * 64; i += 256) {
            int sl = i >> 6, pp = i & 63;
            int t = tb + s0 + sl;
            sx[sl][pp] = xbc[(long)t * CDIM + h * HD + pp] * dt[t * NH + h];
        }
        for (int i = tid; i < 32 * 128; i += 256) {
            int sl = i >> 7, nn = i & 127;
            int t = tb + s0 + sl;
            sb[sl][nn] = xbc[(long)t * CDIM + DINNER + nn] * sdecay[s0 + sl];
        }
        __syncthreads();
#pragma unroll 4
        for (int sl = 0; sl < 32; sl++) {
            float a = sx[sl][p];
            const float4* b4 = (const float4*)&sb[sl][ng * 32];
#pragma unroll
            for (int j4 = 0; j4 < 8; j4++) {
                float4 v = b4[j4];
                acc[j4 * 4 + 0] = fmaf(a, v.x, acc[j4 * 4 + 0]);
                acc[j4 * 4 + 1] = fmaf(a, v.y, acc[j4 * 4 + 1]);
                acc[j4 * 4 + 2] = fmaf(a, v.z, acc[j4 * 4 + 2]);
                acc[j4 * 4 + 3] = fmaf(a, v.w, acc[j4 * 4 + 3]);
            }
        }
        __syncthreads();
    }
    float* o = st + ((long)blockIdx.x << 13) + p * NST + ng * 32;
#pragma unroll
    for (int j = 0; j < 32; j += 4)
        *(float4*)(o + j) = make_float4(acc[j], acc[j + 1], acc[j + 2], acc[j + 3]);
}

// ---------------- sequential chunk scan ----------------
__global__ void k_scan(const float* __restrict__ st, const float* __restrict__ dacs,
                       float* __restrict__ pv)
{
    int b = blockIdx.x >> 6, h = blockIdx.x & 63;
    int tid = threadIdx.x;
    float carry[32];
#pragma unroll
    for (int j = 0; j < 32; j++) carry[j] = 0.f;
    for (int c = 0; c < 8; c++) {
        int cc = b * 8 + c;
        long base = ((long)(cc * 64 + h)) << 13;
        float dec = __expf(dacs[((cc * 64 + h) << 8) + CK - 1]);
#pragma unroll
        for (int j = 0; j < 32; j++) {
            long e = base + tid + j * 256;
            pv[e] = carry[j];
            carry[j] = carry[j] * dec + st[e];
        }
    }
}

// ======= k_y via fp16 MMA: Y = (W@xdt) + (C*el)@prev^T, + D*x, gated =======
// Per block (cc,h). Output 256(l) x 64(p). 8 warps, each 32 l-rows x 64 p.
// smem rows stride 36 u32 (36 == 4 mod 32 -> fragment LDS conflict-free).
#define YSTR 36
__global__ __launch_bounds__(256) void k_y_mma(const float* __restrict__ xbc,
        const float* __restrict__ zx, const float* __restrict__ dt,
        const float* __restrict__ dacs, const float* __restrict__ cb,
        const float* __restrict__ pv, const float* __restrict__ Dsk,
        float* __restrict__ y)
{
    const int cc = blockIdx.x >> 6, h = blockIdx.x & 63;
    const int tb = cc * CK;
    const int tid = threadIdx.x, wid = tid >> 5, lane = tid & 31;
    const int g = lane >> 2, tig = lane & 3;

    __shared__ unsigned At[256 * YSTR];   // 36 KB
    __shared__ unsigned Bt[64 * YSTR];    // 9 KB
    __shared__ float sda[256];
    __shared__ float sel[256];

    sda[tid] = dacs[(blockIdx.x << 8) + tid];
    __syncthreads();
    sel[tid] = __expf(sda[tid]);

    float acc[2][8][4];
#pragma unroll
    for (int i = 0; i < 2; i++)
#pragma unroll
        for (int j = 0; j < 8; j++)
#pragma unroll
            for (int r = 0; r < 4; r++) acc[i][j][r] = 0.f;

    const float* cbb = cb + ((long)cc << 16);

    // ---- phase 1: Y_diag, 4 s-tiles of 64 ----
    for (int st4 = 0; st4 < 4; st4++) {
        int s0 = st4 * 64;
        // A tile: W[l][s] (l = tid row, 32 u32 = 64 s halves)
        {
            int l = tid;
            unsigned* arow = At + l * YSTR;
            if (l < s0) {
#pragma unroll 8
                for (int it = 0; it < 32; it++) arow[it] = 0u;
            } else {
                float dal = sda[l];
#pragma unroll 4
                for (int it = 0; it < 32; it++) {
                    int s = s0 + 2 * it;
                    float w0 = 0.f, w1 = 0.f;
                    if (s <= l) {
                        w0 = __expf(dal - sda[s]) * cbb[(s << 8) + l];
                        if (s + 1 <= l)
                            w1 = __expf(dal - sda[s + 1]) * cbb[((s + 1) << 8) + l];
                    }
                    arow[it] = f2h2(w0, w1);
                }
            }
        }
        // B tile: xdt^T[p][s]
#pragma unroll
        for (int it = 0; it < 8; it++) {
            int idx = it * 256 + tid;
            int p = idx & 63, sq = idx >> 6;          // sq 0..31
            int t0 = tb + s0 + 2 * sq;
            float v0 = xbc[(long)t0 * CDIM + h * HD + p] * dt[t0 * NH + h];
            float v1 = xbc[(long)(t0 + 1) * CDIM + h * HD + p] * dt[(t0 + 1) * NH + h];
            Bt[p * YSTR + sq] = f2h2(v0, v1);
        }
        __syncthreads();
        if (wid * 32 + 31 >= s0) {
#pragma unroll
            for (int ks = 0; ks < 4; ks++) {
                unsigned bf[8][2];
#pragma unroll
                for (int nt = 0; nt < 8; nt++) {
                    const unsigned* bp = Bt + (nt * 8 + g) * YSTR + ks * 8;
                    bf[nt][0] = bp[tig]; bf[nt][1] = bp[tig + 4];
                }
#pragma unroll
                for (int mt = 0; mt < 2; mt++) {
                    const unsigned* ap = At + (wid * 32 + mt * 16 + g) * YSTR + ks * 8;
                    unsigned a0 = ap[tig], a2 = ap[tig + 4];
                    unsigned a1 = ap[8 * YSTR + tig], a3 = ap[8 * YSTR + tig + 4];
#pragma unroll
                    for (int nt = 0; nt < 8; nt++)
                        mma_h16(acc[mt][nt][0], acc[mt][nt][1], acc[mt][nt][2], acc[mt][nt][3],
                                a0, a1, a2, a3, bf[nt][0], bf[nt][1]);
                }
            }
        }
        __syncthreads();
    }

    // ---- phase 2: Y_off, 2 n-subtiles of 64 ----
    const float* pvb = pv + ((long)blockIdx.x << 13);
    for (int ns = 0; ns < 2; ns++) {
        int n0 = ns * 64;
        // A: C[l][n] * exp(dA[l])
#pragma unroll
        for (int it = 0; it < 32; it++) {
            int idx = it * 256 + tid;
            int np = idx & 31, l = idx >> 5;
            float el = sel[l];
            float2 v = *(const float2*)&xbc[(long)(tb + l) * CDIM + DINNER + NST + n0 + 2 * np];
            At[l * YSTR + np] = f2h2(v.x * el, v.y * el);
        }
        // B: prev[p][n]
#pragma unroll
        for (int it = 0; it < 8; it++) {
            int idx = it * 256 + tid;
            int np = idx & 31, p = idx >> 5;
            float2 v = *(const float2*)&pvb[p * NST + n0 + 2 * np];
            Bt[p * YSTR + np] = f2h2(v.x, v.y);
        }
        __syncthreads();
#pragma unroll
        for (int ks = 0; ks < 4; ks++) {
            unsigned bf[8][2];
#pragma unroll
            for (int nt = 0; nt < 8; nt++) {
                const unsigned* bp = Bt + (nt * 8 + g) * YSTR + ks * 8;
                bf[nt][0] = bp[tig]; bf[nt][1] = bp[tig + 4];
            }
#pragma unroll
            for (int mt = 0; mt < 2; mt++) {
                const unsigned* ap = At + (wid * 32 + mt * 16 + g) * YSTR + ks * 8;
                unsigned a0 = ap[tig], a2 = ap[tig + 4];
                unsigned a1 = ap[8 * YSTR + tig], a3 = ap[8 * YSTR + tig + 4];
#pragma unroll
                for (int nt = 0; nt < 8; nt++)
                    mma_h16(acc[mt][nt][0], acc[mt][nt][1], acc[mt][nt][2], acc[mt][nt][3],
                            a0, a1, a2, a3, bf[nt][0], bf[nt][1]);
            }
        }
        __syncthreads();
    }

    // ---- epilogue: + D*x, gate silu(z) ----
    float dsk = Dsk[h];
#pragma unroll
    for (int mt = 0; mt < 2; mt++) {
#pragma unroll
        for (int nt = 0; nt < 8; nt++) {
            int col = nt * 8 + tig * 2;
#pragma unroll
            for (int rr = 0; rr < 2; rr++) {
                int l = wid * 32 + mt * 16 + g + rr * 8;
                int t = tb + l;
                float2 xv = *(const float2*)&xbc[(long)t * CDIM + h * HD + col];
                float2 zv = *(const float2*)&zx[(long)t * DPROJ + h * HD + col];
                float o0 = (acc[mt][nt][rr * 2 + 0] + xv.x * dsk) * fsilu(zv.x);
                float o1 = (acc[mt][nt][rr * 2 + 1] + xv.y * dsk) * fsilu(zv.y);
                *(float2*)&y[(long)t * DINNER + h * HD + col] = make_float2(o0, o1);
            }
        }
    }
}

// ---------------- RMSNorm ----------------
__global__ void k_rms(float* __restrict__ y, const float* __restrict__ nw)
{
    int t = blockIdx.x;
    float* row = y + (long)t * DINNER;
    float ss = 0.f;
    for (int i = threadIdx.x; i < DINNER; i += 256) { float v = row[i]; ss = fmaf(v, v, ss); }
    __shared__ float red[256];
    red[threadIdx.x] = ss; __syncthreads();
    for (int o = 128; o > 0; o >>= 1) {
        if (threadIdx.x < o) red[threadIdx.x] += red[threadIdx.x + o];
        __syncthreads();
    }
    float sc = rsqrtf(red[0] / (float)DINNER + 1e-5f);
    for (int i = threadIdx.x; i < DINNER; i += 256) row[i] = row[i] * sc * nw[i];
}

// ---------------- launch ----------------
extern "C" void kernel_launch(void* const* d_in, const int* in_sizes, int n_in,
                              void* d_out, int out_size)
{
    const float* u     = (const float*)d_in[0];
    const float* Win   = (const float*)d_in[1];
    const float* convw = (const float*)d_in[2];
    const float* convb = (const float*)d_in[3];
    const float* dtb   = (const float*)d_in[4];
    const float* Alog  = (const float*)d_in[5];
    const float* Dsk   = (const float*)d_in[6];
    const float* nw    = (const float*)d_in[7];
    const float* Wout  = (const float*)d_in[8];
    float* out = (float*)d_out;

    static float *zx = nullptr, *xbc, *dt, *dacs, *cb, *st, *pv, *y;
    if (!zx) {
        cudaGetSymbolAddress((void**)&xbc,  g_xbc);
        cudaGetSymbolAddress((void**)&dt,   g_dtv);
        cudaGetSymbolAddress((void**)&dacs, g_dacs);
        cudaGetSymbolAddress((void**)&cb,   g_cb);
        cudaGetSymbolAddress((void**)&st,   g_st);
        cudaGetSymbolAddress((void**)&pv,   g_pv);
        cudaGetSymbolAddress((void**)&y,    g_y);
        cudaGetSymbolAddress((void**)&zx,   g_zx);
    }

    // 1) in_proj: zx = u @ Win^T   (M=4096, N=8512, K=2048)
    gemm_h16<<<dim3(DPROJ / 64, TOK / 128, 1), 256>>>(u, Win, zx,
        DMODEL, DMODEL, DMODEL, DPROJ, 0, 0, 0);

    // 2) dt softplus
    k_dt<<<(TOK * NH + 255) / 256, 256>>>(zx, dtb, dt);

    // 3) conv + silu
    k_conv<<<(int)(((long)TOK * CDIM + 255) / 256), 256>>>(zx, convw, convb, xbc);

    // 4) dA cumsum
    k_dacs<<<NCC * NH, CK>>>(dt, Alog, dacs);

    // 5) CB^T[cc][s][l] = B[s]·C[l]   (batched)
    gemm_h16<<<dim3(CK / 64, CK / 128, NCC), 256>>>(xbc + DINNER, xbc + DINNER + NST, cb,
        NST, CDIM, CDIM, CK, (long)CK * CDIM, (long)CK * CDIM, (long)CK * CK);

    // 6) chunk states
    k_states<<<NCC * NH, 256>>>(xbc, dt, dacs, st);

    // 7) inter-chunk scan
    k_scan<<<2 * NH, 256>>>(st, dacs, pv);

    // 8) Y = Y_diag + Y_off + skip, gated  (tensor-core)
    k_y_mma<<<NCC * NH, 256>>>(xbc, zx, dt, dacs, cb, pv, Dsk, y);

    // 9) RMSNorm
    k_rms<<<TOK, 256>>>(y, nw);

    // 10) out_proj: out = y @ Wout^T  (M=4096, N=2048, K=4096)
    gemm_h16<<<dim3(DMODEL / 64, TOK / 128, 1), 256>>>(y, Wout, out,
        DINNER, DINNER, DINNER, DMODEL, 0, 0, 0);
}

// round 9
// speedup vs baseline: 1.7844x; 1.0550x over previous
#include <cuda_runtime.h>
#include <cuda_fp16.h>

// ---------------- problem constants ----------------
#define TOK    4096        // BATCH*SEQLEN
#define DMODEL 2048
#define DINNER 4096
#define NH     64
#define HD     64
#define NST    128
#define CDIM   4352        // DINNER + 2*NST
#define DPROJ  8512        // 2*DINNER + 2*NST + NH
#define SEQ    2048
#define CK     256         // chunk length
#define NCC    16          // BATCH * (SEQ/CK) total chunks

// ---------------- scratch (device globals; no allocation) ----------------
__device__ __align__(16) float g_zx  [(size_t)TOK*DPROJ];
__device__ __align__(16) float g_xbc [(size_t)TOK*CDIM];
__device__ __align__(16) float g_dtv [(size_t)TOK*NH];
__device__ __align__(16) float g_dacs[(size_t)NCC*NH*CK];
__device__ __align__(16) float g_cb  [(size_t)NCC*CK*CK];
__device__ __align__(16) float g_st  [(size_t)NCC*NH*HD*NST];
__device__ __align__(16) float g_pv  [(size_t)NCC*NH*HD*NST];
__device__ __align__(16) float g_y   [(size_t)TOK*DINNER];

// ---------------- helpers ----------------
__device__ __forceinline__ unsigned f2h2(float lo, float hi) {
    __half2 h = __floats2half2_rn(lo, hi);
    return *(unsigned*)&h;
}
__device__ __forceinline__ void mma_h16(float& c0, float& c1, float& c2, float& c3,
                                        unsigned a0, unsigned a1, unsigned a2, unsigned a3,
                                        unsigned b0, unsigned b1) {
    asm volatile("mma.sync.aligned.m16n8k16.row.col.f32.f16.f16.f32 "
                 "{%0,%1,%2,%3}, {%4,%5,%6,%7}, {%8,%9}, {%0,%1,%2,%3};"
                 : "+f"(c0), "+f"(c1), "+f"(c2), "+f"(c3)
                 : "r"(a0), "r"(a1), "r"(a2), "r"(a3), "r"(b0), "r"(b1));
}
__device__ __forceinline__ float fsilu(float v) {
    return v * __fdividef(1.f, 1.f + __expf(-v));
}

// ---------------- fp16 tensor-core GEMM: C[m,n] = sum_k A[m,k]*B[n,k] ----------------
#define HSTR 12
__global__ __launch_bounds__(256) void gemm_h16(
    const float* __restrict__ A, const float* __restrict__ B, float* __restrict__ C,
    int K, int lda, int ldb, int ldc, long aB, long bB, long cB)
{
    const float* Ab = A + (long)blockIdx.z * aB;
    const float* Bb = B + (long)blockIdx.z * bB;
    float*       Cb = C + (long)blockIdx.z * cB;

    __shared__ unsigned As[128 * HSTR];
    __shared__ unsigned Bs[64 * HSTR];

    int tid  = threadIdx.x;
    int wid  = tid >> 5, lane = tid & 31;
    int g    = lane >> 2, tig = lane & 3;
    int wm   = wid & 3, wn = wid >> 2;
    int m0   = blockIdx.y * 128, n0 = blockIdx.x * 64;

    int aRow = tid >> 1, aColF = (tid & 1) * 8;
    int bRow = tid >> 2, bColF = (tid & 3) * 4;
    const float* aptr = Ab + (long)(m0 + aRow) * lda + aColF;
    const float* bptr = Bb + (long)(n0 + bRow) * ldb + bColF;

    float acc[2][4][4];
#pragma unroll
    for (int i = 0; i < 2; i++)
#pragma unroll
        for (int j = 0; j < 4; j++)
#pragma unroll
            for (int r = 0; r < 4; r++) acc[i][j][r] = 0.f;

    float4 ra0 = *(const float4*)(aptr);
    float4 ra1 = *(const float4*)(aptr + 4);
    float4 rb  = *(const float4*)(bptr);

    for (int k0 = 0; k0 < K; k0 += 16) {
        unsigned* as = As + aRow * HSTR + (tid & 1) * 4;
        as[0] = f2h2(ra0.x, ra0.y); as[1] = f2h2(ra0.z, ra0.w);
        as[2] = f2h2(ra1.x, ra1.y); as[3] = f2h2(ra1.z, ra1.w);
        unsigned* bs = Bs + bRow * HSTR + (tid & 3) * 2;
        bs[0] = f2h2(rb.x, rb.y); bs[1] = f2h2(rb.z, rb.w);
        __syncthreads();

        if (k0 + 16 < K) {
            ra0 = *(const float4*)(aptr + k0 + 16);
            ra1 = *(const float4*)(aptr + k0 + 20);
            rb  = *(const float4*)(bptr + k0 + 16);
        }

        unsigned bf[4][2];
#pragma unroll
        for (int nt = 0; nt < 4; nt++) {
            const unsigned* bp = Bs + (wn * 32 + nt * 8 + g) * HSTR;
            bf[nt][0] = bp[tig]; bf[nt][1] = bp[tig + 4];
        }
#pragma unroll
        for (int mt = 0; mt < 2; mt++) {
            const unsigned* ap0 = As + (wm * 32 + mt * 16 + g) * HSTR;
            const unsigned* ap1 = ap0 + 8 * HSTR;
            unsigned a0 = ap0[tig], a2 = ap0[tig + 4];
            unsigned a1 = ap1[tig], a3 = ap1[tig + 4];
#pragma unroll
            for (int nt = 0; nt < 4; nt++)
                mma_h16(acc[mt][nt][0], acc[mt][nt][1], acc[mt][nt][2], acc[mt][nt][3],
                        a0, a1, a2, a3, bf[nt][0], bf[nt][1]);
        }
        __syncthreads();
    }

#pragma unroll
    for (int mt = 0; mt < 2; mt++) {
#pragma unroll
        for (int nt = 0; nt < 4; nt++) {
            int row = m0 + wm * 32 + mt * 16 + g;
            int col = n0 + wn * 32 + nt * 8 + tig * 2;
            *(float2*)(Cb + (long)row * ldc + col)       = make_float2(acc[mt][nt][0], acc[mt][nt][1]);
            *(float2*)(Cb + (long)(row + 8) * ldc + col) = make_float2(acc[mt][nt][2], acc[mt][nt][3]);
        }
    }
}

// ---------------- dt = softplus(raw + bias) ----------------
__global__ void k_dt(const float* __restrict__ zx, const float* __restrict__ dt_bias,
                     float* __restrict__ dt)
{
    int i = blockIdx.x * 256 + threadIdx.x;
    if (i >= TOK * NH) return;
    int t = i >> 6, h = i & 63;
    float v = zx[(long)t * DPROJ + (DINNER + CDIM) + h] + dt_bias[h];
    dt[i] = (v > 20.f) ? v : log1pf(expf(v));
}

// ---------------- causal conv1d(width 4) + bias + silu ----------------
__global__ void k_conv(const float* __restrict__ zx, const float* __restrict__ w,
                       const float* __restrict__ bias, float* __restrict__ xbc)
{
    long i = (long)blockIdx.x * 256 + threadIdx.x;
    if (i >= (long)TOK * CDIM) return;
    int t = (int)(i / CDIM), c = (int)(i % CDIM);
    int l = t & (SEQ - 1);
    float acc = bias[c];
#pragma unroll
    for (int k = 0; k < 4; k++) {
        int lt = l - 3 + k;
        if (lt >= 0)
            acc = fmaf(w[c * 4 + k], zx[(long)(t - 3 + k) * DPROJ + DINNER + c], acc);
    }
    xbc[i] = fsilu(acc);
}

// ---------------- per-(chunk,head) cumsum of dt*A ----------------
__global__ void k_dacs(const float* __restrict__ dt, const float* __restrict__ Alog,
                       float* __restrict__ dacs)
{
    int cc = blockIdx.x >> 6, h = blockIdx.x & 63;
    int s = threadIdx.x;
    int t = cc * CK + s;
    float a = -expf(Alog[h]);
    float v = dt[t * NH + h] * a;
    __shared__ float sm[CK];
    sm[s] = v; __syncthreads();
    for (int off = 1; off < CK; off <<= 1) {
        float tv = (s >= off) ? sm[s - off] : 0.f;
        __syncthreads();
        sm[s] += tv;
        __syncthreads();
    }
    dacs[(blockIdx.x << 8) + s] = sm[s];
}

// ======= chunk states via fp16 MMA: st[p][n] = sum_s xdt[s][p]*(B[s][n]*decay[s]) =======
// Per block (cc,h): output 64(p) x 128(n), k=256 in 4 s-chunks of 64.
// 8 warps = 4 p-blocks(16) x 2 n-halves(64). smem stride 36 (conflict-free frags).
#define YSTR 36
__global__ __launch_bounds__(256) void k_states_mma(const float* __restrict__ xbc,
        const float* __restrict__ dt, const float* __restrict__ dacs, float* __restrict__ st)
{
    const int cc = blockIdx.x >> 6, h = blockIdx.x & 63;
    const int tb = cc * CK;
    const int tid = threadIdx.x, wid = tid >> 5, lane = tid & 31;
    const int g = lane >> 2, tig = lane & 3;
    const int wm = wid & 3, wn = wid >> 2;   // 4 p-warps x 2 n-warps

    __shared__ unsigned At[64 * YSTR];       // xdt^T tile: [p][s-chunk]
    __shared__ unsigned Bt[128 * YSTR];      // (B*decay)^T tile: [n][s-chunk]
    __shared__ float sdecay[CK];

    const float* dA = dacs + (blockIdx.x << 8);
    {
        float dlast = dA[CK - 1];
        sdecay[tid] = __expf(dlast - dA[tid]);
    }
    __syncthreads();

    float acc[8][4];
#pragma unroll
    for (int j = 0; j < 8; j++)
#pragma unroll
        for (int r = 0; r < 4; r++) acc[j][r] = 0.f;

    for (int s0 = 0; s0 < CK; s0 += 64) {
        // A: xdt^T[p][s]  (2048 u32, 8 per thread; coalesced over p)
#pragma unroll
        for (int it = 0; it < 8; it++) {
            int idx = it * 256 + tid;
            int p = idx & 63, sq = idx >> 6;           // sq 0..31
            int t0 = tb + s0 + 2 * sq;
            float v0 = xbc[(long)t0 * CDIM + h * HD + p] * dt[t0 * NH + h];
            float v1 = xbc[(long)(t0 + 1) * CDIM + h * HD + p] * dt[(t0 + 1) * NH + h];
            At[p * YSTR + sq] = f2h2(v0, v1);
        }
        // B: (B*decay)^T[n][s]  (4096 u32, 16 per thread; coalesced over n)
#pragma unroll
        for (int it = 0; it < 16; it++) {
            int idx = it * 256 + tid;
            int n = idx & 127, sq = idx >> 7;          // sq 0..31
            int t0 = tb + s0 + 2 * sq;
            float v0 = xbc[(long)t0 * CDIM + DINNER + n] * sdecay[s0 + 2 * sq];
            float v1 = xbc[(long)(t0 + 1) * CDIM + DINNER + n] * sdecay[s0 + 2 * sq + 1];
            Bt[n * YSTR + sq] = f2h2(v0, v1);
        }
        __syncthreads();
#pragma unroll
        for (int ks = 0; ks < 4; ks++) {
            unsigned bf[8][2];
#pragma unroll
            for (int nt = 0; nt < 8; nt++) {
                const unsigned* bp = Bt + (wn * 64 + nt * 8 + g) * YSTR + ks * 8;
                bf[nt][0] = bp[tig]; bf[nt][1] = bp[tig + 4];
            }
            const unsigned* ap = At + (wm * 16 + g) * YSTR + ks * 8;
            unsigned a0 = ap[tig], a2 = ap[tig + 4];
            unsigned a1 = ap[8 * YSTR + tig], a3 = ap[8 * YSTR + tig + 4];
#pragma unroll
            for (int nt = 0; nt < 8; nt++)
                mma_h16(acc[nt][0], acc[nt][1], acc[nt][2], acc[nt][3],
                        a0, a1, a2, a3, bf[nt][0], bf[nt][1]);
        }
        __syncthreads();
    }

    // write st[p][n]
    float* ob = st + ((long)blockIdx.x << 13);
#pragma unroll
    for (int nt = 0; nt < 8; nt++) {
        int col = wn * 64 + nt * 8 + tig * 2;
        int row = wm * 16 + g;
        *(float2*)(ob + row * NST + col)       = make_float2(acc[nt][0], acc[nt][1]);
        *(float2*)(ob + (row + 8) * NST + col) = make_float2(acc[nt][2], acc[nt][3]);
    }
}

// ---------------- sequential chunk scan ----------------
__global__ void k_scan(const float* __restrict__ st, const float* __restrict__ dacs,
                       float* __restrict__ pv)
{
    int b = blockIdx.x >> 6, h = blockIdx.x & 63;
    int tid = threadIdx.x;
    float carry[32];
#pragma unroll
    for (int j = 0; j < 32; j++) carry[j] = 0.f;
    for (int c = 0; c < 8; c++) {
        int cc = b * 8 + c;
        long base = ((long)(cc * 64 + h)) << 13;
        float dec = __expf(dacs[((cc * 64 + h) << 8) + CK - 1]);
#pragma unroll
        for (int j = 0; j < 32; j++) {
            long e = base + tid + j * 256;
            pv[e] = carry[j];
            carry[j] = carry[j] * dec + st[e];
        }
    }
}

// ======= k_y via fp16 MMA: Y = (W@xdt) + (C*el)@prev^T, + D*x, gated =======
__global__ __launch_bounds__(256) void k_y_mma(const float* __restrict__ xbc,
        const float* __restrict__ zx, const float* __restrict__ dt,
        const float* __restrict__ dacs, const float* __restrict__ cb,
        const float* __restrict__ pv, const float* __restrict__ Dsk,
        float* __restrict__ y)
{
    const int cc = blockIdx.x >> 6, h = blockIdx.x & 63;
    const int tb = cc * CK;
    const int tid = threadIdx.x, wid = tid >> 5, lane = tid & 31;
    const int g = lane >> 2, tig = lane & 3;

    __shared__ unsigned At[256 * YSTR];   // 36 KB
    __shared__ unsigned Bt[64 * YSTR];    // 9 KB
    __shared__ float sda[256];
    __shared__ float sel[256];

    sda[tid] = dacs[(blockIdx.x << 8) + tid];
    __syncthreads();
    sel[tid] = __expf(sda[tid]);

    float acc[2][8][4];
#pragma unroll
    for (int i = 0; i < 2; i++)
#pragma unroll
        for (int j = 0; j < 8; j++)
#pragma unroll
            for (int r = 0; r < 4; r++) acc[i][j][r] = 0.f;

    const float* cbb = cb + ((long)cc << 16);

    // ---- phase 1: Y_diag, 4 s-tiles of 64 ----
    for (int st4 = 0; st4 < 4; st4++) {
        int s0 = st4 * 64;
        {
            int l = tid;
            unsigned* arow = At + l * YSTR;
            if (l < s0) {
#pragma unroll 8
                for (int it = 0; it < 32; it++) arow[it] = 0u;
            } else {
                float dal = sda[l];
#pragma unroll 4
                for (int it = 0; it < 32; it++) {
                    int s = s0 + 2 * it;
                    float w0 = 0.f, w1 = 0.f;
                    if (s <= l) {
                        w0 = __expf(dal - sda[s]) * cbb[(s << 8) + l];
                        if (s + 1 <= l)
                            w1 = __expf(dal - sda[s + 1]) * cbb[((s + 1) << 8) + l];
                    }
                    arow[it] = f2h2(w0, w1);
                }
            }
        }
#pragma unroll
        for (int it = 0; it < 8; it++) {
            int idx = it * 256 + tid;
            int p = idx & 63, sq = idx >> 6;
            int t0 = tb + s0 + 2 * sq;
            float v0 = xbc[(long)t0 * CDIM + h * HD + p] * dt[t0 * NH + h];
            float v1 = xbc[(long)(t0 + 1) * CDIM + h * HD + p] * dt[(t0 + 1) * NH + h];
            Bt[p * YSTR + sq] = f2h2(v0, v1);
        }
        __syncthreads();
        if (wid * 32 + 31 >= s0) {
#pragma unroll
            for (int ks = 0; ks < 4; ks++) {
                unsigned bf[8][2];
#pragma unroll
                for (int nt = 0; nt < 8; nt++) {
                    const unsigned* bp = Bt + (nt * 8 + g) * YSTR + ks * 8;
                    bf[nt][0] = bp[tig]; bf[nt][1] = bp[tig + 4];
                }
#pragma unroll
                for (int mt = 0; mt < 2; mt++) {
                    const unsigned* ap = At + (wid * 32 + mt * 16 + g) * YSTR + ks * 8;
                    unsigned a0 = ap[tig], a2 = ap[tig + 4];
                    unsigned a1 = ap[8 * YSTR + tig], a3 = ap[8 * YSTR + tig + 4];
#pragma unroll
                    for (int nt = 0; nt < 8; nt++)
                        mma_h16(acc[mt][nt][0], acc[mt][nt][1], acc[mt][nt][2], acc[mt][nt][3],
                                a0, a1, a2, a3, bf[nt][0], bf[nt][1]);
                }
            }
        }
        __syncthreads();
    }

    // ---- phase 2: Y_off, 2 n-subtiles of 64 ----
    const float* pvb = pv + ((long)blockIdx.x << 13);
    for (int ns = 0; ns < 2; ns++) {
        int n0 = ns * 64;
#pragma unroll
        for (int it = 0; it < 32; it++) {
            int idx = it * 256 + tid;
            int np = idx & 31, l = idx >> 5;
            float el = sel[l];
            float2 v = *(const float2*)&xbc[(long)(tb + l) * CDIM + DINNER + NST + n0 + 2 * np];
            At[l * YSTR + np] = f2h2(v.x * el, v.y * el);
        }
#pragma unroll
        for (int it = 0; it < 8; it++) {
            int idx = it * 256 + tid;
            int np = idx & 31, p = idx >> 5;
            float2 v = *(const float2*)&pvb[p * NST + n0 + 2 * np];
            Bt[p * YSTR + np] = f2h2(v.x, v.y);
        }
        __syncthreads();
#pragma unroll
        for (int ks = 0; ks < 4; ks++) {
            unsigned bf[8][2];
#pragma unroll
            for (int nt = 0; nt < 8; nt++) {
                const unsigned* bp = Bt + (nt * 8 + g) * YSTR + ks * 8;
                bf[nt][0] = bp[tig]; bf[nt][1] = bp[tig + 4];
            }
#pragma unroll
            for (int mt = 0; mt < 2; mt++) {
                const unsigned* ap = At + (wid * 32 + mt * 16 + g) * YSTR + ks * 8;
                unsigned a0 = ap[tig], a2 = ap[tig + 4];
                unsigned a1 = ap[8 * YSTR + tig], a3 = ap[8 * YSTR + tig + 4];
#pragma unroll
                for (int nt = 0; nt < 8; nt++)
                    mma_h16(acc[mt][nt][0], acc[mt][nt][1], acc[mt][nt][2], acc[mt][nt][3],
                            a0, a1, a2, a3, bf[nt][0], bf[nt][1]);
            }
        }
        __syncthreads();
    }

    // ---- epilogue: + D*x, gate silu(z) ----
    float dsk = Dsk[h];
#pragma unroll
    for (int mt = 0; mt < 2; mt++) {
#pragma unroll
        for (int nt = 0; nt < 8; nt++) {
            int col = nt * 8 + tig * 2;
#pragma unroll
            for (int rr = 0; rr < 2; rr++) {
                int l = wid * 32 + mt * 16 + g + rr * 8;
                int t = tb + l;
                float2 xv = *(const float2*)&xbc[(long)t * CDIM + h * HD + col];
                float2 zv = *(const float2*)&zx[(long)t * DPROJ + h * HD + col];
                float o0 = (acc[mt][nt][rr * 2 + 0] + xv.x * dsk) * fsilu(zv.x);
                float o1 = (acc[mt][nt][rr * 2 + 1] + xv.y * dsk) * fsilu(zv.y);
                *(float2*)&y[(long)t * DINNER + h * HD + col] = make_float2(o0, o1);
            }
        }
    }
}

// ---------------- RMSNorm ----------------
__global__ void k_rms(float* __restrict__ y, const float* __restrict__ nw)
{
    int t = blockIdx.x;
    float* row = y + (long)t * DINNER;
    float ss = 0.f;
    for (int i = threadIdx.x; i < DINNER; i += 256) { float v = row[i]; ss = fmaf(v, v, ss); }
    __shared__ float red[256];
    red[threadIdx.x] = ss; __syncthreads();
    for (int o = 128; o > 0; o >>= 1) {
        if (threadIdx.x < o) red[threadIdx.x] += red[threadIdx.x + o];
        __syncthreads();
    }
    float sc = rsqrtf(red[0] / (float)DINNER + 1e-5f);
    for (int i = threadIdx.x; i < DINNER; i += 256) row[i] = row[i] * sc * nw[i];
}

// ---------------- launch ----------------
extern "C" void kernel_launch(void* const* d_in, const int* in_sizes, int n_in,
                              void* d_out, int out_size)
{
    const float* u     = (const float*)d_in[0];
    const float* Win   = (const float*)d_in[1];
    const float* convw = (const float*)d_in[2];
    const float* convb = (const float*)d_in[3];
    const float* dtb   = (const float*)d_in[4];
    const float* Alog  = (const float*)d_in[5];
    const float* Dsk   = (const float*)d_in[6];
    const float* nw    = (const float*)d_in[7];
    const float* Wout  = (const float*)d_in[8];
    float* out = (float*)d_out;

    static float *zx = nullptr, *xbc, *dt, *dacs, *cb, *st, *pv, *y;
    if (!zx) {
        cudaGetSymbolAddress((void**)&xbc,  g_xbc);
        cudaGetSymbolAddress((void**)&dt,   g_dtv);
        cudaGetSymbolAddress((void**)&dacs, g_dacs);
        cudaGetSymbolAddress((void**)&cb,   g_cb);
        cudaGetSymbolAddress((void**)&st,   g_st);
        cudaGetSymbolAddress((void**)&pv,   g_pv);
        cudaGetSymbolAddress((void**)&y,    g_y);
        cudaGetSymbolAddress((void**)&zx,   g_zx);
    }

    // 1) in_proj: zx = u @ Win^T   (M=4096, N=8512, K=2048)
    gemm_h16<<<dim3(DPROJ / 64, TOK / 128, 1), 256>>>(u, Win, zx,
        DMODEL, DMODEL, DMODEL, DPROJ, 0, 0, 0);

    // 2) dt softplus
    k_dt<<<(TOK * NH + 255) / 256, 256>>>(zx, dtb, dt);

    // 3) conv + silu
    k_conv<<<(int)(((long)TOK * CDIM + 255) / 256), 256>>>(zx, convw, convb, xbc);

    // 4) dA cumsum
    k_dacs<<<NCC * NH, CK>>>(dt, Alog, dacs);

    // 5) CB^T[cc][s][l] = B[s]·C[l]   (batched)
    gemm_h16<<<dim3(CK / 64, CK / 128, NCC), 256>>>(xbc + DINNER, xbc + DINNER + NST, cb,
        NST, CDIM, CDIM, CK, (long)CK * CDIM, (long)CK * CDIM, (long)CK * CK);

    // 6) chunk states (tensor-core)
    k_states_mma<<<NCC * NH, 256>>>(xbc, dt, dacs, st);

    // 7) inter-chunk scan
    k_scan<<<2 * NH, 256>>>(st, dacs, pv);

    // 8) Y = Y_diag + Y_off + skip, gated  (tensor-core)
    k_y_mma<<<NCC * NH, 256>>>(xbc, zx, dt, dacs, cb, pv, Dsk, y);

    // 9) RMSNorm
    k_rms<<<TOK, 256>>>(y, nw);

    // 10) out_proj: out = y @ Wout^T  (M=4096, N=2048, K=4096)
    gemm_h16<<<dim3(DMODEL / 64, TOK / 128, 1), 256>>>(y, Wout, out,
        DINNER, DINNER, DINNER, DMODEL, 0, 0, 0);
}

// round 10
// speedup vs baseline: 1.9565x; 1.0964x over previous
#include <cuda_runtime.h>
#include <cuda_fp16.h>

// ---------------- problem constants ----------------
#define TOK    4096        // BATCH*SEQLEN
#define DMODEL 2048
#define DINNER 4096
#define NH     64
#define HD     64
#define NST    128
#define CDIM   4352        // DINNER + 2*NST
#define DPROJ  8512        // 2*DINNER + 2*NST + NH
#define SEQ    2048
#define CK     256         // chunk length
#define NCC    16          // BATCH * (SEQ/CK) total chunks

// ---------------- scratch (device globals; no allocation) ----------------
__device__ __align__(16) float g_zx  [(size_t)TOK*DPROJ];
__device__ __align__(16) float g_xbc [(size_t)TOK*CDIM];
__device__ __align__(16) float g_dtv [(size_t)TOK*NH];
__device__ __align__(16) float g_dacs[(size_t)NCC*NH*CK];
__device__ __align__(16) float g_cb  [(size_t)NCC*CK*CK];
__device__ __align__(16) float g_st  [(size_t)NCC*NH*HD*NST];
__device__ __align__(16) float g_pv  [(size_t)NCC*NH*HD*NST];
__device__ __align__(16) float g_y   [(size_t)TOK*DINNER];

// ---------------- helpers ----------------
__device__ __forceinline__ unsigned f2h2(float lo, float hi) {
    __half2 h = __floats2half2_rn(lo, hi);
    return *(unsigned*)&h;
}
__device__ __forceinline__ void mma_h16(float& c0, float& c1, float& c2, float& c3,
                                        unsigned a0, unsigned a1, unsigned a2, unsigned a3,
                                        unsigned b0, unsigned b1) {
    asm volatile("mma.sync.aligned.m16n8k16.row.col.f32.f16.f16.f32 "
                 "{%0,%1,%2,%3}, {%4,%5,%6,%7}, {%8,%9}, {%0,%1,%2,%3};"
                 : "+f"(c0), "+f"(c1), "+f"(c2), "+f"(c3)
                 : "r"(a0), "r"(a1), "r"(a2), "r"(a3), "r"(b0), "r"(b1));
}
__device__ __forceinline__ float fsilu(float v) {
    return v * __fdividef(1.f, 1.f + __expf(-v));
}

// ---------------- fp16 tensor-core GEMM: C[m,n] = sum_k A[m,k]*B[n,k] ----------------
// BM=128, BN=128, BK=16, 256 threads (8 warps), warp tile 32x64 via m16n8k16.
// N handled raggedly: B row loads clamped, C stores guarded (store cols are even, 2-wide).
#define HSTR 12
__global__ __launch_bounds__(256) void gemm_h16(
    const float* __restrict__ A, const float* __restrict__ B, float* __restrict__ C,
    int K, int lda, int ldb, int ldc, int N, long aB, long bB, long cB)
{
    const float* Ab = A + (long)blockIdx.z * aB;
    const float* Bb = B + (long)blockIdx.z * bB;
    float*       Cb = C + (long)blockIdx.z * cB;

    __shared__ unsigned As[128 * HSTR];
    __shared__ unsigned Bs[128 * HSTR];

    int tid  = threadIdx.x;
    int wid  = tid >> 5, lane = tid & 31;
    int g    = lane >> 2, tig = lane & 3;
    int wm   = wid & 3, wn = wid >> 2;          // 4 m-warps x 2 n-warps; warp tile 32x64
    int m0   = blockIdx.y * 128, n0 = blockIdx.x * 128;

    int aRow = tid >> 1, aColF = (tid & 1) * 8;
    const float* aptr = Ab + (long)(m0 + aRow) * lda + aColF;
    int bR = n0 + aRow; if (bR >= N) bR = N - 1;     // clamp ragged rows
    const float* bptr = Bb + (long)bR * ldb + aColF;

    float acc[2][8][4];
#pragma unroll
    for (int i = 0; i < 2; i++)
#pragma unroll
        for (int j = 0; j < 8; j++)
#pragma unroll
            for (int r = 0; r < 4; r++) acc[i][j][r] = 0.f;

    float4 ra0 = *(const float4*)(aptr);
    float4 ra1 = *(const float4*)(aptr + 4);
    float4 rb0 = *(const float4*)(bptr);
    float4 rb1 = *(const float4*)(bptr + 4);

    for (int k0 = 0; k0 < K; k0 += 16) {
        unsigned* as = As + aRow * HSTR + (tid & 1) * 4;
        as[0] = f2h2(ra0.x, ra0.y); as[1] = f2h2(ra0.z, ra0.w);
        as[2] = f2h2(ra1.x, ra1.y); as[3] = f2h2(ra1.z, ra1.w);
        unsigned* bs = Bs + aRow * HSTR + (tid & 1) * 4;
        bs[0] = f2h2(rb0.x, rb0.y); bs[1] = f2h2(rb0.z, rb0.w);
        bs[2] = f2h2(rb1.x, rb1.y); bs[3] = f2h2(rb1.z, rb1.w);
        __syncthreads();

        if (k0 + 16 < K) {
            ra0 = *(const float4*)(aptr + k0 + 16);
            ra1 = *(const float4*)(aptr + k0 + 20);
            rb0 = *(const float4*)(bptr + k0 + 16);
            rb1 = *(const float4*)(bptr + k0 + 20);
        }

        unsigned bf[8][2];
#pragma unroll
        for (int nt = 0; nt < 8; nt++) {
            const unsigned* bp = Bs + (wn * 64 + nt * 8 + g) * HSTR;
            bf[nt][0] = bp[tig]; bf[nt][1] = bp[tig + 4];
        }
#pragma unroll
        for (int mt = 0; mt < 2; mt++) {
            const unsigned* ap0 = As + (wm * 32 + mt * 16 + g) * HSTR;
            const unsigned* ap1 = ap0 + 8 * HSTR;
            unsigned a0 = ap0[tig], a2 = ap0[tig + 4];
            unsigned a1 = ap1[tig], a3 = ap1[tig + 4];
#pragma unroll
            for (int nt = 0; nt < 8; nt++)
                mma_h16(acc[mt][nt][0], acc[mt][nt][1], acc[mt][nt][2], acc[mt][nt][3],
                        a0, a1, a2, a3, bf[nt][0], bf[nt][1]);
        }
        __syncthreads();
    }

#pragma unroll
    for (int mt = 0; mt < 2; mt++) {
#pragma unroll
        for (int nt = 0; nt < 8; nt++) {
            int row = m0 + wm * 32 + mt * 16 + g;
            int col = n0 + wn * 64 + nt * 8 + tig * 2;
            if (col < N) {
                *(float2*)(Cb + (long)row * ldc + col)       = make_float2(acc[mt][nt][0], acc[mt][nt][1]);
                *(float2*)(Cb + (long)(row + 8) * ldc + col) = make_float2(acc[mt][nt][2], acc[mt][nt][3]);
            }
        }
    }
}

// ---------------- dt = softplus(raw + bias) ----------------
__global__ void k_dt(const float* __restrict__ zx, const float* __restrict__ dt_bias,
                     float* __restrict__ dt)
{
    int i = blockIdx.x * 256 + threadIdx.x;
    if (i >= TOK * NH) return;
    int t = i >> 6, h = i & 63;
    float v = zx[(long)t * DPROJ + (DINNER + CDIM) + h] + dt_bias[h];
    dt[i] = (v > 20.f) ? v : log1pf(expf(v));
}

// ---------------- causal conv1d(width 4) + bias + silu ----------------
__global__ void k_conv(const float* __restrict__ zx, const float* __restrict__ w,
                       const float* __restrict__ bias, float* __restrict__ xbc)
{
    long i = (long)blockIdx.x * 256 + threadIdx.x;
    if (i >= (long)TOK * CDIM) return;
    int t = (int)(i / CDIM), c = (int)(i % CDIM);
    int l = t & (SEQ - 1);
    float acc = bias[c];
#pragma unroll
    for (int k = 0; k < 4; k++) {
        int lt = l - 3 + k;
        if (lt >= 0)
            acc = fmaf(w[c * 4 + k], zx[(long)(t - 3 + k) * DPROJ + DINNER + c], acc);
    }
    xbc[i] = fsilu(acc);
}

// ---------------- per-(chunk,head) cumsum of dt*A ----------------
__global__ void k_dacs(const float* __restrict__ dt, const float* __restrict__ Alog,
                       float* __restrict__ dacs)
{
    int cc = blockIdx.x >> 6, h = blockIdx.x & 63;
    int s = threadIdx.x;
    int t = cc * CK + s;
    float a = -expf(Alog[h]);
    float v = dt[t * NH + h] * a;
    __shared__ float sm[CK];
    sm[s] = v; __syncthreads();
    for (int off = 1; off < CK; off <<= 1) {
        float tv = (s >= off) ? sm[s - off] : 0.f;
        __syncthreads();
        sm[s] += tv;
        __syncthreads();
    }
    dacs[(blockIdx.x << 8) + s] = sm[s];
}

// ======= chunk states via fp16 MMA =======
#define YSTR 36
__global__ __launch_bounds__(256) void k_states_mma(const float* __restrict__ xbc,
        const float* __restrict__ dt, const float* __restrict__ dacs, float* __restrict__ st)
{
    const int cc = blockIdx.x >> 6, h = blockIdx.x & 63;
    const int tb = cc * CK;
    const int tid = threadIdx.x, wid = tid >> 5, lane = tid & 31;
    const int g = lane >> 2, tig = lane & 3;
    const int wm = wid & 3, wn = wid >> 2;

    __shared__ unsigned At[64 * YSTR];
    __shared__ unsigned Bt[128 * YSTR];
    __shared__ float sdecay[CK];

    const float* dA = dacs + (blockIdx.x << 8);
    {
        float dlast = dA[CK - 1];
        sdecay[tid] = __expf(dlast - dA[tid]);
    }
    __syncthreads();

    float acc[8][4];
#pragma unroll
    for (int j = 0; j < 8; j++)
#pragma unroll
        for (int r = 0; r < 4; r++) acc[j][r] = 0.f;

    for (int s0 = 0; s0 < CK; s0 += 64) {
#pragma unroll
        for (int it = 0; it < 8; it++) {
            int idx = it * 256 + tid;
            int p = idx & 63, sq = idx >> 6;
            int t0 = tb + s0 + 2 * sq;
            float v0 = xbc[(long)t0 * CDIM + h * HD + p] * dt[t0 * NH + h];
            float v1 = xbc[(long)(t0 + 1) * CDIM + h * HD + p] * dt[(t0 + 1) * NH + h];
            At[p * YSTR + sq] = f2h2(v0, v1);
        }
#pragma unroll
        for (int it = 0; it < 16; it++) {
            int idx = it * 256 + tid;
            int n = idx & 127, sq = idx >> 7;
            int t0 = tb + s0 + 2 * sq;
            float v0 = xbc[(long)t0 * CDIM + DINNER + n] * sdecay[s0 + 2 * sq];
            float v1 = xbc[(long)(t0 + 1) * CDIM + DINNER + n] * sdecay[s0 + 2 * sq + 1];
            Bt[n * YSTR + sq] = f2h2(v0, v1);
        }
        __syncthreads();
#pragma unroll
        for (int ks = 0; ks < 4; ks++) {
            unsigned bf[8][2];
#pragma unroll
            for (int nt = 0; nt < 8; nt++) {
                const unsigned* bp = Bt + (wn * 64 + nt * 8 + g) * YSTR + ks * 8;
                bf[nt][0] = bp[tig]; bf[nt][1] = bp[tig + 4];
            }
            const unsigned* ap = At + (wm * 16 + g) * YSTR + ks * 8;
            unsigned a0 = ap[tig], a2 = ap[tig + 4];
            unsigned a1 = ap[8 * YSTR + tig], a3 = ap[8 * YSTR + tig + 4];
#pragma unroll
            for (int nt = 0; nt < 8; nt++)
                mma_h16(acc[nt][0], acc[nt][1], acc[nt][2], acc[nt][3],
                        a0, a1, a2, a3, bf[nt][0], bf[nt][1]);
        }
        __syncthreads();
    }

    float* ob = st + ((long)blockIdx.x << 13);
#pragma unroll
    for (int nt = 0; nt < 8; nt++) {
        int col = wn * 64 + nt * 8 + tig * 2;
        int row = wm * 16 + g;
        *(float2*)(ob + row * NST + col)       = make_float2(acc[nt][0], acc[nt][1]);
        *(float2*)(ob + (row + 8) * NST + col) = make_float2(acc[nt][2], acc[nt][3]);
    }
}

// ---------------- sequential chunk scan ----------------
__global__ void k_scan(const float* __restrict__ st, const float* __restrict__ dacs,
                       float* __restrict__ pv)
{
    int b = blockIdx.x >> 6, h = blockIdx.x & 63;
    int tid = threadIdx.x;
    float carry[32];
#pragma unroll
    for (int j = 0; j < 32; j++) carry[j] = 0.f;
    for (int c = 0; c < 8; c++) {
        int cc = b * 8 + c;
        long base = ((long)(cc * 64 + h)) << 13;
        float dec = __expf(dacs[((cc * 64 + h) << 8) + CK - 1]);
#pragma unroll
        for (int j = 0; j < 32; j++) {
            long e = base + tid + j * 256;
            pv[e] = carry[j];
            carry[j] = carry[j] * dec + st[e];
        }
    }
}

// ======= k_y via fp16 MMA: Y = (W@xdt) + (C*el)@prev^T, + D*x, gated =======
__global__ __launch_bounds__(256) void k_y_mma(const float* __restrict__ xbc,
        const float* __restrict__ zx, const float* __restrict__ dt,
        const float* __restrict__ dacs, const float* __restrict__ cb,
        const float* __restrict__ pv, const float* __restrict__ Dsk,
        float* __restrict__ y)
{
    const int cc = blockIdx.x >> 6, h = blockIdx.x & 63;
    const int tb = cc * CK;
    const int tid = threadIdx.x, wid = tid >> 5, lane = tid & 31;
    const int g = lane >> 2, tig = lane & 3;

    __shared__ unsigned At[256 * YSTR];
    __shared__ unsigned Bt[64 * YSTR];
    __shared__ float sda[256];
    __shared__ float sel[256];

    sda[tid] = dacs[(blockIdx.x << 8) + tid];
    __syncthreads();
    sel[tid] = __expf(sda[tid]);

    float acc[2][8][4];
#pragma unroll
    for (int i = 0; i < 2; i++)
#pragma unroll
        for (int j = 0; j < 8; j++)
#pragma unroll
            for (int r = 0; r < 4; r++) acc[i][j][r] = 0.f;

    const float* cbb = cb + ((long)cc << 16);

    // ---- phase 1: Y_diag, 4 s-tiles of 64 ----
    for (int st4 = 0; st4 < 4; st4++) {
        int s0 = st4 * 64;
        {
            int l = tid;
            unsigned* arow = At + l * YSTR;
            if (l < s0) {
#pragma unroll 8
                for (int it = 0; it < 32; it++) arow[it] = 0u;
            } else {
                float dal = sda[l];
#pragma unroll 4
                for (int it = 0; it < 32; it++) {
                    int s = s0 + 2 * it;
                    float w0 = 0.f, w1 = 0.f;
                    if (s <= l) {
                        w0 = __expf(dal - sda[s]) * cbb[(s << 8) + l];
                        if (s + 1 <= l)
                            w1 = __expf(dal - sda[s + 1]) * cbb[((s + 1) << 8) + l];
                    }
                    arow[it] = f2h2(w0, w1);
                }
            }
        }
#pragma unroll
        for (int it = 0; it < 8; it++) {
            int idx = it * 256 + tid;
            int p = idx & 63, sq = idx >> 6;
            int t0 = tb + s0 + 2 * sq;
            float v0 = xbc[(long)t0 * CDIM + h * HD + p] * dt[t0 * NH + h];
            float v1 = xbc[(long)(t0 + 1) * CDIM + h * HD + p] * dt[(t0 + 1) * NH + h];
            Bt[p * YSTR + sq] = f2h2(v0, v1);
        }
        __syncthreads();
        if (wid * 32 + 31 >= s0) {
#pragma unroll
            for (int ks = 0; ks < 4; ks++) {
                unsigned bf[8][2];
#pragma unroll
                for (int nt = 0; nt < 8; nt++) {
                    const unsigned* bp = Bt + (nt * 8 + g) * YSTR + ks * 8;
                    bf[nt][0] = bp[tig]; bf[nt][1] = bp[tig + 4];
                }
#pragma unroll
                for (int mt = 0; mt < 2; mt++) {
                    const unsigned* ap = At + (wid * 32 + mt * 16 + g) * YSTR + ks * 8;
                    unsigned a0 = ap[tig], a2 = ap[tig + 4];
                    unsigned a1 = ap[8 * YSTR + tig], a3 = ap[8 * YSTR + tig + 4];
#pragma unroll
                    for (int nt = 0; nt < 8; nt++)
                        mma_h16(acc[mt][nt][0], acc[mt][nt][1], acc[mt][nt][2], acc[mt][nt][3],
                                a0, a1, a2, a3, bf[nt][0], bf[nt][1]);
                }
            }
        }
        __syncthreads();
    }

    // ---- phase 2: Y_off, 2 n-subtiles of 64 ----
    const float* pvb = pv + ((long)blockIdx.x << 13);
    for (int ns = 0; ns < 2; ns++) {
        int n0 = ns * 64;
#pragma unroll
        for (int it = 0; it < 32; it++) {
            int idx = it * 256 + tid;
            int np = idx & 31, l = idx >> 5;
            float el = sel[l];
            float2 v = *(const float2*)&xbc[(long)(tb + l) * CDIM + DINNER + NST + n0 + 2 * np];
            At[l * YSTR + np] = f2h2(v.x * el, v.y * el);
        }
#pragma unroll
        for (int it = 0; it < 8; it++) {
            int idx = it * 256 + tid;
            int np = idx & 31, p = idx >> 5;
            float2 v = *(const float2*)&pvb[p * NST + n0 + 2 * np];
            Bt[p * YSTR + np] = f2h2(v.x, v.y);
        }
        __syncthreads();
#pragma unroll
        for (int ks = 0; ks < 4; ks++) {
            unsigned bf[8][2];
#pragma unroll
            for (int nt = 0; nt < 8; nt++) {
                const unsigned* bp = Bt + (nt * 8 + g) * YSTR + ks * 8;
                bf[nt][0] = bp[tig]; bf[nt][1] = bp[tig + 4];
            }
#pragma unroll
            for (int mt = 0; mt < 2; mt++) {
                const unsigned* ap = At + (wid * 32 + mt * 16 + g) * YSTR + ks * 8;
                unsigned a0 = ap[tig], a2 = ap[tig + 4];
                unsigned a1 = ap[8 * YSTR + tig], a3 = ap[8 * YSTR + tig + 4];
#pragma unroll
                for (int nt = 0; nt < 8; nt++)
                    mma_h16(acc[mt][nt][0], acc[mt][nt][1], acc[mt][nt][2], acc[mt][nt][3],
                            a0, a1, a2, a3, bf[nt][0], bf[nt][1]);
            }
        }
        __syncthreads();
    }

    // ---- epilogue: + D*x, gate silu(z) ----
    float dsk = Dsk[h];
#pragma unroll
    for (int mt = 0; mt < 2; mt++) {
#pragma unroll
        for (int nt = 0; nt < 8; nt++) {
            int col = nt * 8 + tig * 2;
#pragma unroll
            for (int rr = 0; rr < 2; rr++) {
                int l = wid * 32 + mt * 16 + g + rr * 8;
                int t = tb + l;
                float2 xv = *(const float2*)&xbc[(long)t * CDIM + h * HD + col];
                float2 zv = *(const float2*)&zx[(long)t * DPROJ + h * HD + col];
                float o0 = (acc[mt][nt][rr * 2 + 0] + xv.x * dsk) * fsilu(zv.x);
                float o1 = (acc[mt][nt][rr * 2 + 1] + xv.y * dsk) * fsilu(zv.y);
                *(float2*)&y[(long)t * DINNER + h * HD + col] = make_float2(o0, o1);
            }
        }
    }
}

// ---------------- RMSNorm ----------------
__global__ void k_rms(float* __restrict__ y, const float* __restrict__ nw)
{
    int t = blockIdx.x;
    float* row = y + (long)t * DINNER;
    float ss = 0.f;
    for (int i = threadIdx.x; i < DINNER; i += 256) { float v = row[i]; ss = fmaf(v, v, ss); }
    __shared__ float red[256];
    red[threadIdx.x] = ss; __syncthreads();
    for (int o = 128; o > 0; o >>= 1) {
        if (threadIdx.x < o) red[threadIdx.x] += red[threadIdx.x + o];
        __syncthreads();
    }
    float sc = rsqrtf(red[0] / (float)DINNER + 1e-5f);
    for (int i = threadIdx.x; i < DINNER; i += 256) row[i] = row[i] * sc * nw[i];
}

// ---------------- launch ----------------
extern "C" void kernel_launch(void* const* d_in, const int* in_sizes, int n_in,
                              void* d_out, int out_size)
{
    const float* u     = (const float*)d_in[0];
    const float* Win   = (const float*)d_in[1];
    const float* convw = (const float*)d_in[2];
    const float* convb = (const float*)d_in[3];
    const float* dtb   = (const float*)d_in[4];
    const float* Alog  = (const float*)d_in[5];
    const float* Dsk   = (const float*)d_in[6];
    const float* nw    = (const float*)d_in[7];
    const float* Wout  = (const float*)d_in[8];
    float* out = (float*)d_out;

    static float *zx = nullptr, *xbc, *dt, *dacs, *cb, *st, *pv, *y;
    if (!zx) {
        cudaGetSymbolAddress((void**)&xbc,  g_xbc);
        cudaGetSymbolAddress((void**)&dt,   g_dtv);
        cudaGetSymbolAddress((void**)&dacs, g_dacs);
        cudaGetSymbolAddress((void**)&cb,   g_cb);
        cudaGetSymbolAddress((void**)&st,   g_st);
        cudaGetSymbolAddress((void**)&pv,   g_pv);
        cudaGetSymbolAddress((void**)&y,    g_y);
        cudaGetSymbolAddress((void**)&zx,   g_zx);
    }

    // 1) in_proj: zx = u @ Win^T   (M=4096, N=8512, K=2048); ragged N -> 67 BN=128 tiles
    gemm_h16<<<dim3((DPROJ + 127) / 128, TOK / 128, 1), 256>>>(u, Win, zx,
        DMODEL, DMODEL, DMODEL, DPROJ, DPROJ, 0, 0, 0);

    // 2) dt softplus
    k_dt<<<(TOK * NH + 255) / 256, 256>>>(zx, dtb, dt);

    // 3) conv + silu
    k_conv<<<(int)(((long)TOK * CDIM + 255) / 256), 256>>>(zx, convw, convb, xbc);

    // 4) dA cumsum
    k_dacs<<<NCC * NH, CK>>>(dt, Alog, dacs);

    // 5) CB^T[cc][s][l] = B[s]·C[l]   (batched, M=256,N=256,K=128)
    gemm_h16<<<dim3(CK / 128, CK / 128, NCC), 256>>>(xbc + DINNER, xbc + DINNER + NST, cb,
        NST, CDIM, CDIM, CK, CK, (long)CK * CDIM, (long)CK * CDIM, (long)CK * CK);

    // 6) chunk states (tensor-core)
    k_states_mma<<<NCC * NH, 256>>>(xbc, dt, dacs, st);

    // 7) inter-chunk scan
    k_scan<<<2 * NH, 256>>>(st, dacs, pv);

    // 8) Y = Y_diag + Y_off + skip, gated  (tensor-core)
    k_y_mma<<<NCC * NH, 256>>>(xbc, zx, dt, dacs, cb, pv, Dsk, y);

    // 9) RMSNorm
    k_rms<<<TOK, 256>>>(y, nw);

    // 10) out_proj: out = y @ Wout^T  (M=4096, N=2048, K=4096)
    gemm_h16<<<dim3(DMODEL / 128, TOK / 128, 1), 256>>>(y, Wout, out,
        DINNER, DINNER, DINNER, DMODEL, DMODEL, 0, 0, 0);
}

// round 11
// speedup vs baseline: 1.9997x; 1.0221x over previous
#include <cuda_runtime.h>
#include <cuda_fp16.h>

// ---------------- problem constants ----------------
#define TOK    4096        // BATCH*SEQLEN
#define DMODEL 2048
#define DINNER 4096
#define NH     64
#define HD     64
#define NST    128
#define CDIM   4352        // DINNER + 2*NST
#define DPROJ  8512        // 2*DINNER + 2*NST + NH
#define SEQ    2048
#define CK     256         // chunk length
#define NCC    16          // BATCH * (SEQ/CK) total chunks

// ---------------- scratch (device globals; no allocation) ----------------
__device__ __align__(16) float g_zx  [(size_t)TOK*DPROJ];
__device__ __align__(16) float g_xbc [(size_t)TOK*CDIM];
__device__ __align__(16) float g_dtv [(size_t)TOK*NH];
__device__ __align__(16) float g_dacs[(size_t)NCC*NH*CK];
__device__ __align__(16) float g_cb  [(size_t)NCC*CK*CK];
__device__ __align__(16) float g_st  [(size_t)NCC*NH*HD*NST];
__device__ __align__(16) float g_pv  [(size_t)NCC*NH*HD*NST];
__device__ __align__(16) float g_y   [(size_t)TOK*DINNER];

// ---------------- helpers ----------------
__device__ __forceinline__ unsigned f2h2(float lo, float hi) {
    __half2 h = __floats2half2_rn(lo, hi);
    return *(unsigned*)&h;
}
__device__ __forceinline__ void mma_h16(float& c0, float& c1, float& c2, float& c3,
                                        unsigned a0, unsigned a1, unsigned a2, unsigned a3,
                                        unsigned b0, unsigned b1) {
    asm volatile("mma.sync.aligned.m16n8k16.row.col.f32.f16.f16.f32 "
                 "{%0,%1,%2,%3}, {%4,%5,%6,%7}, {%8,%9}, {%0,%1,%2,%3};"
                 : "+f"(c0), "+f"(c1), "+f"(c2), "+f"(c3)
                 : "r"(a0), "r"(a1), "r"(a2), "r"(a3), "r"(b0), "r"(b1));
}
__device__ __forceinline__ float fsilu(float v) {
    return v * __fdividef(1.f, 1.f + __expf(-v));
}

// ---------------- fp16 tensor-core GEMM: C[m,n] = sum_k A[m,k]*B[n,k] ----------------
// BM=128, BN=128, BK=16, 256 threads (8 warps), warp tile 32x64, DOUBLE-BUFFERED.
#define HSTR 12
__global__ __launch_bounds__(256) void gemm_h16(
    const float* __restrict__ A, const float* __restrict__ B, float* __restrict__ C,
    int K, int lda, int ldb, int ldc, int N, long aB, long bB, long cB)
{
    const float* Ab = A + (long)blockIdx.z * aB;
    const float* Bb = B + (long)blockIdx.z * bB;
    float*       Cb = C + (long)blockIdx.z * cB;

    __shared__ unsigned As[2][128 * HSTR];
    __shared__ unsigned Bs[2][128 * HSTR];

    int tid  = threadIdx.x;
    int wid  = tid >> 5, lane = tid & 31;
    int g    = lane >> 2, tig = lane & 3;
    int wm   = wid & 3, wn = wid >> 2;          // 4 m-warps x 2 n-warps; warp tile 32x64
    int m0   = blockIdx.y * 128, n0 = blockIdx.x * 128;

    int aRow = tid >> 1, aColF = (tid & 1) * 8;
    const float* aptr = Ab + (long)(m0 + aRow) * lda + aColF;
    int bR = n0 + aRow; if (bR >= N) bR = N - 1;     // clamp ragged rows
    const float* bptr = Bb + (long)bR * ldb + aColF;

    float acc[2][8][4];
#pragma unroll
    for (int i = 0; i < 2; i++)
#pragma unroll
        for (int j = 0; j < 8; j++)
#pragma unroll
            for (int r = 0; r < 4; r++) acc[i][j][r] = 0.f;

    float4 ra0 = *(const float4*)(aptr);
    float4 ra1 = *(const float4*)(aptr + 4);
    float4 rb0 = *(const float4*)(bptr);
    float4 rb1 = *(const float4*)(bptr + 4);
    {
        unsigned* as = As[0] + aRow * HSTR + (tid & 1) * 4;
        as[0] = f2h2(ra0.x, ra0.y); as[1] = f2h2(ra0.z, ra0.w);
        as[2] = f2h2(ra1.x, ra1.y); as[3] = f2h2(ra1.z, ra1.w);
        unsigned* bs = Bs[0] + aRow * HSTR + (tid & 1) * 4;
        bs[0] = f2h2(rb0.x, rb0.y); bs[1] = f2h2(rb0.z, rb0.w);
        bs[2] = f2h2(rb1.x, rb1.y); bs[3] = f2h2(rb1.z, rb1.w);
    }
    __syncthreads();

    int cur = 0;
    for (int k0 = 0; k0 < K; k0 += 16) {
        bool nxt = (k0 + 16) < K;
        if (nxt) {
            ra0 = *(const float4*)(aptr + k0 + 16);
            ra1 = *(const float4*)(aptr + k0 + 20);
            rb0 = *(const float4*)(bptr + k0 + 16);
            rb1 = *(const float4*)(bptr + k0 + 20);
        }

        const unsigned* Ac = As[cur];
        const unsigned* Bc = Bs[cur];
        unsigned bf[8][2];
#pragma unroll
        for (int nt = 0; nt < 8; nt++) {
            const unsigned* bp = Bc + (wn * 64 + nt * 8 + g) * HSTR;
            bf[nt][0] = bp[tig]; bf[nt][1] = bp[tig + 4];
        }
#pragma unroll
        for (int mt = 0; mt < 2; mt++) {
            const unsigned* ap0 = Ac + (wm * 32 + mt * 16 + g) * HSTR;
            const unsigned* ap1 = ap0 + 8 * HSTR;
            unsigned a0 = ap0[tig], a2 = ap0[tig + 4];
            unsigned a1 = ap1[tig], a3 = ap1[tig + 4];
#pragma unroll
            for (int nt = 0; nt < 8; nt++)
                mma_h16(acc[mt][nt][0], acc[mt][nt][1], acc[mt][nt][2], acc[mt][nt][3],
                        a0, a1, a2, a3, bf[nt][0], bf[nt][1]);
        }

        if (nxt) {
            int s = cur ^ 1;
            unsigned* as = As[s] + aRow * HSTR + (tid & 1) * 4;
            as[0] = f2h2(ra0.x, ra0.y); as[1] = f2h2(ra0.z, ra0.w);
            as[2] = f2h2(ra1.x, ra1.y); as[3] = f2h2(ra1.z, ra1.w);
            unsigned* bs = Bs[s] + aRow * HSTR + (tid & 1) * 4;
            bs[0] = f2h2(rb0.x, rb0.y); bs[1] = f2h2(rb0.z, rb0.w);
            bs[2] = f2h2(rb1.x, rb1.y); bs[3] = f2h2(rb1.z, rb1.w);
        }
        __syncthreads();
        cur ^= 1;
    }

#pragma unroll
    for (int mt = 0; mt < 2; mt++) {
#pragma unroll
        for (int nt = 0; nt < 8; nt++) {
            int row = m0 + wm * 32 + mt * 16 + g;
            int col = n0 + wn * 64 + nt * 8 + tig * 2;
            if (col < N) {
                *(float2*)(Cb + (long)row * ldc + col)       = make_float2(acc[mt][nt][0], acc[mt][nt][1]);
                *(float2*)(Cb + (long)(row + 8) * ldc + col) = make_float2(acc[mt][nt][2], acc[mt][nt][3]);
            }
        }
    }
}

// ---------------- causal conv1d(width 4) + bias + silu ----------------
__global__ void k_conv(const float* __restrict__ zx, const float* __restrict__ w,
                       const float* __restrict__ bias, float* __restrict__ xbc)
{
    long i = (long)blockIdx.x * 256 + threadIdx.x;
    if (i >= (long)TOK * CDIM) return;
    int t = (int)(i / CDIM), c = (int)(i % CDIM);
    int l = t & (SEQ - 1);
    float acc = bias[c];
#pragma unroll
    for (int k = 0; k < 4; k++) {
        int lt = l - 3 + k;
        if (lt >= 0)
            acc = fmaf(w[c * 4 + k], zx[(long)(t - 3 + k) * DPROJ + DINNER + c], acc);
    }
    xbc[i] = fsilu(acc);
}

// ------- per-(chunk,head) softplus(dt) + cumsum of dt*A (fused; writes dt too) -------
__global__ void k_dacs(const float* __restrict__ zx, const float* __restrict__ dt_bias,
                       const float* __restrict__ Alog, float* __restrict__ dtv,
                       float* __restrict__ dacs)
{
    int cc = blockIdx.x >> 6, h = blockIdx.x & 63;
    int s = threadIdx.x;
    int t = cc * CK + s;
    float raw = zx[(long)t * DPROJ + (DINNER + CDIM) + h] + dt_bias[h];
    float d = (raw > 20.f) ? raw : log1pf(expf(raw));
    dtv[t * NH + h] = d;
    float a = -expf(Alog[h]);
    float v = d * a;
    __shared__ float sm[CK];
    sm[s] = v; __syncthreads();
    for (int off = 1; off < CK; off <<= 1) {
        float tv = (s >= off) ? sm[s - off] : 0.f;
        __syncthreads();
        sm[s] += tv;
        __syncthreads();
    }
    dacs[(blockIdx.x << 8) + s] = sm[s];
}

// ======= chunk states via fp16 MMA =======
#define YSTR 36
__global__ __launch_bounds__(256) void k_states_mma(const float* __restrict__ xbc,
        const float* __restrict__ dt, const float* __restrict__ dacs, float* __restrict__ st)
{
    const int cc = blockIdx.x >> 6, h = blockIdx.x & 63;
    const int tb = cc * CK;
    const int tid = threadIdx.x, wid = tid >> 5, lane = tid & 31;
    const int g = lane >> 2, tig = lane & 3;
    const int wm = wid & 3, wn = wid >> 2;

    __shared__ unsigned At[64 * YSTR];
    __shared__ unsigned Bt[128 * YSTR];
    __shared__ float sdecay[CK];

    const float* dA = dacs + (blockIdx.x << 8);
    {
        float dlast = dA[CK - 1];
        sdecay[tid] = __expf(dlast - dA[tid]);
    }
    __syncthreads();

    float acc[8][4];
#pragma unroll
    for (int j = 0; j < 8; j++)
#pragma unroll
        for (int r = 0; r < 4; r++) acc[j][r] = 0.f;

    for (int s0 = 0; s0 < CK; s0 += 64) {
#pragma unroll
        for (int it = 0; it < 8; it++) {
            int idx = it * 256 + tid;
            int p = idx & 63, sq = idx >> 6;
            int t0 = tb + s0 + 2 * sq;
            float v0 = xbc[(long)t0 * CDIM + h * HD + p] * dt[t0 * NH + h];
            float v1 = xbc[(long)(t0 + 1) * CDIM + h * HD + p] * dt[(t0 + 1) * NH + h];
            At[p * YSTR + sq] = f2h2(v0, v1);
        }
#pragma unroll
        for (int it = 0; it < 16; it++) {
            int idx = it * 256 + tid;
            int n = idx & 127, sq = idx >> 7;
            int t0 = tb + s0 + 2 * sq;
            float v0 = xbc[(long)t0 * CDIM + DINNER + n] * sdecay[s0 + 2 * sq];
            float v1 = xbc[(long)(t0 + 1) * CDIM + DINNER + n] * sdecay[s0 + 2 * sq + 1];
            Bt[n * YSTR + sq] = f2h2(v0, v1);
        }
        __syncthreads();
#pragma unroll
        for (int ks = 0; ks < 4; ks++) {
            unsigned bf[8][2];
#pragma unroll
            for (int nt = 0; nt < 8; nt++) {
                const unsigned* bp = Bt + (wn * 64 + nt * 8 + g) * YSTR + ks * 8;
                bf[nt][0] = bp[tig]; bf[nt][1] = bp[tig + 4];
            }
            const unsigned* ap = At + (wm * 16 + g) * YSTR + ks * 8;
            unsigned a0 = ap[tig], a2 = ap[tig + 4];
            unsigned a1 = ap[8 * YSTR + tig], a3 = ap[8 * YSTR + tig + 4];
#pragma unroll
            for (int nt = 0; nt < 8; nt++)
                mma_h16(acc[nt][0], acc[nt][1], acc[nt][2], acc[nt][3],
                        a0, a1, a2, a3, bf[nt][0], bf[nt][1]);
        }
        __syncthreads();
    }

    float* ob = st + ((long)blockIdx.x << 13);
#pragma unroll
    for (int nt = 0; nt < 8; nt++) {
        int col = wn * 64 + nt * 8 + tig * 2;
        int row = wm * 16 + g;
        *(float2*)(ob + row * NST + col)       = make_float2(acc[nt][0], acc[nt][1]);
        *(float2*)(ob + (row + 8) * NST + col) = make_float2(acc[nt][2], acc[nt][3]);
    }
}

// ---------------- sequential chunk scan (4 quarter-blocks per (b,h)) ----------------
__global__ void k_scan(const float* __restrict__ st, const float* __restrict__ dacs,
                       float* __restrict__ pv)
{
    int bh = blockIdx.x >> 2, q = blockIdx.x & 3;
    int b = bh >> 6, h = bh & 63;
    int tid = threadIdx.x;
    int off = q * 2048 + tid;
    float carry[8];
#pragma unroll
    for (int j = 0; j < 8; j++) carry[j] = 0.f;
    for (int c = 0; c < 8; c++) {
        int cc = b * 8 + c;
        long base = (((long)(cc * 64 + h)) << 13) + off;
        float dec = __expf(dacs[((cc * 64 + h) << 8) + CK - 1]);
#pragma unroll
        for (int j = 0; j < 8; j++) {
            long e = base + j * 256;
            pv[e] = carry[j];
            carry[j] = carry[j] * dec + st[e];
        }
    }
}

// ======= k_y via fp16 MMA: Y = (W@xdt) + (C*el)@prev^T, + D*x, gated =======
__global__ __launch_bounds__(256) void k_y_mma(const float* __restrict__ xbc,
        const float* __restrict__ zx, const float* __restrict__ dt,
        const float* __restrict__ dacs, const float* __restrict__ cb,
        const float* __restrict__ pv, const float* __restrict__ Dsk,
        float* __restrict__ y)
{
    const int cc = blockIdx.x >> 6, h = blockIdx.x & 63;
    const int tb = cc * CK;
    const int tid = threadIdx.x, wid = tid >> 5, lane = tid & 31;
    const int g = lane >> 2, tig = lane & 3;

    __shared__ unsigned At[256 * YSTR];
    __shared__ unsigned Bt[64 * YSTR];
    __shared__ float sda[256];
    __shared__ float sel[256];

    sda[tid] = dacs[(blockIdx.x << 8) + tid];
    __syncthreads();
    sel[tid] = __expf(sda[tid]);

    float acc[2][8][4];
#pragma unroll
    for (int i = 0; i < 2; i++)
#pragma unroll
        for (int j = 0; j < 8; j++)
#pragma unroll
            for (int r = 0; r < 4; r++) acc[i][j][r] = 0.f;

    const float* cbb = cb + ((long)cc << 16);

    // ---- phase 1: Y_diag, 4 s-tiles of 64 ----
    for (int st4 = 0; st4 < 4; st4++) {
        int s0 = st4 * 64;
        {
            int l = tid;
            unsigned* arow = At + l * YSTR;
            if (l < s0) {
#pragma unroll 8
                for (int it = 0; it < 32; it++) arow[it] = 0u;
            } else {
                float dal = sda[l];
#pragma unroll 4
                for (int it = 0; it < 32; it++) {
                    int s = s0 + 2 * it;
                    float w0 = 0.f, w1 = 0.f;
                    if (s <= l) {
                        w0 = __expf(dal - sda[s]) * cbb[(s << 8) + l];
                        if (s + 1 <= l)
                            w1 = __expf(dal - sda[s + 1]) * cbb[((s + 1) << 8) + l];
                    }
                    arow[it] = f2h2(w0, w1);
                }
            }
        }
#pragma unroll
        for (int it = 0; it < 8; it++) {
            int idx = it * 256 + tid;
            int p = idx & 63, sq = idx >> 6;
            int t0 = tb + s0 + 2 * sq;
            float v0 = xbc[(long)t0 * CDIM + h * HD + p] * dt[t0 * NH + h];
            float v1 = xbc[(long)(t0 + 1) * CDIM + h * HD + p] * dt[(t0 + 1) * NH + h];
            Bt[p * YSTR + sq] = f2h2(v0, v1);
        }
        __syncthreads();
        if (wid * 32 + 31 >= s0) {
#pragma unroll
            for (int ks = 0; ks < 4; ks++) {
                unsigned bf[8][2];
#pragma unroll
                for (int nt = 0; nt < 8; nt++) {
                    const unsigned* bp = Bt + (nt * 8 + g) * YSTR + ks * 8;
                    bf[nt][0] = bp[tig]; bf[nt][1] = bp[tig + 4];
                }
#pragma unroll
                for (int mt = 0; mt < 2; mt++) {
                    const unsigned* ap = At + (wid * 32 + mt * 16 + g) * YSTR + ks * 8;
                    unsigned a0 = ap[tig], a2 = ap[tig + 4];
                    unsigned a1 = ap[8 * YSTR + tig], a3 = ap[8 * YSTR + tig + 4];
#pragma unroll
                    for (int nt = 0; nt < 8; nt++)
                        mma_h16(acc[mt][nt][0], acc[mt][nt][1], acc[mt][nt][2], acc[mt][nt][3],
                                a0, a1, a2, a3, bf[nt][0], bf[nt][1]);
                }
            }
        }
        __syncthreads();
    }

    // ---- phase 2: Y_off, 2 n-subtiles of 64 ----
    const float* pvb = pv + ((long)blockIdx.x << 13);
    for (int ns = 0; ns < 2; ns++) {
        int n0 = ns * 64;
#pragma unroll
        for (int it = 0; it < 32; it++) {
            int idx = it * 256 + tid;
            int np = idx & 31, l = idx >> 5;
            float el = sel[l];
            float2 v = *(const float2*)&xbc[(long)(tb + l) * CDIM + DINNER + NST + n0 + 2 * np];
            At[l * YSTR + np] = f2h2(v.x * el, v.y * el);
        }
#pragma unroll
        for (int it = 0; it < 8; it++) {
            int idx = it * 256 + tid;
            int np = idx & 31, p = idx >> 5;
            float2 v = *(const float2*)&pvb[p * NST + n0 + 2 * np];
            Bt[p * YSTR + np] = f2h2(v.x, v.y);
        }
        __syncthreads();
#pragma unroll
        for (int ks = 0; ks < 4; ks++) {
            unsigned bf[8][2];
#pragma unroll
            for (int nt = 0; nt < 8; nt++) {
                const unsigned* bp = Bt + (nt * 8 + g) * YSTR + ks * 8;
                bf[nt][0] = bp[tig]; bf[nt][1] = bp[tig + 4];
            }
#pragma unroll
            for (int mt = 0; mt < 2; mt++) {
                const unsigned* ap = At + (wid * 32 + mt * 16 + g) * YSTR + ks * 8;
                unsigned a0 = ap[tig], a2 = ap[tig + 4];
                unsigned a1 = ap[8 * YSTR + tig], a3 = ap[8 * YSTR + tig + 4];
#pragma unroll
                for (int nt = 0; nt < 8; nt++)
                    mma_h16(acc[mt][nt][0], acc[mt][nt][1], acc[mt][nt][2], acc[mt][nt][3],
                            a0, a1, a2, a3, bf[nt][0], bf[nt][1]);
            }
        }
        __syncthreads();
    }

    // ---- epilogue: + D*x, gate silu(z) ----
    float dsk = Dsk[h];
#pragma unroll
    for (int mt = 0; mt < 2; mt++) {
#pragma unroll
        for (int nt = 0; nt < 8; nt++) {
            int col = nt * 8 + tig * 2;
#pragma unroll
            for (int rr = 0; rr < 2; rr++) {
                int l = wid * 32 + mt * 16 + g + rr * 8;
                int t = tb + l;
                float2 xv = *(const float2*)&xbc[(long)t * CDIM + h * HD + col];
                float2 zv = *(const float2*)&zx[(long)t * DPROJ + h * HD + col];
                float o0 = (acc[mt][nt][rr * 2 + 0] + xv.x * dsk) * fsilu(zv.x);
                float o1 = (acc[mt][nt][rr * 2 + 1] + xv.y * dsk) * fsilu(zv.y);
                *(float2*)&y[(long)t * DINNER + h * HD + col] = make_float2(o0, o1);
            }
        }
    }
}

// ---------------- RMSNorm ----------------
__global__ void k_rms(float* __restrict__ y, const float* __restrict__ nw)
{
    int t = blockIdx.x;
    float* row = y + (long)t * DINNER;
    float ss = 0.f;
    for (int i = threadIdx.x; i < DINNER; i += 256) { float v = row[i]; ss = fmaf(v, v, ss); }
    __shared__ float red[256];
    red[threadIdx.x] = ss; __syncthreads();
    for (int o = 128; o > 0; o >>= 1) {
        if (threadIdx.x < o) red[threadIdx.x] += red[threadIdx.x + o];
        __syncthreads();
    }
    float sc = rsqrtf(red[0] / (float)DINNER + 1e-5f);
    for (int i = threadIdx.x; i < DINNER; i += 256) row[i] = row[i] * sc * nw[i];
}

// ---------------- launch ----------------
extern "C" void kernel_launch(void* const* d_in, const int* in_sizes, int n_in,
                              void* d_out, int out_size)
{
    const float* u     = (const float*)d_in[0];
    const float* Win   = (const float*)d_in[1];
    const float* convw = (const float*)d_in[2];
    const float* convb = (const float*)d_in[3];
    const float* dtb   = (const float*)d_in[4];
    const float* Alog  = (const float*)d_in[5];
    const float* Dsk   = (const float*)d_in[6];
    const float* nw    = (const float*)d_in[7];
    const float* Wout  = (const float*)d_in[8];
    float* out = (float*)d_out;

    static float *zx = nullptr, *xbc, *dt, *dacs, *cb, *st, *pv, *y;
    if (!zx) {
        cudaGetSymbolAddress((void**)&xbc,  g_xbc);
        cudaGetSymbolAddress((void**)&dt,   g_dtv);
        cudaGetSymbolAddress((void**)&dacs, g_dacs);
        cudaGetSymbolAddress((void**)&cb,   g_cb);
        cudaGetSymbolAddress((void**)&st,   g_st);
        cudaGetSymbolAddress((void**)&pv,   g_pv);
        cudaGetSymbolAddress((void**)&y,    g_y);
        cudaGetSymbolAddress((void**)&zx,   g_zx);
    }

    // 1) in_proj: zx = u @ Win^T   (M=4096, N=8512, K=2048)
    gemm_h16<<<dim3((DPROJ + 127) / 128, TOK / 128, 1), 256>>>(u, Win, zx,
        DMODEL, DMODEL, DMODEL, DPROJ, DPROJ, 0, 0, 0);

    // 2) conv + silu
    k_conv<<<(int)(((long)TOK * CDIM + 255) / 256), 256>>>(zx, convw, convb, xbc);

    // 3) softplus(dt) + dA cumsum (fused)
    k_dacs<<<NCC * NH, CK>>>(zx, dtb, Alog, dt, dacs);

    // 4) CB^T[cc][s][l] = B[s]·C[l]   (batched, M=256,N=256,K=128)
    gemm_h16<<<dim3(CK / 128, CK / 128, NCC), 256>>>(xbc + DINNER, xbc + DINNER + NST, cb,
        NST, CDIM, CDIM, CK, CK, (long)CK * CDIM, (long)CK * CDIM, (long)CK * CK);

    // 5) chunk states (tensor-core)
    k_states_mma<<<NCC * NH, 256>>>(xbc, dt, dacs, st);

    // 6) inter-chunk scan (4x parallelism)
    k_scan<<<2 * NH * 4, 256>>>(st, dacs, pv);

    // 7) Y = Y_diag + Y_off + skip, gated  (tensor-core)
    k_y_mma<<<NCC * NH, 256>>>(xbc, zx, dt, dacs, cb, pv, Dsk, y);

    // 8) RMSNorm
    k_rms<<<TOK, 256>>>(y, nw);

    // 9) out_proj: out = y @ Wout^T  (M=4096, N=2048, K=4096)
    gemm_h16<<<dim3(DMODEL / 128, TOK / 128, 1), 256>>>(y, Wout, out,
        DINNER, DINNER, DINNER, DMODEL, DMODEL, 0, 0, 0);
}

// round 12
// speedup vs baseline: 2.0003x; 1.0003x over previous
#include <cuda_runtime.h>
#include <cuda_fp16.h>

// ---------------- problem constants ----------------
#define TOK    4096        // BATCH*SEQLEN
#define DMODEL 2048
#define DINNER 4096
#define NH     64
#define HD     64
#define NST    128
#define CDIM   4352        // DINNER + 2*NST
#define DPROJ  8512        // 2*DINNER + 2*NST + NH
#define SEQ    2048
#define CK     256         // chunk length
#define NCC    16          // BATCH * (SEQ/CK) total chunks

// ---------------- scratch (device globals; no allocation) ----------------
__device__ __align__(16) float g_zx  [(size_t)TOK*DPROJ];
__device__ __align__(16) float g_xbc [(size_t)TOK*CDIM];
__device__ __align__(16) float g_dtv [(size_t)TOK*NH];
__device__ __align__(16) float g_dacs[(size_t)NCC*NH*CK];
__device__ __align__(16) float g_cb  [(size_t)NCC*CK*CK];
__device__ __align__(16) float g_st  [(size_t)NCC*NH*HD*NST];
__device__ __align__(16) float g_pv  [(size_t)NCC*NH*HD*NST];
__device__ __align__(16) float g_y   [(size_t)TOK*DINNER];

// ---------------- helpers ----------------
__device__ __forceinline__ unsigned f2h2(float lo, float hi) {
    __half2 h = __floats2half2_rn(lo, hi);
    return *(unsigned*)&h;
}
__device__ __forceinline__ void mma_h16(float& c0, float& c1, float& c2, float& c3,
                                        unsigned a0, unsigned a1, unsigned a2, unsigned a3,
                                        unsigned b0, unsigned b1) {
    asm volatile("mma.sync.aligned.m16n8k16.row.col.f32.f16.f16.f32 "
                 "{%0,%1,%2,%3}, {%4,%5,%6,%7}, {%8,%9}, {%0,%1,%2,%3};"
                 : "+f"(c0), "+f"(c1), "+f"(c2), "+f"(c3)
                 : "r"(a0), "r"(a1), "r"(a2), "r"(a3), "r"(b0), "r"(b1));
}
__device__ __forceinline__ float fsilu(float v) {
    return v * __fdividef(1.f, 1.f + __expf(-v));
}

// ---------------- fp16 tensor-core GEMM: C[m,n] = sum_k A[m,k]*B[n,k] ----------------
// BM=128, BN=128, BK=16, 256 threads (8 warps), warp tile 32x64, DOUBLE-BUFFERED.
#define HSTR 12
__global__ __launch_bounds__(256) void gemm_h16(
    const float* __restrict__ A, const float* __restrict__ B, float* __restrict__ C,
    int K, int lda, int ldb, int ldc, int N, long aB, long bB, long cB)
{
    const float* Ab = A + (long)blockIdx.z * aB;
    const float* Bb = B + (long)blockIdx.z * bB;
    float*       Cb = C + (long)blockIdx.z * cB;

    __shared__ unsigned As[2][128 * HSTR];
    __shared__ unsigned Bs[2][128 * HSTR];

    int tid  = threadIdx.x;
    int wid  = tid >> 5, lane = tid & 31;
    int g    = lane >> 2, tig = lane & 3;
    int wm   = wid & 3, wn = wid >> 2;          // 4 m-warps x 2 n-warps; warp tile 32x64
    int m0   = blockIdx.y * 128, n0 = blockIdx.x * 128;

    int aRow = tid >> 1, aColF = (tid & 1) * 8;
    const float* aptr = Ab + (long)(m0 + aRow) * lda + aColF;
    int bR = n0 + aRow; if (bR >= N) bR = N - 1;     // clamp ragged rows
    const float* bptr = Bb + (long)bR * ldb + aColF;

    float acc[2][8][4];
#pragma unroll
    for (int i = 0; i < 2; i++)
#pragma unroll
        for (int j = 0; j < 8; j++)
#pragma unroll
            for (int r = 0; r < 4; r++) acc[i][j][r] = 0.f;

    float4 ra0 = *(const float4*)(aptr);
    float4 ra1 = *(const float4*)(aptr + 4);
    float4 rb0 = *(const float4*)(bptr);
    float4 rb1 = *(const float4*)(bptr + 4);
    {
        unsigned* as = As[0] + aRow * HSTR + (tid & 1) * 4;
        as[0] = f2h2(ra0.x, ra0.y); as[1] = f2h2(ra0.z, ra0.w);
        as[2] = f2h2(ra1.x, ra1.y); as[3] = f2h2(ra1.z, ra1.w);
        unsigned* bs = Bs[0] + aRow * HSTR + (tid & 1) * 4;
        bs[0] = f2h2(rb0.x, rb0.y); bs[1] = f2h2(rb0.z, rb0.w);
        bs[2] = f2h2(rb1.x, rb1.y); bs[3] = f2h2(rb1.z, rb1.w);
    }
    __syncthreads();

    int cur = 0;
    for (int k0 = 0; k0 < K; k0 += 16) {
        bool nxt = (k0 + 16) < K;
        if (nxt) {
            ra0 = *(const float4*)(aptr + k0 + 16);
            ra1 = *(const float4*)(aptr + k0 + 20);
            rb0 = *(const float4*)(bptr + k0 + 16);
            rb1 = *(const float4*)(bptr + k0 + 20);
        }

        const unsigned* Ac = As[cur];
        const unsigned* Bc = Bs[cur];
        unsigned bf[8][2];
#pragma unroll
        for (int nt = 0; nt < 8; nt++) {
            const unsigned* bp = Bc + (wn * 64 + nt * 8 + g) * HSTR;
            bf[nt][0] = bp[tig]; bf[nt][1] = bp[tig + 4];
        }
#pragma unroll
        for (int mt = 0; mt < 2; mt++) {
            const unsigned* ap0 = Ac + (wm * 32 + mt * 16 + g) * HSTR;
            const unsigned* ap1 = ap0 + 8 * HSTR;
            unsigned a0 = ap0[tig], a2 = ap0[tig + 4];
            unsigned a1 = ap1[tig], a3 = ap1[tig + 4];
#pragma unroll
            for (int nt = 0; nt < 8; nt++)
                mma_h16(acc[mt][nt][0], acc[mt][nt][1], acc[mt][nt][2], acc[mt][nt][3],
                        a0, a1, a2, a3, bf[nt][0], bf[nt][1]);
        }

        if (nxt) {
            int s = cur ^ 1;
            unsigned* as = As[s] + aRow * HSTR + (tid & 1) * 4;
            as[0] = f2h2(ra0.x, ra0.y); as[1] = f2h2(ra0.z, ra0.w);
            as[2] = f2h2(ra1.x, ra1.y); as[3] = f2h2(ra1.z, ra1.w);
            unsigned* bs = Bs[s] + aRow * HSTR + (tid & 1) * 4;
            bs[0] = f2h2(rb0.x, rb0.y); bs[1] = f2h2(rb0.z, rb0.w);
            bs[2] = f2h2(rb1.x, rb1.y); bs[3] = f2h2(rb1.z, rb1.w);
        }
        __syncthreads();
        cur ^= 1;
    }

#pragma unroll
    for (int mt = 0; mt < 2; mt++) {
#pragma unroll
        for (int nt = 0; nt < 8; nt++) {
            int row = m0 + wm * 32 + mt * 16 + g;
            int col = n0 + wn * 64 + nt * 8 + tig * 2;
            if (col < N) {
                *(float2*)(Cb + (long)row * ldc + col)       = make_float2(acc[mt][nt][0], acc[mt][nt][1]);
                *(float2*)(Cb + (long)(row + 8) * ldc + col) = make_float2(acc[mt][nt][2], acc[mt][nt][3]);
            }
        }
    }
}

// ---------------- causal conv1d(width 4) + bias + silu ----------------
__global__ void k_conv(const float* __restrict__ zx, const float* __restrict__ w,
                       const float* __restrict__ bias, float* __restrict__ xbc)
{
    long i = (long)blockIdx.x * 256 + threadIdx.x;
    if (i >= (long)TOK * CDIM) return;
    int t = (int)(i / CDIM), c = (int)(i % CDIM);
    int l = t & (SEQ - 1);
    float acc = bias[c];
#pragma unroll
    for (int k = 0; k < 4; k++) {
        int lt = l - 3 + k;
        if (lt >= 0)
            acc = fmaf(w[c * 4 + k], zx[(long)(t - 3 + k) * DPROJ + DINNER + c], acc);
    }
    xbc[i] = fsilu(acc);
}

// ------- per-(chunk,head) softplus(dt) + cumsum of dt*A (fused; writes dt too) -------
__global__ void k_dacs(const float* __restrict__ zx, const float* __restrict__ dt_bias,
                       const float* __restrict__ Alog, float* __restrict__ dtv,
                       float* __restrict__ dacs)
{
    int cc = blockIdx.x >> 6, h = blockIdx.x & 63;
    int s = threadIdx.x;
    int t = cc * CK + s;
    float raw = zx[(long)t * DPROJ + (DINNER + CDIM) + h] + dt_bias[h];
    float d = (raw > 20.f) ? raw : log1pf(expf(raw));
    dtv[t * NH + h] = d;
    float a = -expf(Alog[h]);
    float v = d * a;
    __shared__ float sm[CK];
    sm[s] = v; __syncthreads();
    for (int off = 1; off < CK; off <<= 1) {
        float tv = (s >= off) ? sm[s - off] : 0.f;
        __syncthreads();
        sm[s] += tv;
        __syncthreads();
    }
    dacs[(blockIdx.x << 8) + s] = sm[s];
}

// ======= chunk states via fp16 MMA =======
#define YSTR 36
__global__ __launch_bounds__(256) void k_states_mma(const float* __restrict__ xbc,
        const float* __restrict__ dt, const float* __restrict__ dacs, float* __restrict__ st)
{
    const int cc = blockIdx.x >> 6, h = blockIdx.x & 63;
    const int tb = cc * CK;
    const int tid = threadIdx.x, wid = tid >> 5, lane = tid & 31;
    const int g = lane >> 2, tig = lane & 3;
    const int wm = wid & 3, wn = wid >> 2;

    __shared__ unsigned At[64 * YSTR];
    __shared__ unsigned Bt[128 * YSTR];
    __shared__ float sdecay[CK];

    const float* dA = dacs + (blockIdx.x << 8);
    {
        float dlast = dA[CK - 1];
        sdecay[tid] = __expf(dlast - dA[tid]);
    }
    __syncthreads();

    float acc[8][4];
#pragma unroll
    for (int j = 0; j < 8; j++)
#pragma unroll
        for (int r = 0; r < 4; r++) acc[j][r] = 0.f;

    for (int s0 = 0; s0 < CK; s0 += 64) {
#pragma unroll
        for (int it = 0; it < 8; it++) {
            int idx = it * 256 + tid;
            int p = idx & 63, sq = idx >> 6;
            int t0 = tb + s0 + 2 * sq;
            float v0 = xbc[(long)t0 * CDIM + h * HD + p] * dt[t0 * NH + h];
            float v1 = xbc[(long)(t0 + 1) * CDIM + h * HD + p] * dt[(t0 + 1) * NH + h];
            At[p * YSTR + sq] = f2h2(v0, v1);
        }
#pragma unroll
        for (int it = 0; it < 16; it++) {
            int idx = it * 256 + tid;
            int n = idx & 127, sq = idx >> 7;
            int t0 = tb + s0 + 2 * sq;
            float v0 = xbc[(long)t0 * CDIM + DINNER + n] * sdecay[s0 + 2 * sq];
            float v1 = xbc[(long)(t0 + 1) * CDIM + DINNER + n] * sdecay[s0 + 2 * sq + 1];
            Bt[n * YSTR + sq] = f2h2(v0, v1);
        }
        __syncthreads();
#pragma unroll
        for (int ks = 0; ks < 4; ks++) {
            unsigned bf[8][2];
#pragma unroll
            for (int nt = 0; nt < 8; nt++) {
                const unsigned* bp = Bt + (wn * 64 + nt * 8 + g) * YSTR + ks * 8;
                bf[nt][0] = bp[tig]; bf[nt][1] = bp[tig + 4];
            }
            const unsigned* ap = At + (wm * 16 + g) * YSTR + ks * 8;
            unsigned a0 = ap[tig], a2 = ap[tig + 4];
            unsigned a1 = ap[8 * YSTR + tig], a3 = ap[8 * YSTR + tig + 4];
#pragma unroll
            for (int nt = 0; nt < 8; nt++)
                mma_h16(acc[nt][0], acc[nt][1], acc[nt][2], acc[nt][3],
                        a0, a1, a2, a3, bf[nt][0], bf[nt][1]);
        }
        __syncthreads();
    }

    float* ob = st + ((long)blockIdx.x << 13);
#pragma unroll
    for (int nt = 0; nt < 8; nt++) {
        int col = wn * 64 + nt * 8 + tig * 2;
        int row = wm * 16 + g;
        *(float2*)(ob + row * NST + col)       = make_float2(acc[nt][0], acc[nt][1]);
        *(float2*)(ob + (row + 8) * NST + col) = make_float2(acc[nt][2], acc[nt][3]);
    }
}

// ---------------- sequential chunk scan (4 quarter-blocks per (b,h)) ----------------
__global__ void k_scan(const float* __restrict__ st, const float* __restrict__ dacs,
                       float* __restrict__ pv)
{
    int bh = blockIdx.x >> 2, q = blockIdx.x & 3;
    int b = bh >> 6, h = bh & 63;
    int tid = threadIdx.x;
    int off = q * 2048 + tid;
    float carry[8];
#pragma unroll
    for (int j = 0; j < 8; j++) carry[j] = 0.f;
    for (int c = 0; c < 8; c++) {
        int cc = b * 8 + c;
        long base = (((long)(cc * 64 + h)) << 13) + off;
        float dec = __expf(dacs[((cc * 64 + h) << 8) + CK - 1]);
#pragma unroll
        for (int j = 0; j < 8; j++) {
            long e = base + j * 256;
            pv[e] = carry[j];
            carry[j] = carry[j] * dec + st[e];
        }
    }
}

// ======= k_y via fp16 MMA: Y = (W@xdt) + (C*el)@prev^T, + D*x, gated =======
// W-build uses overflow-safe rank-1 factorization per 64-wide s-tile:
//   exp(dal-das) = exp(dal-da[s0]) * exp(da[s0]-das)  when tile range R <= 60
// (fallback to per-element exp for pathological tiles). sel[] is time-shared:
// phase 1 it holds the tile-relative s factors; phase 2 it holds exp(dal).
__global__ __launch_bounds__(256) void k_y_mma(const float* __restrict__ xbc,
        const float* __restrict__ zx, const float* __restrict__ dt,
        const float* __restrict__ dacs, const float* __restrict__ cb,
        const float* __restrict__ pv, const float* __restrict__ Dsk,
        float* __restrict__ y)
{
    const int cc = blockIdx.x >> 6, h = blockIdx.x & 63;
    const int tb = cc * CK;
    const int tid = threadIdx.x, wid = tid >> 5, lane = tid & 31;
    const int g = lane >> 2, tig = lane & 3;

    __shared__ unsigned At[256 * YSTR];
    __shared__ unsigned Bt[64 * YSTR];
    __shared__ float sda[256];
    __shared__ float sel[256];

    sda[tid] = dacs[(blockIdx.x << 8) + tid];
    __syncthreads();
    // phase-1 role of sel: tile-relative decay factor exp(da[tile_start] - da[s]) >= 1
    sel[tid] = __expf(sda[(tid >> 6) << 6] - sda[tid]);
    __syncthreads();

    float acc[2][8][4];
#pragma unroll
    for (int i = 0; i < 2; i++)
#pragma unroll
        for (int j = 0; j < 8; j++)
#pragma unroll
            for (int r = 0; r < 4; r++) acc[i][j][r] = 0.f;

    const float* cbb = cb + ((long)cc << 16);

    // ---- phase 1: Y_diag, 4 s-tiles of 64 ----
    for (int st4 = 0; st4 < 4; st4++) {
        int s0 = st4 * 64;
        float Rt = sda[s0] - sda[s0 + 63];    // tile decay range (>= 0)
        bool fast = (Rt <= 60.f);
        {
            int l = tid;
            unsigned* arow = At + l * YSTR;
            if (l < s0) {
#pragma unroll 8
                for (int it = 0; it < 32; it++) arow[it] = 0u;
            } else {
                float dal = sda[l];
                if (fast) {
                    float f1 = __expf(dal - sda[s0]);   // <= 1 for l >= s0
#pragma unroll 4
                    for (int it = 0; it < 32; it++) {
                        int s = s0 + 2 * it;
                        float w0 = 0.f, w1 = 0.f;
                        if (s <= l) {
                            w0 = f1 * sel[s] * cbb[(s << 8) + l];
                            if (s + 1 <= l)
                                w1 = f1 * sel[s + 1] * cbb[((s + 1) << 8) + l];
                        }
                        arow[it] = f2h2(w0, w1);
                    }
                } else {
#pragma unroll 4
                    for (int it = 0; it < 32; it++) {
                        int s = s0 + 2 * it;
                        float w0 = 0.f, w1 = 0.f;
                        if (s <= l) {
                            w0 = __expf(dal - sda[s]) * cbb[(s << 8) + l];
                            if (s + 1 <= l)
                                w1 = __expf(dal - sda[s + 1]) * cbb[((s + 1) << 8) + l];
                        }
                        arow[it] = f2h2(w0, w1);
                    }
                }
            }
        }
#pragma unroll
        for (int it = 0; it < 8; it++) {
            int idx = it * 256 + tid;
            int p = idx & 63, sq = idx >> 6;
            int t0 = tb + s0 + 2 * sq;
            float v0 = xbc[(long)t0 * CDIM + h * HD + p] * dt[t0 * NH + h];
            float v1 = xbc[(long)(t0 + 1) * CDIM + h * HD + p] * dt[(t0 + 1) * NH + h];
            Bt[p * YSTR + sq] = f2h2(v0, v1);
        }
        __syncthreads();
        if (wid * 32 + 31 >= s0) {
#pragma unroll
            for (int ks = 0; ks < 4; ks++) {
                unsigned bf[8][2];
#pragma unroll
                for (int nt = 0; nt < 8; nt++) {
                    const unsigned* bp = Bt + (nt * 8 + g) * YSTR + ks * 8;
                    bf[nt][0] = bp[tig]; bf[nt][1] = bp[tig + 4];
                }
#pragma unroll
                for (int mt = 0; mt < 2; mt++) {
                    const unsigned* ap = At + (wid * 32 + mt * 16 + g) * YSTR + ks * 8;
                    unsigned a0 = ap[tig], a2 = ap[tig + 4];
                    unsigned a1 = ap[8 * YSTR + tig], a3 = ap[8 * YSTR + tig + 4];
#pragma unroll
                    for (int nt = 0; nt < 8; nt++)
                        mma_h16(acc[mt][nt][0], acc[mt][nt][1], acc[mt][nt][2], acc[mt][nt][3],
                                a0, a1, a2, a3, bf[nt][0], bf[nt][1]);
                }
            }
        }
        __syncthreads();
    }

    // phase-2 role of sel: exp(dA[l])
    sel[tid] = __expf(sda[tid]);
    __syncthreads();

    // ---- phase 2: Y_off, 2 n-subtiles of 64 ----
    const float* pvb = pv + ((long)blockIdx.x << 13);
    for (int ns = 0; ns < 2; ns++) {
        int n0 = ns * 64;
#pragma unroll
        for (int it = 0; it < 32; it++) {
            int idx = it * 256 + tid;
            int np = idx & 31, l = idx >> 5;
            float el = sel[l];
            float2 v = *(const float2*)&xbc[(long)(tb + l) * CDIM + DINNER + NST + n0 + 2 * np];
            At[l * YSTR + np] = f2h2(v.x * el, v.y * el);
        }
#pragma unroll
        for (int it = 0; it < 8; it++) {
            int idx = it * 256 + tid;
            int np = idx & 31, p = idx >> 5;
            float2 v = *(const float2*)&pvb[p * NST + n0 + 2 * np];
            Bt[p * YSTR + np] = f2h2(v.x, v.y);
        }
        __syncthreads();
#pragma unroll
        for (int ks = 0; ks < 4; ks++) {
            unsigned bf[8][2];
#pragma unroll
            for (int nt = 0; nt < 8; nt++) {
                const unsigned* bp = Bt + (nt * 8 + g) * YSTR + ks * 8;
                bf[nt][0] = bp[tig]; bf[nt][1] = bp[tig + 4];
            }
#pragma unroll
            for (int mt = 0; mt < 2; mt++) {
                const unsigned* ap = At + (wid * 32 + mt * 16 + g) * YSTR + ks * 8;
                unsigned a0 = ap[tig], a2 = ap[tig + 4];
                unsigned a1 = ap[8 * YSTR + tig], a3 = ap[8 * YSTR + tig + 4];
#pragma unroll
                for (int nt = 0; nt < 8; nt++)
                    mma_h16(acc[mt][nt][0], acc[mt][nt][1], acc[mt][nt][2], acc[mt][nt][3],
                            a0, a1, a2, a3, bf[nt][0], bf[nt][1]);
            }
        }
        __syncthreads();
    }

    // ---- epilogue: + D*x, gate silu(z) ----
    float dsk = Dsk[h];
#pragma unroll
    for (int mt = 0; mt < 2; mt++) {
#pragma unroll
        for (int nt = 0; nt < 8; nt++) {
            int col = nt * 8 + tig * 2;
#pragma unroll
            for (int rr = 0; rr < 2; rr++) {
                int l = wid * 32 + mt * 16 + g + rr * 8;
                int t = tb + l;
                float2 xv = *(const float2*)&xbc[(long)t * CDIM + h * HD + col];
                float2 zv = *(const float2*)&zx[(long)t * DPROJ + h * HD + col];
                float o0 = (acc[mt][nt][rr * 2 + 0] + xv.x * dsk) * fsilu(zv.x);
                float o1 = (acc[mt][nt][rr * 2 + 1] + xv.y * dsk) * fsilu(zv.y);
                *(float2*)&y[(long)t * DINNER + h * HD + col] = make_float2(o0, o1);
            }
        }
    }
}

// ---------------- RMSNorm ----------------
__global__ void k_rms(float* __restrict__ y, const float* __restrict__ nw)
{
    int t = blockIdx.x;
    float* row = y + (long)t * DINNER;
    float ss = 0.f;
    for (int i = threadIdx.x; i < DINNER; i += 256) { float v = row[i]; ss = fmaf(v, v, ss); }
    __shared__ float red[256];
    red[threadIdx.x] = ss; __syncthreads();
    for (int o = 128; o > 0; o >>= 1) {
        if (threadIdx.x < o) red[threadIdx.x] += red[threadIdx.x + o];
        __syncthreads();
    }
    float sc = rsqrtf(red[0] / (float)DINNER + 1e-5f);
    for (int i = threadIdx.x; i < DINNER; i += 256) row[i] = row[i] * sc * nw[i];
}

// ---------------- launch ----------------
extern "C" void kernel_launch(void* const* d_in, const int* in_sizes, int n_in,
                              void* d_out, int out_size)
{
    const float* u     = (const float*)d_in[0];
    const float* Win   = (const float*)d_in[1];
    const float* convw = (const float*)d_in[2];
    const float* convb = (const float*)d_in[3];
    const float* dtb   = (const float*)d_in[4];
    const float* Alog  = (const float*)d_in[5];
    const float* Dsk   = (const float*)d_in[6];
    const float* nw    = (const float*)d_in[7];
    const float* Wout  = (const float*)d_in[8];
    float* out = (float*)d_out;

    static float *zx = nullptr, *xbc, *dt, *dacs, *cb, *st, *pv, *y;
    if (!zx) {
        cudaGetSymbolAddress((void**)&xbc,  g_xbc);
        cudaGetSymbolAddress((void**)&dt,   g_dtv);
        cudaGetSymbolAddress((void**)&dacs, g_dacs);
        cudaGetSymbolAddress((void**)&cb,   g_cb);
        cudaGetSymbolAddress((void**)&st,   g_st);
        cudaGetSymbolAddress((void**)&pv,   g_pv);
        cudaGetSymbolAddress((void**)&y,    g_y);
        cudaGetSymbolAddress((void**)&zx,   g_zx);
    }

    // 1) in_proj: zx = u @ Win^T   (M=4096, N=8512, K=2048)
    gemm_h16<<<dim3((DPROJ + 127) / 128, TOK / 128, 1), 256>>>(u, Win, zx,
        DMODEL, DMODEL, DMODEL, DPROJ, DPROJ, 0, 0, 0);

    // 2) conv + silu
    k_conv<<<(int)(((long)TOK * CDIM + 255) / 256), 256>>>(zx, convw, convb, xbc);

    // 3) softplus(dt) + dA cumsum (fused)
    k_dacs<<<NCC * NH, CK>>>(zx, dtb, Alog, dt, dacs);

    // 4) CB^T[cc][s][l] = B[s]·C[l]   (batched, M=256,N=256,K=128)
    gemm_h16<<<dim3(CK / 128, CK / 128, NCC), 256>>>(xbc + DINNER, xbc + DINNER + NST, cb,
        NST, CDIM, CDIM, CK, CK, (long)CK * CDIM, (long)CK * CDIM, (long)CK * CK);

    // 5) chunk states (tensor-core)
    k_states_mma<<<NCC * NH, 256>>>(xbc, dt, dacs, st);

    // 6) inter-chunk scan (4x parallelism)
    k_scan<<<2 * NH * 4, 256>>>(st, dacs, pv);

    // 7) Y = Y_diag + Y_off + skip, gated  (tensor-core)
    k_y_mma<<<NCC * NH, 256>>>(xbc, zx, dt, dacs, cb, pv, Dsk, y);

    // 8) RMSNorm
    k_rms<<<TOK, 256>>>(y, nw);

    // 9) out_proj: out = y @ Wout^T  (M=4096, N=2048, K=4096)
    gemm_h16<<<dim3(DMODEL / 128, TOK / 128, 1), 256>>>(y, Wout, out,
        DINNER, DINNER, DINNER, DMODEL, DMODEL, 0, 0, 0);
}

// round 13
// speedup vs baseline: 2.0075x; 1.0036x over previous
#include <cuda_runtime.h>
#include <cuda_fp16.h>

// ---------------- problem constants ----------------
#define TOK    4096        // BATCH*SEQLEN
#define DMODEL 2048
#define DINNER 4096
#define NH     64
#define HD     64
#define NST    128
#define CDIM   4352        // DINNER + 2*NST
#define DPROJ  8512        // 2*DINNER + 2*NST + NH
#define SEQ    2048
#define CK     256         // chunk length
#define NCC    16          // BATCH * (SEQ/CK) total chunks

// ---------------- scratch (device globals; no allocation) ----------------
__device__ __align__(16) float g_zx  [(size_t)TOK*DPROJ];
__device__ __align__(16) float g_xbc [(size_t)TOK*CDIM];
__device__ __align__(16) float g_dtv [(size_t)TOK*NH];
__device__ __align__(16) float g_dacs[(size_t)NCC*NH*CK];
__device__ __align__(16) float g_cb  [(size_t)NCC*CK*CK];
__device__ __align__(16) float g_st  [(size_t)NCC*NH*HD*NST];
__device__ __align__(16) float g_pv  [(size_t)NCC*NH*HD*NST];
__device__ __align__(16) float g_y   [(size_t)TOK*DINNER];

// ---------------- helpers ----------------
__device__ __forceinline__ unsigned f2h2(float lo, float hi) {
    __half2 h = __floats2half2_rn(lo, hi);
    return *(unsigned*)&h;
}
__device__ __forceinline__ void mma_h16(float& c0, float& c1, float& c2, float& c3,
                                        unsigned a0, unsigned a1, unsigned a2, unsigned a3,
                                        unsigned b0, unsigned b1) {
    asm volatile("mma.sync.aligned.m16n8k16.row.col.f32.f16.f16.f32 "
                 "{%0,%1,%2,%3}, {%4,%5,%6,%7}, {%8,%9}, {%0,%1,%2,%3};"
                 : "+f"(c0), "+f"(c1), "+f"(c2), "+f"(c3)
                 : "r"(a0), "r"(a1), "r"(a2), "r"(a3), "r"(b0), "r"(b1));
}
__device__ __forceinline__ float fsilu(float v) {
    return v * __fdividef(1.f, 1.f + __expf(-v));
}

// ---------------- fp16 tensor-core GEMM: C[m,n] = sum_k A[m,k]*B[n,k] ----------------
// BM=128, BN=128, BK=16, 256 threads (8 warps), warp tile 32x64, DOUBLE-BUFFERED.
#define HSTR 12
__global__ __launch_bounds__(256) void gemm_h16(
    const float* __restrict__ A, const float* __restrict__ B, float* __restrict__ C,
    int K, int lda, int ldb, int ldc, int N, long aB, long bB, long cB)
{
    const float* Ab = A + (long)blockIdx.z * aB;
    const float* Bb = B + (long)blockIdx.z * bB;
    float*       Cb = C + (long)blockIdx.z * cB;

    __shared__ unsigned As[2][128 * HSTR];
    __shared__ unsigned Bs[2][128 * HSTR];

    int tid  = threadIdx.x;
    int wid  = tid >> 5, lane = tid & 31;
    int g    = lane >> 2, tig = lane & 3;
    int wm   = wid & 3, wn = wid >> 2;          // 4 m-warps x 2 n-warps; warp tile 32x64
    int m0   = blockIdx.y * 128, n0 = blockIdx.x * 128;

    int aRow = tid >> 1, aColF = (tid & 1) * 8;
    const float* aptr = Ab + (long)(m0 + aRow) * lda + aColF;
    int bR = n0 + aRow; if (bR >= N) bR = N - 1;     // clamp ragged rows
    const float* bptr = Bb + (long)bR * ldb + aColF;

    float acc[2][8][4];
#pragma unroll
    for (int i = 0; i < 2; i++)
#pragma unroll
        for (int j = 0; j < 8; j++)
#pragma unroll
            for (int r = 0; r < 4; r++) acc[i][j][r] = 0.f;

    float4 ra0 = *(const float4*)(aptr);
    float4 ra1 = *(const float4*)(aptr + 4);
    float4 rb0 = *(const float4*)(bptr);
    float4 rb1 = *(const float4*)(bptr + 4);
    {
        unsigned* as = As[0] + aRow * HSTR + (tid & 1) * 4;
        as[0] = f2h2(ra0.x, ra0.y); as[1] = f2h2(ra0.z, ra0.w);
        as[2] = f2h2(ra1.x, ra1.y); as[3] = f2h2(ra1.z, ra1.w);
        unsigned* bs = Bs[0] + aRow * HSTR + (tid & 1) * 4;
        bs[0] = f2h2(rb0.x, rb0.y); bs[1] = f2h2(rb0.z, rb0.w);
        bs[2] = f2h2(rb1.x, rb1.y); bs[3] = f2h2(rb1.z, rb1.w);
    }
    __syncthreads();

    int cur = 0;
    for (int k0 = 0; k0 < K; k0 += 16) {
        bool nxt = (k0 + 16) < K;
        if (nxt) {
            ra0 = *(const float4*)(aptr + k0 + 16);
            ra1 = *(const float4*)(aptr + k0 + 20);
            rb0 = *(const float4*)(bptr + k0 + 16);
            rb1 = *(const float4*)(bptr + k0 + 20);
        }

        const unsigned* Ac = As[cur];
        const unsigned* Bc = Bs[cur];
        unsigned bf[8][2];
#pragma unroll
        for (int nt = 0; nt < 8; nt++) {
            const unsigned* bp = Bc + (wn * 64 + nt * 8 + g) * HSTR;
            bf[nt][0] = bp[tig]; bf[nt][1] = bp[tig + 4];
        }
#pragma unroll
        for (int mt = 0; mt < 2; mt++) {
            const unsigned* ap0 = Ac + (wm * 32 + mt * 16 + g) * HSTR;
            const unsigned* ap1 = ap0 + 8 * HSTR;
            unsigned a0 = ap0[tig], a2 = ap0[tig + 4];
            unsigned a1 = ap1[tig], a3 = ap1[tig + 4];
#pragma unroll
            for (int nt = 0; nt < 8; nt++)
                mma_h16(acc[mt][nt][0], acc[mt][nt][1], acc[mt][nt][2], acc[mt][nt][3],
                        a0, a1, a2, a3, bf[nt][0], bf[nt][1]);
        }

        if (nxt) {
            int s = cur ^ 1;
            unsigned* as = As[s] + aRow * HSTR + (tid & 1) * 4;
            as[0] = f2h2(ra0.x, ra0.y); as[1] = f2h2(ra0.z, ra0.w);
            as[2] = f2h2(ra1.x, ra1.y); as[3] = f2h2(ra1.z, ra1.w);
            unsigned* bs = Bs[s] + aRow * HSTR + (tid & 1) * 4;
            bs[0] = f2h2(rb0.x, rb0.y); bs[1] = f2h2(rb0.z, rb0.w);
            bs[2] = f2h2(rb1.x, rb1.y); bs[3] = f2h2(rb1.z, rb1.w);
        }
        __syncthreads();
        cur ^= 1;
    }

#pragma unroll
    for (int mt = 0; mt < 2; mt++) {
#pragma unroll
        for (int nt = 0; nt < 8; nt++) {
            int row = m0 + wm * 32 + mt * 16 + g;
            int col = n0 + wn * 64 + nt * 8 + tig * 2;
            if (col < N) {
                *(float2*)(Cb + (long)row * ldc + col)       = make_float2(acc[mt][nt][0], acc[mt][nt][1]);
                *(float2*)(Cb + (long)(row + 8) * ldc + col) = make_float2(acc[mt][nt][2], acc[mt][nt][3]);
            }
        }
    }
}

// ------- causal conv1d(width 4) + bias + silu, 4 channels per thread -------
#define C4 (CDIM / 4)   // 1088
__global__ void k_conv(const float* __restrict__ zx, const float* __restrict__ w,
                       const float* __restrict__ bias, float* __restrict__ xbc)
{
    int i = blockIdx.x * 256 + threadIdx.x;
    if (i >= TOK * C4) return;
    int t = i / C4, c4 = i - t * C4;
    int c = c4 * 4;
    int l = t & (SEQ - 1);

    float4 acc = *(const float4*)&bias[c];
    float4 w0 = *(const float4*)&w[(c + 0) * 4];   // taps for channel c+0
    float4 w1 = *(const float4*)&w[(c + 1) * 4];
    float4 w2 = *(const float4*)&w[(c + 2) * 4];
    float4 w3 = *(const float4*)&w[(c + 3) * 4];
    const float* base = zx + (long)t * DPROJ + DINNER + c;

#pragma unroll
    for (int k = 0; k < 4; k++) {
        int lt = l - 3 + k;
        if (lt >= 0) {
            float4 xv = *(const float4*)(base + (long)(k - 3) * DPROJ);
            float a0 = (k == 0) ? w0.x : (k == 1) ? w0.y : (k == 2) ? w0.z : w0.w;
            float a1 = (k == 0) ? w1.x : (k == 1) ? w1.y : (k == 2) ? w1.z : w1.w;
            float a2 = (k == 0) ? w2.x : (k == 1) ? w2.y : (k == 2) ? w2.z : w2.w;
            float a3 = (k == 0) ? w3.x : (k == 1) ? w3.y : (k == 2) ? w3.z : w3.w;
            acc.x = fmaf(a0, xv.x, acc.x);
            acc.y = fmaf(a1, xv.y, acc.y);
            acc.z = fmaf(a2, xv.z, acc.z);
            acc.w = fmaf(a3, xv.w, acc.w);
        }
    }
    float4 o;
    o.x = fsilu(acc.x); o.y = fsilu(acc.y); o.z = fsilu(acc.z); o.w = fsilu(acc.w);
    *(float4*)&xbc[(long)t * CDIM + c] = o;
}

// ------- per-(chunk,head) softplus(dt) + cumsum of dt*A (fused; writes dt too) -------
__global__ void k_dacs(const float* __restrict__ zx, const float* __restrict__ dt_bias,
                       const float* __restrict__ Alog, float* __restrict__ dtv,
                       float* __restrict__ dacs)
{
    int cc = blockIdx.x >> 6, h = blockIdx.x & 63;
    int s = threadIdx.x;
    int t = cc * CK + s;
    float raw = zx[(long)t * DPROJ + (DINNER + CDIM) + h] + dt_bias[h];
    float d = (raw > 20.f) ? raw : log1pf(expf(raw));
    dtv[t * NH + h] = d;
    float a = -expf(Alog[h]);
    float v = d * a;
    __shared__ float sm[CK];
    sm[s] = v; __syncthreads();
    for (int off = 1; off < CK; off <<= 1) {
        float tv = (s >= off) ? sm[s - off] : 0.f;
        __syncthreads();
        sm[s] += tv;
        __syncthreads();
    }
    dacs[(blockIdx.x << 8) + s] = sm[s];
}

// ======= chunk states via fp16 MMA =======
#define YSTR 36
__global__ __launch_bounds__(256) void k_states_mma(const float* __restrict__ xbc,
        const float* __restrict__ dt, const float* __restrict__ dacs, float* __restrict__ st)
{
    const int cc = blockIdx.x >> 6, h = blockIdx.x & 63;
    const int tb = cc * CK;
    const int tid = threadIdx.x, wid = tid >> 5, lane = tid & 31;
    const int g = lane >> 2, tig = lane & 3;
    const int wm = wid & 3, wn = wid >> 2;

    __shared__ unsigned At[64 * YSTR];
    __shared__ unsigned Bt[128 * YSTR];
    __shared__ float sdecay[CK];

    const float* dA = dacs + (blockIdx.x << 8);
    {
        float dlast = dA[CK - 1];
        sdecay[tid] = __expf(dlast - dA[tid]);
    }
    __syncthreads();

    float acc[8][4];
#pragma unroll
    for (int j = 0; j < 8; j++)
#pragma unroll
        for (int r = 0; r < 4; r++) acc[j][r] = 0.f;

    for (int s0 = 0; s0 < CK; s0 += 64) {
#pragma unroll
        for (int it = 0; it < 8; it++) {
            int idx = it * 256 + tid;
            int p = idx & 63, sq = idx >> 6;
            int t0 = tb + s0 + 2 * sq;
            float v0 = xbc[(long)t0 * CDIM + h * HD + p] * dt[t0 * NH + h];
            float v1 = xbc[(long)(t0 + 1) * CDIM + h * HD + p] * dt[(t0 + 1) * NH + h];
            At[p * YSTR + sq] = f2h2(v0, v1);
        }
#pragma unroll
        for (int it = 0; it < 16; it++) {
            int idx = it * 256 + tid;
            int n = idx & 127, sq = idx >> 7;
            int t0 = tb + s0 + 2 * sq;
            float v0 = xbc[(long)t0 * CDIM + DINNER + n] * sdecay[s0 + 2 * sq];
            float v1 = xbc[(long)(t0 + 1) * CDIM + DINNER + n] * sdecay[s0 + 2 * sq + 1];
            Bt[n * YSTR + sq] = f2h2(v0, v1);
        }
        __syncthreads();
#pragma unroll
        for (int ks = 0; ks < 4; ks++) {
            unsigned bf[8][2];
#pragma unroll
            for (int nt = 0; nt < 8; nt++) {
                const unsigned* bp = Bt + (wn * 64 + nt * 8 + g) * YSTR + ks * 8;
                bf[nt][0] = bp[tig]; bf[nt][1] = bp[tig + 4];
            }
            const unsigned* ap = At + (wm * 16 + g) * YSTR + ks * 8;
            unsigned a0 = ap[tig], a2 = ap[tig + 4];
            unsigned a1 = ap[8 * YSTR + tig], a3 = ap[8 * YSTR + tig + 4];
#pragma unroll
            for (int nt = 0; nt < 8; nt++)
                mma_h16(acc[nt][0], acc[nt][1], acc[nt][2], acc[nt][3],
                        a0, a1, a2, a3, bf[nt][0], bf[nt][1]);
        }
        __syncthreads();
    }

    float* ob = st + ((long)blockIdx.x << 13);
#pragma unroll
    for (int nt = 0; nt < 8; nt++) {
        int col = wn * 64 + nt * 8 + tig * 2;
        int row = wm * 16 + g;
        *(float2*)(ob + row * NST + col)       = make_float2(acc[nt][0], acc[nt][1]);
        *(float2*)(ob + (row + 8) * NST + col) = make_float2(acc[nt][2], acc[nt][3]);
    }
}

// ---------------- sequential chunk scan (4 quarter-blocks per (b,h)) ----------------
__global__ void k_scan(const float* __restrict__ st, const float* __restrict__ dacs,
                       float* __restrict__ pv)
{
    int bh = blockIdx.x >> 2, q = blockIdx.x & 3;
    int b = bh >> 6, h = bh & 63;
    int tid = threadIdx.x;
    int off = q * 2048 + tid;
    float carry[8];
#pragma unroll
    for (int j = 0; j < 8; j++) carry[j] = 0.f;
    for (int c = 0; c < 8; c++) {
        int cc = b * 8 + c;
        long base = (((long)(cc * 64 + h)) << 13) + off;
        float dec = __expf(dacs[((cc * 64 + h) << 8) + CK - 1]);
#pragma unroll
        for (int j = 0; j < 8; j++) {
            long e = base + j * 256;
            pv[e] = carry[j];
            carry[j] = carry[j] * dec + st[e];
        }
    }
}

// ======= k_y via fp16 MMA: Y = (W@xdt) + (C*el)@prev^T, + D*x, gated =======
__global__ __launch_bounds__(256) void k_y_mma(const float* __restrict__ xbc,
        const float* __restrict__ zx, const float* __restrict__ dt,
        const float* __restrict__ dacs, const float* __restrict__ cb,
        const float* __restrict__ pv, const float* __restrict__ Dsk,
        float* __restrict__ y)
{
    const int cc = blockIdx.x >> 6, h = blockIdx.x & 63;
    const int tb = cc * CK;
    const int tid = threadIdx.x, wid = tid >> 5, lane = tid & 31;
    const int g = lane >> 2, tig = lane & 3;

    __shared__ unsigned At[256 * YSTR];
    __shared__ unsigned Bt[64 * YSTR];
    __shared__ float sda[256];
    __shared__ float sel[256];

    sda[tid] = dacs[(blockIdx.x << 8) + tid];
    __syncthreads();
    sel[tid] = __expf(sda[(tid >> 6) << 6] - sda[tid]);
    __syncthreads();

    float acc[2][8][4];
#pragma unroll
    for (int i = 0; i < 2; i++)
#pragma unroll
        for (int j = 0; j < 8; j++)
#pragma unroll
            for (int r = 0; r < 4; r++) acc[i][j][r] = 0.f;

    const float* cbb = cb + ((long)cc << 16);

    // ---- phase 1: Y_diag, 4 s-tiles of 64 ----
    for (int st4 = 0; st4 < 4; st4++) {
        int s0 = st4 * 64;
        float Rt = sda[s0] - sda[s0 + 63];
        bool fast = (Rt <= 60.f);
        {
            int l = tid;
            unsigned* arow = At + l * YSTR;
            if (l < s0) {
#pragma unroll 8
                for (int it = 0; it < 32; it++) arow[it] = 0u;
            } else {
                float dal = sda[l];
                if (fast) {
                    float f1 = __expf(dal - sda[s0]);
#pragma unroll 4
                    for (int it = 0; it < 32; it++) {
                        int s = s0 + 2 * it;
                        float w0 = 0.f, w1 = 0.f;
                        if (s <= l) {
                            w0 = f1 * sel[s] * cbb[(s << 8) + l];
                            if (s + 1 <= l)
                                w1 = f1 * sel[s + 1] * cbb[((s + 1) << 8) + l];
                        }
                        arow[it] = f2h2(w0, w1);
                    }
                } else {
#pragma unroll 4
                    for (int it = 0; it < 32; it++) {
                        int s = s0 + 2 * it;
                        float w0 = 0.f, w1 = 0.f;
                        if (s <= l) {
                            w0 = __expf(dal - sda[s]) * cbb[(s << 8) + l];
                            if (s + 1 <= l)
                                w1 = __expf(dal - sda[s + 1]) * cbb[((s + 1) << 8) + l];
                        }
                        arow[it] = f2h2(w0, w1);
                    }
                }
            }
        }
#pragma unroll
        for (int it = 0; it < 8; it++) {
            int idx = it * 256 + tid;
            int p = idx & 63, sq = idx >> 6;
            int t0 = tb + s0 + 2 * sq;
            float v0 = xbc[(long)t0 * CDIM + h * HD + p] * dt[t0 * NH + h];
            float v1 = xbc[(long)(t0 + 1) * CDIM + h * HD + p] * dt[(t0 + 1) * NH + h];
            Bt[p * YSTR + sq] = f2h2(v0, v1);
        }
        __syncthreads();
        if (wid * 32 + 31 >= s0) {
#pragma unroll
            for (int ks = 0; ks < 4; ks++) {
                unsigned bf[8][2];
#pragma unroll
                for (int nt = 0; nt < 8; nt++) {
                    const unsigned* bp = Bt + (nt * 8 + g) * YSTR + ks * 8;
                    bf[nt][0] = bp[tig]; bf[nt][1] = bp[tig + 4];
                }
#pragma unroll
                for (int mt = 0; mt < 2; mt++) {
                    const unsigned* ap = At + (wid * 32 + mt * 16 + g) * YSTR + ks * 8;
                    unsigned a0 = ap[tig], a2 = ap[tig + 4];
                    unsigned a1 = ap[8 * YSTR + tig], a3 = ap[8 * YSTR + tig + 4];
#pragma unroll
                    for (int nt = 0; nt < 8; nt++)
                        mma_h16(acc[mt][nt][0], acc[mt][nt][1], acc[mt][nt][2], acc[mt][nt][3],
                                a0, a1, a2, a3, bf[nt][0], bf[nt][1]);
                }
            }
        }
        __syncthreads();
    }

    // phase-2 role of sel: exp(dA[l])
    sel[tid] = __expf(sda[tid]);
    __syncthreads();

    // ---- phase 2: Y_off, 2 n-subtiles of 64 ----
    const float* pvb = pv + ((long)blockIdx.x << 13);
    for (int ns = 0; ns < 2; ns++) {
        int n0 = ns * 64;
#pragma unroll
        for (int it = 0; it < 32; it++) {
            int idx = it * 256 + tid;
            int np = idx & 31, l = idx >> 5;
            float el = sel[l];
            float2 v = *(const float2*)&xbc[(long)(tb + l) * CDIM + DINNER + NST + n0 + 2 * np];
            At[l * YSTR + np] = f2h2(v.x * el, v.y * el);
        }
#pragma unroll
        for (int it = 0; it < 8; it++) {
            int idx = it * 256 + tid;
            int np = idx & 31, p = idx >> 5;
            float2 v = *(const float2*)&pvb[p * NST + n0 + 2 * np];
            Bt[p * YSTR + np] = f2h2(v.x, v.y);
        }
        __syncthreads();
#pragma unroll
        for (int ks = 0; ks < 4; ks++) {
            unsigned bf[8][2];
#pragma unroll
            for (int nt = 0; nt < 8; nt++) {
                const unsigned* bp = Bt + (nt * 8 + g) * YSTR + ks * 8;
                bf[nt][0] = bp[tig]; bf[nt][1] = bp[tig + 4];
            }
#pragma unroll
            for (int mt = 0; mt < 2; mt++) {
                const unsigned* ap = At + (wid * 32 + mt * 16 + g) * YSTR + ks * 8;
                unsigned a0 = ap[tig], a2 = ap[tig + 4];
                unsigned a1 = ap[8 * YSTR + tig], a3 = ap[8 * YSTR + tig + 4];
#pragma unroll
                for (int nt = 0; nt < 8; nt++)
                    mma_h16(acc[mt][nt][0], acc[mt][nt][1], acc[mt][nt][2], acc[mt][nt][3],
                            a0, a1, a2, a3, bf[nt][0], bf[nt][1]);
            }
        }
        __syncthreads();
    }

    // ---- epilogue: + D*x, gate silu(z) ----
    float dsk = Dsk[h];
#pragma unroll
    for (int mt = 0; mt < 2; mt++) {
#pragma unroll
        for (int nt = 0; nt < 8; nt++) {
            int col = nt * 8 + tig * 2;
#pragma unroll
            for (int rr = 0; rr < 2; rr++) {
                int l = wid * 32 + mt * 16 + g + rr * 8;
                int t = tb + l;
                float2 xv = *(const float2*)&xbc[(long)t * CDIM + h * HD + col];
                float2 zv = *(const float2*)&zx[(long)t * DPROJ + h * HD + col];
                float o0 = (acc[mt][nt][rr * 2 + 0] + xv.x * dsk) * fsilu(zv.x);
                float o1 = (acc[mt][nt][rr * 2 + 1] + xv.y * dsk) * fsilu(zv.y);
                *(float2*)&y[(long)t * DINNER + h * HD + col] = make_float2(o0, o1);
            }
        }
    }
}

// ---------------- RMSNorm (vectorized) ----------------
__global__ void k_rms(float* __restrict__ y, const float* __restrict__ nw)
{
    int t = blockIdx.x;
    float4* row = (float4*)(y + (long)t * DINNER);
    const float4* nw4 = (const float4*)nw;
    float ss = 0.f;
    for (int i = threadIdx.x; i < DINNER / 4; i += 256) {
        float4 v = row[i];
        ss = fmaf(v.x, v.x, ss); ss = fmaf(v.y, v.y, ss);
        ss = fmaf(v.z, v.z, ss); ss = fmaf(v.w, v.w, ss);
    }
    __shared__ float red[256];
    red[threadIdx.x] = ss; __syncthreads();
    for (int o = 128; o > 0; o >>= 1) {
        if (threadIdx.x < o) red[threadIdx.x] += red[threadIdx.x + o];
        __syncthreads();
    }
    float sc = rsqrtf(red[0] / (float)DINNER + 1e-5f);
    for (int i = threadIdx.x; i < DINNER / 4; i += 256) {
        float4 v = row[i], n = nw4[i];
        v.x *= sc * n.x; v.y *= sc * n.y; v.z *= sc * n.z; v.w *= sc * n.w;
        row[i] = v;
    }
}

// ---------------- launch ----------------
extern "C" void kernel_launch(void* const* d_in, const int* in_sizes, int n_in,
                              void* d_out, int out_size)
{
    const float* u     = (const float*)d_in[0];
    const float* Win   = (const float*)d_in[1];
    const float* convw = (const float*)d_in[2];
    const float* convb = (const float*)d_in[3];
    const float* dtb   = (const float*)d_in[4];
    const float* Alog  = (const float*)d_in[5];
    const float* Dsk   = (const float*)d_in[6];
    const float* nw    = (const float*)d_in[7];
    const float* Wout  = (const float*)d_in[8];
    float* out = (float*)d_out;

    static float *zx = nullptr, *xbc, *dt, *dacs, *cb, *st, *pv, *y;
    if (!zx) {
        cudaGetSymbolAddress((void**)&xbc,  g_xbc);
        cudaGetSymbolAddress((void**)&dt,   g_dtv);
        cudaGetSymbolAddress((void**)&dacs, g_dacs);
        cudaGetSymbolAddress((void**)&cb,   g_cb);
        cudaGetSymbolAddress((void**)&st,   g_st);
        cudaGetSymbolAddress((void**)&pv,   g_pv);
        cudaGetSymbolAddress((void**)&y,    g_y);
        cudaGetSymbolAddress((void**)&zx,   g_zx);
    }

    // 1) in_proj: zx = u @ Win^T   (M=4096, N=8512, K=2048)
    gemm_h16<<<dim3((DPROJ + 127) / 128, TOK / 128, 1), 256>>>(u, Win, zx,
        DMODEL, DMODEL, DMODEL, DPROJ, DPROJ, 0, 0, 0);

    // 2) conv + silu (4 channels/thread)
    k_conv<<<(TOK * C4 + 255) / 256, 256>>>(zx, convw, convb, xbc);

    // 3) softplus(dt) + dA cumsum (fused)
    k_dacs<<<NCC * NH, CK>>>(zx, dtb, Alog, dt, dacs);

    // 4) CB^T[cc][s][l] = B[s]·C[l]   (batched, M=256,N=256,K=128)
    gemm_h16<<<dim3(CK / 128, CK / 128, NCC), 256>>>(xbc + DINNER, xbc + DINNER + NST, cb,
        NST, CDIM, CDIM, CK, CK, (long)CK * CDIM, (long)CK * CDIM, (long)CK * CK);

    // 5) chunk states (tensor-core)
    k_states_mma<<<NCC * NH, 256>>>(xbc, dt, dacs, st);

    // 6) inter-chunk scan (4x parallelism)
    k_scan<<<2 * NH * 4, 256>>>(st, dacs, pv);

    // 7) Y = Y_diag + Y_off + skip, gated  (tensor-core)
    k_y_mma<<<NCC * NH, 256>>>(xbc, zx, dt, dacs, cb, pv, Dsk, y);

    // 8) RMSNorm
    k_rms<<<TOK, 256>>>(y, nw);

    // 9) out_proj: out = y @ Wout^T  (M=4096, N=2048, K=4096)
    gemm_h16<<<dim3(DMODEL / 128, TOK / 128, 1), 256>>>(y, Wout, out,
        DINNER, DINNER, DINNER, DMODEL, DMODEL, 0, 0, 0);
}

// round 14
// speedup vs baseline: 2.4749x; 1.2328x over previous
#include <cuda_runtime.h>
#include <cuda_fp16.h>

// ---------------- problem constants ----------------
#define TOK    4096        // BATCH*SEQLEN
#define DMODEL 2048
#define DINNER 4096
#define NH     64
#define HD     64
#define NST    128
#define CDIM   4352        // DINNER + 2*NST
#define DPROJ  8512        // 2*DINNER + 2*NST + NH
#define SEQ    2048
#define CK     256         // chunk length
#define NCC    16          // BATCH * (SEQ/CK) total chunks

// ---------------- scratch (device globals; no allocation) ----------------
__device__ __align__(16) float  g_zx  [(size_t)TOK*DPROJ];
__device__ __align__(16) float  g_xbc [(size_t)TOK*CDIM];
__device__ __align__(16) float  g_dtv [(size_t)TOK*NH];
__device__ __align__(16) float  g_dacs[(size_t)NCC*NH*CK];
__device__ __align__(16) float  g_cb  [(size_t)NCC*CK*CK];
__device__ __align__(16) float  g_st  [(size_t)NCC*NH*HD*NST];
__device__ __align__(16) float  g_pv  [(size_t)NCC*NH*HD*NST];
__device__ __align__(16) float  g_y   [(size_t)TOK*DINNER];
__device__ __align__(16) __half g_uh  [(size_t)TOK*DMODEL];     // u in fp16
__device__ __align__(16) __half g_winh[(size_t)DPROJ*DMODEL];   // Win in fp16
__device__ __align__(16) __half g_wouth[(size_t)DMODEL*DINNER]; // Wout in fp16
__device__ __align__(16) __half g_bch [(size_t)TOK*2*NST];      // conv B|C slice fp16
__device__ __align__(16) __half g_yh  [(size_t)TOK*DINNER];     // normalized y fp16

// ---------------- helpers ----------------
__device__ __forceinline__ unsigned f2h2(float lo, float hi) {
    __half2 h = __floats2half2_rn(lo, hi);
    return *(unsigned*)&h;
}
__device__ __forceinline__ void mma_h16(float& c0, float& c1, float& c2, float& c3,
                                        unsigned a0, unsigned a1, unsigned a2, unsigned a3,
                                        unsigned b0, unsigned b1) {
    asm volatile("mma.sync.aligned.m16n8k16.row.col.f32.f16.f16.f32 "
                 "{%0,%1,%2,%3}, {%4,%5,%6,%7}, {%8,%9}, {%0,%1,%2,%3};"
                 : "+f"(c0), "+f"(c1), "+f"(c2), "+f"(c3)
                 : "r"(a0), "r"(a1), "r"(a2), "r"(a3), "r"(b0), "r"(b1));
}
__device__ __forceinline__ float fsilu(float v) {
    return v * __fdividef(1.f, 1.f + __expf(-v));
}

// ---------------- fp32 -> fp16 convert (vectorized) ----------------
__global__ void k_cvt(const float* __restrict__ in, __half* __restrict__ out, int n4)
{
    int i = blockIdx.x * 256 + threadIdx.x;
    if (i >= n4) return;
    float4 v = ((const float4*)in)[i];
    ((uint2*)out)[i] = make_uint2(f2h2(v.x, v.y), f2h2(v.z, v.w));
}

// ------- fp16-NATIVE tensor-core GEMM: C[m,n] = sum_k A[m,k]*B[n,k] -------
// A,B are __half row-major. BM=128, BN=128, BK=16, 256 thr, warp tile 32x64,
// DOUBLE-BUFFERED. Loader: 1 LDG.128 + 1 STS.128 per operand per thread.
#define HSTR 12
__global__ __launch_bounds__(256) void gemm_h16n(
    const __half* __restrict__ A, const __half* __restrict__ B, float* __restrict__ C,
    int K, int lda, int ldb, int ldc, int N, long aB, long bB, long cB)
{
    const __half* Ab = A + (long)blockIdx.z * aB;
    const __half* Bb = B + (long)blockIdx.z * bB;
    float*        Cb = C + (long)blockIdx.z * cB;

    __shared__ unsigned As[2][128 * HSTR];
    __shared__ unsigned Bs[2][128 * HSTR];

    int tid  = threadIdx.x;
    int wid  = tid >> 5, lane = tid & 31;
    int g    = lane >> 2, tig = lane & 3;
    int wm   = wid & 3, wn = wid >> 2;          // 4 m-warps x 2 n-warps; warp tile 32x64
    int m0   = blockIdx.y * 128, n0 = blockIdx.x * 128;

    int aRow = tid >> 1, aColH = (tid & 1) * 8;   // 8 halves = 16B
    const __half* aptr = Ab + (long)(m0 + aRow) * lda + aColH;
    int bR = n0 + aRow; if (bR >= N) bR = N - 1;  // clamp ragged rows
    const __half* bptr = Bb + (long)bR * ldb + aColH;

    float acc[2][8][4];
#pragma unroll
    for (int i = 0; i < 2; i++)
#pragma unroll
        for (int j = 0; j < 8; j++)
#pragma unroll
            for (int r = 0; r < 4; r++) acc[i][j][r] = 0.f;

    uint4 ra = *(const uint4*)(aptr);
    uint4 rb = *(const uint4*)(bptr);
    *(uint4*)(As[0] + aRow * HSTR + (tid & 1) * 4) = ra;
    *(uint4*)(Bs[0] + aRow * HSTR + (tid & 1) * 4) = rb;
    __syncthreads();

    int cur = 0;
    for (int k0 = 0; k0 < K; k0 += 16) {
        bool nxt = (k0 + 16) < K;
        if (nxt) {
            ra = *(const uint4*)(aptr + k0 + 16);
            rb = *(const uint4*)(bptr + k0 + 16);
        }

        const unsigned* Ac = As[cur];
        const unsigned* Bc = Bs[cur];
        unsigned bf[8][2];
#pragma unroll
        for (int nt = 0; nt < 8; nt++) {
            const unsigned* bp = Bc + (wn * 64 + nt * 8 + g) * HSTR;
            bf[nt][0] = bp[tig]; bf[nt][1] = bp[tig + 4];
        }
#pragma unroll
        for (int mt = 0; mt < 2; mt++) {
            const unsigned* ap0 = Ac + (wm * 32 + mt * 16 + g) * HSTR;
            const unsigned* ap1 = ap0 + 8 * HSTR;
            unsigned a0 = ap0[tig], a2 = ap0[tig + 4];
            unsigned a1 = ap1[tig], a3 = ap1[tig + 4];
#pragma unroll
            for (int nt = 0; nt < 8; nt++)
                mma_h16(acc[mt][nt][0], acc[mt][nt][1], acc[mt][nt][2], acc[mt][nt][3],
                        a0, a1, a2, a3, bf[nt][0], bf[nt][1]);
        }

        if (nxt) {
            int s = cur ^ 1;
            *(uint4*)(As[s] + aRow * HSTR + (tid & 1) * 4) = ra;
            *(uint4*)(Bs[s] + aRow * HSTR + (tid & 1) * 4) = rb;
        }
        __syncthreads();
        cur ^= 1;
    }

#pragma unroll
    for (int mt = 0; mt < 2; mt++) {
#pragma unroll
        for (int nt = 0; nt < 8; nt++) {
            int row = m0 + wm * 32 + mt * 16 + g;
            int col = n0 + wn * 64 + nt * 8 + tig * 2;
            if (col < N) {
                *(float2*)(Cb + (long)row * ldc + col)       = make_float2(acc[mt][nt][0], acc[mt][nt][1]);
                *(float2*)(Cb + (long)(row + 8) * ldc + col) = make_float2(acc[mt][nt][2], acc[mt][nt][3]);
            }
        }
    }
}

// ------- causal conv1d(width 4) + bias + silu, 4 channels/thread; emits fp16 B|C -------
#define C4 (CDIM / 4)   // 1088
__global__ void k_conv(const float* __restrict__ zx, const float* __restrict__ w,
                       const float* __restrict__ bias, float* __restrict__ xbc,
                       __half* __restrict__ bch)
{
    int i = blockIdx.x * 256 + threadIdx.x;
    if (i >= TOK * C4) return;
    int t = i / C4, c4 = i - t * C4;
    int c = c4 * 4;
    int l = t & (SEQ - 1);

    float4 acc = *(const float4*)&bias[c];
    float4 w0 = *(const float4*)&w[(c + 0) * 4];
    float4 w1 = *(const float4*)&w[(c + 1) * 4];
    float4 w2 = *(const float4*)&w[(c + 2) * 4];
    float4 w3 = *(const float4*)&w[(c + 3) * 4];
    const float* base = zx + (long)t * DPROJ + DINNER + c;

#pragma unroll
    for (int k = 0; k < 4; k++) {
        int lt = l - 3 + k;
        if (lt >= 0) {
            float4 xv = *(const float4*)(base + (long)(k - 3) * DPROJ);
            float a0 = (k == 0) ? w0.x : (k == 1) ? w0.y : (k == 2) ? w0.z : w0.w;
            float a1 = (k == 0) ? w1.x : (k == 1) ? w1.y : (k == 2) ? w1.z : w1.w;
            float a2 = (k == 0) ? w2.x : (k == 1) ? w2.y : (k == 2) ? w2.z : w2.w;
            float a3 = (k == 0) ? w3.x : (k == 1) ? w3.y : (k == 2) ? w3.z : w3.w;
            acc.x = fmaf(a0, xv.x, acc.x);
            acc.y = fmaf(a1, xv.y, acc.y);
            acc.z = fmaf(a2, xv.z, acc.z);
            acc.w = fmaf(a3, xv.w, acc.w);
        }
    }
    float4 o;
    o.x = fsilu(acc.x); o.y = fsilu(acc.y); o.z = fsilu(acc.z); o.w = fsilu(acc.w);
    *(float4*)&xbc[(long)t * CDIM + c] = o;
    if (c >= DINNER) {
        // fp16 copy of the B|C slice for the CB GEMM
        *(uint2*)&bch[(long)t * (2 * NST) + (c - DINNER)] =
            make_uint2(f2h2(o.x, o.y), f2h2(o.z, o.w));
    }
}

// ------- per-(chunk,head) softplus(dt) + cumsum of dt*A (fused; writes dt too) -------
__global__ void k_dacs(const float* __restrict__ zx, const float* __restrict__ dt_bias,
                       const float* __restrict__ Alog, float* __restrict__ dtv,
                       float* __restrict__ dacs)
{
    int cc = blockIdx.x >> 6, h = blockIdx.x & 63;
    int s = threadIdx.x;
    int t = cc * CK + s;
    float raw = zx[(long)t * DPROJ + (DINNER + CDIM) + h] + dt_bias[h];
    float d = (raw > 20.f) ? raw : log1pf(expf(raw));
    dtv[t * NH + h] = d;
    float a = -expf(Alog[h]);
    float v = d * a;
    __shared__ float sm[CK];
    sm[s] = v; __syncthreads();
    for (int off = 1; off < CK; off <<= 1) {
        float tv = (s >= off) ? sm[s - off] : 0.f;
        __syncthreads();
        sm[s] += tv;
        __syncthreads();
    }
    dacs[(blockIdx.x << 8) + s] = sm[s];
}

// ======= chunk states via fp16 MMA =======
#define YSTR 36
__global__ __launch_bounds__(256) void k_states_mma(const float* __restrict__ xbc,
        const float* __restrict__ dt, const float* __restrict__ dacs, float* __restrict__ st)
{
    const int cc = blockIdx.x >> 6, h = blockIdx.x & 63;
    const int tb = cc * CK;
    const int tid = threadIdx.x, wid = tid >> 5, lane = tid & 31;
    const int g = lane >> 2, tig = lane & 3;
    const int wm = wid & 3, wn = wid >> 2;

    __shared__ unsigned At[64 * YSTR];
    __shared__ unsigned Bt[128 * YSTR];
    __shared__ float sdecay[CK];

    const float* dA = dacs + (blockIdx.x << 8);
    {
        float dlast = dA[CK - 1];
        sdecay[tid] = __expf(dlast - dA[tid]);
    }
    __syncthreads();

    float acc[8][4];
#pragma unroll
    for (int j = 0; j < 8; j++)
#pragma unroll
        for (int r = 0; r < 4; r++) acc[j][r] = 0.f;

    for (int s0 = 0; s0 < CK; s0 += 64) {
#pragma unroll
        for (int it = 0; it < 8; it++) {
            int idx = it * 256 + tid;
            int p = idx & 63, sq = idx >> 6;
            int t0 = tb + s0 + 2 * sq;
            float v0 = xbc[(long)t0 * CDIM + h * HD + p] * dt[t0 * NH + h];
            float v1 = xbc[(long)(t0 + 1) * CDIM + h * HD + p] * dt[(t0 + 1) * NH + h];
            At[p * YSTR + sq] = f2h2(v0, v1);
        }
#pragma unroll
        for (int it = 0; it < 16; it++) {
            int idx = it * 256 + tid;
            int n = idx & 127, sq = idx >> 7;
            int t0 = tb + s0 + 2 * sq;
            float v0 = xbc[(long)t0 * CDIM + DINNER + n] * sdecay[s0 + 2 * sq];
            float v1 = xbc[(long)(t0 + 1) * CDIM + DINNER + n] * sdecay[s0 + 2 * sq + 1];
            Bt[n * YSTR + sq] = f2h2(v0, v1);
        }
        __syncthreads();
#pragma unroll
        for (int ks = 0; ks < 4; ks++) {
            unsigned bf[8][2];
#pragma unroll
            for (int nt = 0; nt < 8; nt++) {
                const unsigned* bp = Bt + (wn * 64 + nt * 8 + g) * YSTR + ks * 8;
                bf[nt][0] = bp[tig]; bf[nt][1] = bp[tig + 4];
            }
            const unsigned* ap = At + (wm * 16 + g) * YSTR + ks * 8;
            unsigned a0 = ap[tig], a2 = ap[tig + 4];
            unsigned a1 = ap[8 * YSTR + tig], a3 = ap[8 * YSTR + tig + 4];
#pragma unroll
            for (int nt = 0; nt < 8; nt++)
                mma_h16(acc[nt][0], acc[nt][1], acc[nt][2], acc[nt][3],
                        a0, a1, a2, a3, bf[nt][0], bf[nt][1]);
        }
        __syncthreads();
    }

    float* ob = st + ((long)blockIdx.x << 13);
#pragma unroll
    for (int nt = 0; nt < 8; nt++) {
        int col = wn * 64 + nt * 8 + tig * 2;
        int row = wm * 16 + g;
        *(float2*)(ob + row * NST + col)       = make_float2(acc[nt][0], acc[nt][1]);
        *(float2*)(ob + (row + 8) * NST + col) = make_float2(acc[nt][2], acc[nt][3]);
    }
}

// ---------------- sequential chunk scan (4 quarter-blocks per (b,h)) ----------------
__global__ void k_scan(const float* __restrict__ st, const float* __restrict__ dacs,
                       float* __restrict__ pv)
{
    int bh = blockIdx.x >> 2, q = blockIdx.x & 3;
    int b = bh >> 6, h = bh & 63;
    int tid = threadIdx.x;
    int off = q * 2048 + tid;
    float carry[8];
#pragma unroll
    for (int j = 0; j < 8; j++) carry[j] = 0.f;
    for (int c = 0; c < 8; c++) {
        int cc = b * 8 + c;
        long base = (((long)(cc * 64 + h)) << 13) + off;
        float dec = __expf(dacs[((cc * 64 + h) << 8) + CK - 1]);
#pragma unroll
        for (int j = 0; j < 8; j++) {
            long e = base + j * 256;
            pv[e] = carry[j];
            carry[j] = carry[j] * dec + st[e];
        }
    }
}

// ======= k_y via fp16 MMA: Y = (W@xdt) + (C*el)@prev^T, + D*x, gated =======
__global__ __launch_bounds__(256) void k_y_mma(const float* __restrict__ xbc,
        const float* __restrict__ zx, const float* __restrict__ dt,
        const float* __restrict__ dacs, const float* __restrict__ cb,
        const float* __restrict__ pv, const float* __restrict__ Dsk,
        float* __restrict__ y)
{
    const int cc = blockIdx.x >> 6, h = blockIdx.x & 63;
    const int tb = cc * CK;
    const int tid = threadIdx.x, wid = tid >> 5, lane = tid & 31;
    const int g = lane >> 2, tig = lane & 3;

    __shared__ unsigned At[256 * YSTR];
    __shared__ unsigned Bt[64 * YSTR];
    __shared__ float sda[256];
    __shared__ float sel[256];

    sda[tid] = dacs[(blockIdx.x << 8) + tid];
    __syncthreads();
    sel[tid] = __expf(sda[(tid >> 6) << 6] - sda[tid]);
    __syncthreads();

    float acc[2][8][4];
#pragma unroll
    for (int i = 0; i < 2; i++)
#pragma unroll
        for (int j = 0; j < 8; j++)
#pragma unroll
            for (int r = 0; r < 4; r++) acc[i][j][r] = 0.f;

    const float* cbb = cb + ((long)cc << 16);

    // ---- phase 1: Y_diag, 4 s-tiles of 64 ----
    for (int st4 = 0; st4 < 4; st4++) {
        int s0 = st4 * 64;
        float Rt = sda[s0] - sda[s0 + 63];
        bool fast = (Rt <= 60.f);
        {
            int l = tid;
            unsigned* arow = At + l * YSTR;
            if (l < s0) {
#pragma unroll 8
                for (int it = 0; it < 32; it++) arow[it] = 0u;
            } else {
                float dal = sda[l];
                if (fast) {
                    float f1 = __expf(dal - sda[s0]);
#pragma unroll 4
                    for (int it = 0; it < 32; it++) {
                        int s = s0 + 2 * it;
                        float w0 = 0.f, w1 = 0.f;
                        if (s <= l) {
                            w0 = f1 * sel[s] * cbb[(s << 8) + l];
                            if (s + 1 <= l)
                                w1 = f1 * sel[s + 1] * cbb[((s + 1) << 8) + l];
                        }
                        arow[it] = f2h2(w0, w1);
                    }
                } else {
#pragma unroll 4
                    for (int it = 0; it < 32; it++) {
                        int s = s0 + 2 * it;
                        float w0 = 0.f, w1 = 0.f;
                        if (s <= l) {
                            w0 = __expf(dal - sda[s]) * cbb[(s << 8) + l];
                            if (s + 1 <= l)
                                w1 = __expf(dal - sda[s + 1]) * cbb[((s + 1) << 8) + l];
                        }
                        arow[it] = f2h2(w0, w1);
                    }
                }
            }
        }
#pragma unroll
        for (int it = 0; it < 8; it++) {
            int idx = it * 256 + tid;
            int p = idx & 63, sq = idx >> 6;
            int t0 = tb + s0 + 2 * sq;
            float v0 = xbc[(long)t0 * CDIM + h * HD + p] * dt[t0 * NH + h];
            float v1 = xbc[(long)(t0 + 1) * CDIM + h * HD + p] * dt[(t0 + 1) * NH + h];
            Bt[p * YSTR + sq] = f2h2(v0, v1);
        }
        __syncthreads();
        if (wid * 32 + 31 >= s0) {
#pragma unroll
            for (int ks = 0; ks < 4; ks++) {
                unsigned bf[8][2];
#pragma unroll
                for (int nt = 0; nt < 8; nt++) {
                    const unsigned* bp = Bt + (nt * 8 + g) * YSTR + ks * 8;
                    bf[nt][0] = bp[tig]; bf[nt][1] = bp[tig + 4];
                }
#pragma unroll
                for (int mt = 0; mt < 2; mt++) {
                    const unsigned* ap = At + (wid * 32 + mt * 16 + g) * YSTR + ks * 8;
                    unsigned a0 = ap[tig], a2 = ap[tig + 4];
                    unsigned a1 = ap[8 * YSTR + tig], a3 = ap[8 * YSTR + tig + 4];
#pragma unroll
                    for (int nt = 0; nt < 8; nt++)
                        mma_h16(acc[mt][nt][0], acc[mt][nt][1], acc[mt][nt][2], acc[mt][nt][3],
                                a0, a1, a2, a3, bf[nt][0], bf[nt][1]);
                }
            }
        }
        __syncthreads();
    }

    // phase-2 role of sel: exp(dA[l])
    sel[tid] = __expf(sda[tid]);
    __syncthreads();

    // ---- phase 2: Y_off, 2 n-subtiles of 64 ----
    const float* pvb = pv + ((long)blockIdx.x << 13);
    for (int ns = 0; ns < 2; ns++) {
        int n0 = ns * 64;
#pragma unroll
        for (int it = 0; it < 32; it++) {
            int idx = it * 256 + tid;
            int np = idx & 31, l = idx >> 5;
            float el = sel[l];
            float2 v = *(const float2*)&xbc[(long)(tb + l) * CDIM + DINNER + NST + n0 + 2 * np];
            At[l * YSTR + np] = f2h2(v.x * el, v.y * el);
        }
#pragma unroll
        for (int it = 0; it < 8; it++) {
            int idx = it * 256 + tid;
            int np = idx & 31, p = idx >> 5;
            float2 v = *(const float2*)&pvb[p * NST + n0 + 2 * np];
            Bt[p * YSTR + np] = f2h2(v.x, v.y);
        }
        __syncthreads();
#pragma unroll
        for (int ks = 0; ks < 4; ks++) {
            unsigned bf[8][2];
#pragma unroll
            for (int nt = 0; nt < 8; nt++) {
                const unsigned* bp = Bt + (nt * 8 + g) * YSTR + ks * 8;
                bf[nt][0] = bp[tig]; bf[nt][1] = bp[tig + 4];
            }
#pragma unroll
            for (int mt = 0; mt < 2; mt++) {
                const unsigned* ap = At + (wid * 32 + mt * 16 + g) * YSTR + ks * 8;
                unsigned a0 = ap[tig], a2 = ap[tig + 4];
                unsigned a1 = ap[8 * YSTR + tig], a3 = ap[8 * YSTR + tig + 4];
#pragma unroll
                for (int nt = 0; nt < 8; nt++)
                    mma_h16(acc[mt][nt][0], acc[mt][nt][1], acc[mt][nt][2], acc[mt][nt][3],
                            a0, a1, a2, a3, bf[nt][0], bf[nt][1]);
            }
        }
        __syncthreads();
    }

    // ---- epilogue: + D*x, gate silu(z) ----
    float dsk = Dsk[h];
#pragma unroll
    for (int mt = 0; mt < 2; mt++) {
#pragma unroll
        for (int nt = 0; nt < 8; nt++) {
            int col = nt * 8 + tig * 2;
#pragma unroll
            for (int rr = 0; rr < 2; rr++) {
                int l = wid * 32 + mt * 16 + g + rr * 8;
                int t = tb + l;
                float2 xv = *(const float2*)&xbc[(long)t * CDIM + h * HD + col];
                float2 zv = *(const float2*)&zx[(long)t * DPROJ + h * HD + col];
                float o0 = (acc[mt][nt][rr * 2 + 0] + xv.x * dsk) * fsilu(zv.x);
                float o1 = (acc[mt][nt][rr * 2 + 1] + xv.y * dsk) * fsilu(zv.y);
                *(float2*)&y[(long)t * DINNER + h * HD + col] = make_float2(o0, o1);
            }
        }
    }
}

// ---------------- RMSNorm: reads y fp32, writes normalized fp16 ----------------
__global__ void k_rms(const float* __restrict__ y, const float* __restrict__ nw,
                      __half* __restrict__ yh)
{
    int t = blockIdx.x;
    const float4* row = (const float4*)(y + (long)t * DINNER);
    const float4* nw4 = (const float4*)nw;
    float ss = 0.f;
    for (int i = threadIdx.x; i < DINNER / 4; i += 256) {
        float4 v = row[i];
        ss = fmaf(v.x, v.x, ss); ss = fmaf(v.y, v.y, ss);
        ss = fmaf(v.z, v.z, ss); ss = fmaf(v.w, v.w, ss);
    }
    __shared__ float red[256];
    red[threadIdx.x] = ss; __syncthreads();
    for (int o = 128; o > 0; o >>= 1) {
        if (threadIdx.x < o) red[threadIdx.x] += red[threadIdx.x + o];
        __syncthreads();
    }
    float sc = rsqrtf(red[0] / (float)DINNER + 1e-5f);
    uint2* oh = (uint2*)(yh + (long)t * DINNER);
    for (int i = threadIdx.x; i < DINNER / 4; i += 256) {
        float4 v = row[i], n = nw4[i];
        oh[i] = make_uint2(f2h2(v.x * sc * n.x, v.y * sc * n.y),
                           f2h2(v.z * sc * n.z, v.w * sc * n.w));
    }
}

// ---------------- launch ----------------
extern "C" void kernel_launch(void* const* d_in, const int* in_sizes, int n_in,
                              void* d_out, int out_size)
{
    const float* u     = (const float*)d_in[0];
    const float* Win   = (const float*)d_in[1];
    const float* convw = (const float*)d_in[2];
    const float* convb = (const float*)d_in[3];
    const float* dtb   = (const float*)d_in[4];
    const float* Alog  = (const float*)d_in[5];
    const float* Dsk   = (const float*)d_in[6];
    const float* nw    = (const float*)d_in[7];
    const float* Wout  = (const float*)d_in[8];
    float* out = (float*)d_out;

    static float *zx = nullptr, *xbc, *dt, *dacs, *cb, *st, *pv, *y;
    static __half *uh, *winh, *wouth, *bch, *yh;
    if (!zx) {
        cudaGetSymbolAddress((void**)&xbc,   g_xbc);
        cudaGetSymbolAddress((void**)&dt,    g_dtv);
        cudaGetSymbolAddress((void**)&dacs,  g_dacs);
        cudaGetSymbolAddress((void**)&cb,    g_cb);
        cudaGetSymbolAddress((void**)&st,    g_st);
        cudaGetSymbolAddress((void**)&pv,    g_pv);
        cudaGetSymbolAddress((void**)&y,     g_y);
        cudaGetSymbolAddress((void**)&uh,    g_uh);
        cudaGetSymbolAddress((void**)&winh,  g_winh);
        cudaGetSymbolAddress((void**)&wouth, g_wouth);
        cudaGetSymbolAddress((void**)&bch,   g_bch);
        cudaGetSymbolAddress((void**)&yh,    g_yh);
        cudaGetSymbolAddress((void**)&zx,    g_zx);
    }

    // 0) fp16 conversions of GEMM operands
    k_cvt<<<(TOK * DMODEL / 4 + 255) / 256, 256>>>(u, uh, TOK * DMODEL / 4);
    k_cvt<<<(DPROJ * DMODEL / 4 + 255) / 256, 256>>>(Win, winh, DPROJ * DMODEL / 4);
    k_cvt<<<(DMODEL * DINNER / 4 + 255) / 256, 256>>>(Wout, wouth, DMODEL * DINNER / 4);

    // 1) in_proj: zx = u @ Win^T   (M=4096, N=8512, K=2048)
    gemm_h16n<<<dim3((DPROJ + 127) / 128, TOK / 128, 1), 256>>>(uh, winh, zx,
        DMODEL, DMODEL, DMODEL, DPROJ, DPROJ, 0, 0, 0);

    // 2) conv + silu (4 channels/thread, emits fp16 B|C slice)
    k_conv<<<(TOK * C4 + 255) / 256, 256>>>(zx, convw, convb, xbc, bch);

    // 3) softplus(dt) + dA cumsum (fused)
    k_dacs<<<NCC * NH, CK>>>(zx, dtb, Alog, dt, dacs);

    // 4) CB^T[cc][s][l] = B[s]·C[l]   (batched, fp16-native; M=256,N=256,K=128)
    gemm_h16n<<<dim3(CK / 128, CK / 128, NCC), 256>>>(bch, bch + NST, cb,
        NST, 2 * NST, 2 * NST, CK, CK, (long)CK * 2 * NST, (long)CK * 2 * NST, (long)CK * CK);

    // 5) chunk states (tensor-core)
    k_states_mma<<<NCC * NH, 256>>>(xbc, dt, dacs, st);

    // 6) inter-chunk scan (4x parallelism)
    k_scan<<<2 * NH * 4, 256>>>(st, dacs, pv);

    // 7) Y = Y_diag + Y_off + skip, gated  (tensor-core)
    k_y_mma<<<NCC * NH, 256>>>(xbc, zx, dt, dacs, cb, pv, Dsk, y);

    // 8) RMSNorm -> fp16
    k_rms<<<TOK, 256>>>(y, nw, yh);

    // 9) out_proj: out = yh @ Wout^T  (M=4096, N=2048, K=4096)
    gemm_h16n<<<dim3(DMODEL / 128, TOK / 128, 1), 256>>>(yh, wouth, out,
        DINNER, DINNER, DINNER, DMODEL, DMODEL, 0, 0, 0);
}

// round 15
// speedup vs baseline: 2.7349x; 1.1051x over previous
#include <cuda_runtime.h>
#include <cuda_fp16.h>

// ---------------- problem constants ----------------
#define TOK    4096        // BATCH*SEQLEN
#define DMODEL 2048
#define DINNER 4096
#define NH     64
#define HD     64
#define NST    128
#define CDIM   4352        // DINNER + 2*NST
#define DPROJ  8512        // 2*DINNER + 2*NST + NH
#define SEQ    2048
#define CK     256         // chunk length
#define NCC    16          // BATCH * (SEQ/CK) total chunks

// ---------------- scratch (device globals; no allocation) ----------------
__device__ __align__(16) float  g_zx  [(size_t)TOK*DPROJ];
__device__ __align__(16) float  g_xbc [(size_t)TOK*CDIM];
__device__ __align__(16) float  g_dtv [(size_t)TOK*NH];
__device__ __align__(16) float  g_dacs[(size_t)NCC*NH*CK];
__device__ __align__(16) float  g_cb  [(size_t)NCC*CK*CK];
__device__ __align__(16) float  g_st  [(size_t)NCC*NH*HD*NST];
__device__ __align__(16) float  g_pv  [(size_t)NCC*NH*HD*NST];
__device__ __align__(16) float  g_y   [(size_t)TOK*DINNER];
__device__ __align__(16) __half g_uh  [(size_t)TOK*DMODEL];
__device__ __align__(16) __half g_winh[(size_t)DPROJ*DMODEL];
__device__ __align__(16) __half g_wouth[(size_t)DMODEL*DINNER];
__device__ __align__(16) __half g_bch [(size_t)TOK*2*NST];
__device__ __align__(16) __half g_yh  [(size_t)TOK*DINNER];

// ---------------- helpers ----------------
__device__ __forceinline__ unsigned f2h2(float lo, float hi) {
    __half2 h = __floats2half2_rn(lo, hi);
    return *(unsigned*)&h;
}
__device__ __forceinline__ void mma_h16(float& c0, float& c1, float& c2, float& c3,
                                        unsigned a0, unsigned a1, unsigned a2, unsigned a3,
                                        unsigned b0, unsigned b1) {
    asm volatile("mma.sync.aligned.m16n8k16.row.col.f32.f16.f16.f32 "
                 "{%0,%1,%2,%3}, {%4,%5,%6,%7}, {%8,%9}, {%0,%1,%2,%3};"
                 : "+f"(c0), "+f"(c1), "+f"(c2), "+f"(c3)
                 : "r"(a0), "r"(a1), "r"(a2), "r"(a3), "r"(b0), "r"(b1));
}
__device__ __forceinline__ void ldsm_x4(unsigned& r0, unsigned& r1, unsigned& r2,
                                        unsigned& r3, unsigned addr) {
    asm volatile("ldmatrix.sync.aligned.m8n8.x4.shared.b16 {%0,%1,%2,%3}, [%4];"
                 : "=r"(r0), "=r"(r1), "=r"(r2), "=r"(r3) : "r"(addr));
}
__device__ __forceinline__ float fsilu(float v) {
    return v * __fdividef(1.f, 1.f + __expf(-v));
}

// ---------------- fp32 -> fp16 convert (vectorized) ----------------
__global__ void k_cvt(const float* __restrict__ in, __half* __restrict__ out, int n4)
{
    int i = blockIdx.x * 256 + threadIdx.x;
    if (i >= n4) return;
    float4 v = ((const float4*)in)[i];
    ((uint2*)out)[i] = make_uint2(f2h2(v.x, v.y), f2h2(v.z, v.w));
}

// ------- fp16-NATIVE tensor-core GEMM with ldmatrix fragment loads -------
// BM=128, BN=128, BK=16, 256 thr, warp tile 32x64, DOUBLE-BUFFERED.
// HSTR=12 (48B row stride) is LDSM-conflict-free: 8 rows hit 8 distinct 16B banks.
#define HSTR 12
__global__ __launch_bounds__(256) void gemm_h16n(
    const __half* __restrict__ A, const __half* __restrict__ B, float* __restrict__ C,
    int K, int lda, int ldb, int ldc, int N, long aB, long bB, long cB)
{
    const __half* Ab = A + (long)blockIdx.z * aB;
    const __half* Bb = B + (long)blockIdx.z * bB;
    float*        Cb = C + (long)blockIdx.z * cB;

    __shared__ unsigned As[2][128 * HSTR];
    __shared__ unsigned Bs[2][128 * HSTR];

    int tid  = threadIdx.x;
    int wid  = tid >> 5, lane = tid & 31;
    int g    = lane >> 2, tig = lane & 3;
    int wm   = wid & 3, wn = wid >> 2;          // 4 m-warps x 2 n-warps; warp tile 32x64
    int m0   = blockIdx.y * 128, n0 = blockIdx.x * 128;

    int aRow = tid >> 1, aColH = (tid & 1) * 8;
    const __half* aptr = Ab + (long)(m0 + aRow) * lda + aColH;
    int bR = n0 + aRow; if (bR >= N) bR = N - 1;
    const __half* bptr = Bb + (long)bR * ldb + aColH;

    // LDSM per-lane addresses (byte offsets into stage-0 buffers)
    unsigned asBase = (unsigned)__cvta_generic_to_shared(&As[0][0]);
    unsigned bsBase = (unsigned)__cvta_generic_to_shared(&Bs[0][0]);
    // A tiles: lanes 0-7:(m0-7,k0-7) 8-15:(m8-15,k0-7) 16-23:(m0-7,k8-15) 24-31:(m8-15,k8-15)
    unsigned aLd = ((unsigned)((wm * 32 + ((lane >> 3) & 1) * 8 + (lane & 7)) * HSTR
                               + (lane >> 4) * 4)) * 4u;
    // B tiles: lanes 0-7:(n0-7,k0-7) 8-15:(n0-7,k8-15) 16-23:(n8-15,k0-7) 24-31:(n8-15,k8-15)
    unsigned bLd = ((unsigned)((wn * 64 + ((lane >> 4) & 1) * 8 + (lane & 7)) * HSTR
                               + ((lane >> 3) & 1) * 4)) * 4u;
    const unsigned STGB = 128 * HSTR * 4;   // stage stride in bytes

    float acc[2][8][4];
#pragma unroll
    for (int i = 0; i < 2; i++)
#pragma unroll
        for (int j = 0; j < 8; j++)
#pragma unroll
            for (int r = 0; r < 4; r++) acc[i][j][r] = 0.f;

    uint4 ra = *(const uint4*)(aptr);
    uint4 rb = *(const uint4*)(bptr);
    *(uint4*)(As[0] + aRow * HSTR + (tid & 1) * 4) = ra;
    *(uint4*)(Bs[0] + aRow * HSTR + (tid & 1) * 4) = rb;
    __syncthreads();

    int cur = 0;
    for (int k0 = 0; k0 < K; k0 += 16) {
        bool nxt = (k0 + 16) < K;
        if (nxt) {
            ra = *(const uint4*)(aptr + k0 + 16);
            rb = *(const uint4*)(bptr + k0 + 16);
        }

        unsigned so = cur * STGB;
        unsigned bf[8][2];
#pragma unroll
        for (int ntp = 0; ntp < 4; ntp++)
            ldsm_x4(bf[2*ntp][0], bf[2*ntp][1], bf[2*ntp+1][0], bf[2*ntp+1][1],
                    bsBase + so + bLd + ntp * (16 * HSTR * 4));
#pragma unroll
        for (int mt = 0; mt < 2; mt++) {
            unsigned a0, a1, a2, a3;
            ldsm_x4(a0, a1, a2, a3, asBase + so + aLd + mt * (16 * HSTR * 4));
#pragma unroll
            for (int nt = 0; nt < 8; nt++)
                mma_h16(acc[mt][nt][0], acc[mt][nt][1], acc[mt][nt][2], acc[mt][nt][3],
                        a0, a1, a2, a3, bf[nt][0], bf[nt][1]);
        }

        if (nxt) {
            int s = cur ^ 1;
            *(uint4*)(As[s] + aRow * HSTR + (tid & 1) * 4) = ra;
            *(uint4*)(Bs[s] + aRow * HSTR + (tid & 1) * 4) = rb;
        }
        __syncthreads();
        cur ^= 1;
    }

#pragma unroll
    for (int mt = 0; mt < 2; mt++) {
#pragma unroll
        for (int nt = 0; nt < 8; nt++) {
            int row = m0 + wm * 32 + mt * 16 + g;
            int col = n0 + wn * 64 + nt * 8 + tig * 2;
            if (col < N) {
                *(float2*)(Cb + (long)row * ldc + col)       = make_float2(acc[mt][nt][0], acc[mt][nt][1]);
                *(float2*)(Cb + (long)(row + 8) * ldc + col) = make_float2(acc[mt][nt][2], acc[mt][nt][3]);
            }
        }
    }
}

// ------- causal conv1d(width 4) + bias + silu, 4 channels/thread; emits fp16 B|C -------
#define C4 (CDIM / 4)   // 1088
__global__ void k_conv(const float* __restrict__ zx, const float* __restrict__ w,
                       const float* __restrict__ bias, float* __restrict__ xbc,
                       __half* __restrict__ bch)
{
    int i = blockIdx.x * 256 + threadIdx.x;
    if (i >= TOK * C4) return;
    int t = i / C4, c4 = i - t * C4;
    int c = c4 * 4;
    int l = t & (SEQ - 1);

    float4 acc = *(const float4*)&bias[c];
    float4 w0 = *(const float4*)&w[(c + 0) * 4];
    float4 w1 = *(const float4*)&w[(c + 1) * 4];
    float4 w2 = *(const float4*)&w[(c + 2) * 4];
    float4 w3 = *(const float4*)&w[(c + 3) * 4];
    const float* base = zx + (long)t * DPROJ + DINNER + c;

#pragma unroll
    for (int k = 0; k < 4; k++) {
        int lt = l - 3 + k;
        if (lt >= 0) {
            float4 xv = *(const float4*)(base + (long)(k - 3) * DPROJ);
            float a0 = (k == 0) ? w0.x : (k == 1) ? w0.y : (k == 2) ? w0.z : w0.w;
            float a1 = (k == 0) ? w1.x : (k == 1) ? w1.y : (k == 2) ? w1.z : w1.w;
            float a2 = (k == 0) ? w2.x : (k == 1) ? w2.y : (k == 2) ? w2.z : w2.w;
            float a3 = (k == 0) ? w3.x : (k == 1) ? w3.y : (k == 2) ? w3.z : w3.w;
            acc.x = fmaf(a0, xv.x, acc.x);
            acc.y = fmaf(a1, xv.y, acc.y);
            acc.z = fmaf(a2, xv.z, acc.z);
            acc.w = fmaf(a3, xv.w, acc.w);
        }
    }
    float4 o;
    o.x = fsilu(acc.x); o.y = fsilu(acc.y); o.z = fsilu(acc.z); o.w = fsilu(acc.w);
    *(float4*)&xbc[(long)t * CDIM + c] = o;
    if (c >= DINNER) {
        *(uint2*)&bch[(long)t * (2 * NST) + (c - DINNER)] =
            make_uint2(f2h2(o.x, o.y), f2h2(o.z, o.w));
    }
}

// ------- per-(chunk,head) softplus(dt) + cumsum of dt*A (fused; writes dt too) -------
__global__ void k_dacs(const float* __restrict__ zx, const float* __restrict__ dt_bias,
                       const float* __restrict__ Alog, float* __restrict__ dtv,
                       float* __restrict__ dacs)
{
    int cc = blockIdx.x >> 6, h = blockIdx.x & 63;
    int s = threadIdx.x;
    int t = cc * CK + s;
    float raw = zx[(long)t * DPROJ + (DINNER + CDIM) + h] + dt_bias[h];
    float d = (raw > 20.f) ? raw : log1pf(expf(raw));
    dtv[t * NH + h] = d;
    float a = -expf(Alog[h]);
    float v = d * a;
    __shared__ float sm[CK];
    sm[s] = v; __syncthreads();
    for (int off = 1; off < CK; off <<= 1) {
        float tv = (s >= off) ? sm[s - off] : 0.f;
        __syncthreads();
        sm[s] += tv;
        __syncthreads();
    }
    dacs[(blockIdx.x << 8) + s] = sm[s];
}

// ======= chunk states via fp16 MMA =======
#define YSTR 36
__global__ __launch_bounds__(256) void k_states_mma(const float* __restrict__ xbc,
        const float* __restrict__ dt, const float* __restrict__ dacs, float* __restrict__ st)
{
    const int cc = blockIdx.x >> 6, h = blockIdx.x & 63;
    const int tb = cc * CK;
    const int tid = threadIdx.x, wid = tid >> 5, lane = tid & 31;
    const int g = lane >> 2, tig = lane & 3;
    const int wm = wid & 3, wn = wid >> 2;

    __shared__ unsigned At[64 * YSTR];
    __shared__ unsigned Bt[128 * YSTR];
    __shared__ float sdecay[CK];

    const float* dA = dacs + (blockIdx.x << 8);
    {
        float dlast = dA[CK - 1];
        sdecay[tid] = __expf(dlast - dA[tid]);
    }
    __syncthreads();

    float acc[8][4];
#pragma unroll
    for (int j = 0; j < 8; j++)
#pragma unroll
        for (int r = 0; r < 4; r++) acc[j][r] = 0.f;

    for (int s0 = 0; s0 < CK; s0 += 64) {
#pragma unroll
        for (int it = 0; it < 8; it++) {
            int idx = it * 256 + tid;
            int p = idx & 63, sq = idx >> 6;
            int t0 = tb + s0 + 2 * sq;
            float v0 = xbc[(long)t0 * CDIM + h * HD + p] * dt[t0 * NH + h];
            float v1 = xbc[(long)(t0 + 1) * CDIM + h * HD + p] * dt[(t0 + 1) * NH + h];
            At[p * YSTR + sq] = f2h2(v0, v1);
        }
#pragma unroll
        for (int it = 0; it < 16; it++) {
            int idx = it * 256 + tid;
            int n = idx & 127, sq = idx >> 7;
            int t0 = tb + s0 + 2 * sq;
            float v0 = xbc[(long)t0 * CDIM + DINNER + n] * sdecay[s0 + 2 * sq];
            float v1 = xbc[(long)(t0 + 1) * CDIM + DINNER + n] * sdecay[s0 + 2 * sq + 1];
            Bt[n * YSTR + sq] = f2h2(v0, v1);
        }
        __syncthreads();
#pragma unroll
        for (int ks = 0; ks < 4; ks++) {
            unsigned bf[8][2];
#pragma unroll
            for (int nt = 0; nt < 8; nt++) {
                const unsigned* bp = Bt + (wn * 64 + nt * 8 + g) * YSTR + ks * 8;
                bf[nt][0] = bp[tig]; bf[nt][1] = bp[tig + 4];
            }
            const unsigned* ap = At + (wm * 16 + g) * YSTR + ks * 8;
            unsigned a0 = ap[tig], a2 = ap[tig + 4];
            unsigned a1 = ap[8 * YSTR + tig], a3 = ap[8 * YSTR + tig + 4];
#pragma unroll
            for (int nt = 0; nt < 8; nt++)
                mma_h16(acc[nt][0], acc[nt][1], acc[nt][2], acc[nt][3],
                        a0, a1, a2, a3, bf[nt][0], bf[nt][1]);
        }
        __syncthreads();
    }

    float* ob = st + ((long)blockIdx.x << 13);
#pragma unroll
    for (int nt = 0; nt < 8; nt++) {
        int col = wn * 64 + nt * 8 + tig * 2;
        int row = wm * 16 + g;
        *(float2*)(ob + row * NST + col)       = make_float2(acc[nt][0], acc[nt][1]);
        *(float2*)(ob + (row + 8) * NST + col) = make_float2(acc[nt][2], acc[nt][3]);
    }
}

// ---------------- sequential chunk scan (4 quarter-blocks per (b,h)) ----------------
__global__ void k_scan(const float* __restrict__ st, const float* __restrict__ dacs,
                       float* __restrict__ pv)
{
    int bh = blockIdx.x >> 2, q = blockIdx.x & 3;
    int b = bh >> 6, h = bh & 63;
    int tid = threadIdx.x;
    int off = q * 2048 + tid;
    float carry[8];
#pragma unroll
    for (int j = 0; j < 8; j++) carry[j] = 0.f;
    for (int c = 0; c < 8; c++) {
        int cc = b * 8 + c;
        long base = (((long)(cc * 64 + h)) << 13) + off;
        float dec = __expf(dacs[((cc * 64 + h) << 8) + CK - 1]);
#pragma unroll
        for (int j = 0; j < 8; j++) {
            long e = base + j * 256;
            pv[e] = carry[j];
            carry[j] = carry[j] * dec + st[e];
        }
    }
}

// ======= k_y via fp16 MMA: Y = (W@xdt) + (C*el)@prev^T, + D*x, gated =======
__global__ __launch_bounds__(256) void k_y_mma(const float* __restrict__ xbc,
        const float* __restrict__ zx, const float* __restrict__ dt,
        const float* __restrict__ dacs, const float* __restrict__ cb,
        const float* __restrict__ pv, const float* __restrict__ Dsk,
        float* __restrict__ y)
{
    const int cc = blockIdx.x >> 6, h = blockIdx.x & 63;
    const int tb = cc * CK;
    const int tid = threadIdx.x, wid = tid >> 5, lane = tid & 31;
    const int g = lane >> 2, tig = lane & 3;

    __shared__ unsigned At[256 * YSTR];
    __shared__ unsigned Bt[64 * YSTR];
    __shared__ float sda[256];
    __shared__ float sel[256];

    sda[tid] = dacs[(blockIdx.x << 8) + tid];
    __syncthreads();
    sel[tid] = __expf(sda[(tid >> 6) << 6] - sda[tid]);
    __syncthreads();

    float acc[2][8][4];
#pragma unroll
    for (int i = 0; i < 2; i++)
#pragma unroll
        for (int j = 0; j < 8; j++)
#pragma unroll
            for (int r = 0; r < 4; r++) acc[i][j][r] = 0.f;

    const float* cbb = cb + ((long)cc << 16);

    // ---- phase 1: Y_diag, 4 s-tiles of 64 ----
    for (int st4 = 0; st4 < 4; st4++) {
        int s0 = st4 * 64;
        float Rt = sda[s0] - sda[s0 + 63];
        bool fast = (Rt <= 60.f);
        {
            int l = tid;
            unsigned* arow = At + l * YSTR;
            if (l < s0) {
#pragma unroll 8
                for (int it = 0; it < 32; it++) arow[it] = 0u;
            } else {
                float dal = sda[l];
                if (fast) {
                    float f1 = __expf(dal - sda[s0]);
#pragma unroll 4
                    for (int it = 0; it < 32; it++) {
                        int s = s0 + 2 * it;
                        float w0 = 0.f, w1 = 0.f;
                        if (s <= l) {
                            w0 = f1 * sel[s] * cbb[(s << 8) + l];
                            if (s + 1 <= l)
                                w1 = f1 * sel[s + 1] * cbb[((s + 1) << 8) + l];
                        }
                        arow[it] = f2h2(w0, w1);
                    }
                } else {
#pragma unroll 4
                    for (int it = 0; it < 32; it++) {
                        int s = s0 + 2 * it;
                        float w0 = 0.f, w1 = 0.f;
                        if (s <= l) {
                            w0 = __expf(dal - sda[s]) * cbb[(s << 8) + l];
                            if (s + 1 <= l)
                                w1 = __expf(dal - sda[s + 1]) * cbb[((s + 1) << 8) + l];
                        }
                        arow[it] = f2h2(w0, w1);
                    }
                }
            }
        }
#pragma unroll
        for (int it = 0; it < 8; it++) {
            int idx = it * 256 + tid;
            int p = idx & 63, sq = idx >> 6;
            int t0 = tb + s0 + 2 * sq;
            float v0 = xbc[(long)t0 * CDIM + h * HD + p] * dt[t0 * NH + h];
            float v1 = xbc[(long)(t0 + 1) * CDIM + h * HD + p] * dt[(t0 + 1) * NH + h];
            Bt[p * YSTR + sq] = f2h2(v0, v1);
        }
        __syncthreads();
        if (wid * 32 + 31 >= s0) {
#pragma unroll
            for (int ks = 0; ks < 4; ks++) {
                unsigned bf[8][2];
#pragma unroll
                for (int nt = 0; nt < 8; nt++) {
                    const unsigned* bp = Bt + (nt * 8 + g) * YSTR + ks * 8;
                    bf[nt][0] = bp[tig]; bf[nt][1] = bp[tig + 4];
                }
#pragma unroll
                for (int mt = 0; mt < 2; mt++) {
                    const unsigned* ap = At + (wid * 32 + mt * 16 + g) * YSTR + ks * 8;
                    unsigned a0 = ap[tig], a2 = ap[tig + 4];
                    unsigned a1 = ap[8 * YSTR + tig], a3 = ap[8 * YSTR + tig + 4];
#pragma unroll
                    for (int nt = 0; nt < 8; nt++)
                        mma_h16(acc[mt][nt][0], acc[mt][nt][1], acc[mt][nt][2], acc[mt][nt][3],
                                a0, a1, a2, a3, bf[nt][0], bf[nt][1]);
                }
            }
        }
        __syncthreads();
    }

    // phase-2 role of sel: exp(dA[l])
    sel[tid] = __expf(sda[tid]);
    __syncthreads();

    // ---- phase 2: Y_off, 2 n-subtiles of 64 ----
    const float* pvb = pv + ((long)blockIdx.x << 13);
    for (int ns = 0; ns < 2; ns++) {
        int n0 = ns * 64;
#pragma unroll
        for (int it = 0; it < 32; it++) {
            int idx = it * 256 + tid;
            int np = idx & 31, l = idx >> 5;
            float el = sel[l];
            float2 v = *(const float2*)&xbc[(long)(tb + l) * CDIM + DINNER + NST + n0 + 2 * np];
            At[l * YSTR + np] = f2h2(v.x * el, v.y * el);
        }
#pragma unroll
        for (int it = 0; it < 8; it++) {
            int idx = it * 256 + tid;
            int np = idx & 31, p = idx >> 5;
            float2 v = *(const float2*)&pvb[p * NST + n0 + 2 * np];
            Bt[p * YSTR + np] = f2h2(v.x, v.y);
        }
        __syncthreads();
#pragma unroll
        for (int ks = 0; ks < 4; ks++) {
            unsigned bf[8][2];
#pragma unroll
            for (int nt = 0; nt < 8; nt++) {
                const unsigned* bp = Bt + (nt * 8 + g) * YSTR + ks * 8;
                bf[nt][0] = bp[tig]; bf[nt][1] = bp[tig + 4];
            }
#pragma unroll
            for (int mt = 0; mt < 2; mt++) {
                const unsigned* ap = At + (wid * 32 + mt * 16 + g) * YSTR + ks * 8;
                unsigned a0 = ap[tig], a2 = ap[tig + 4];
                unsigned a1 = ap[8 * YSTR + tig], a3 = ap[8 * YSTR + tig + 4];
#pragma unroll
                for (int nt = 0; nt < 8; nt++)
                    mma_h16(acc[mt][nt][0], acc[mt][nt][1], acc[mt][nt][2], acc[mt][nt][3],
                            a0, a1, a2, a3, bf[nt][0], bf[nt][1]);
            }
        }
        __syncthreads();
    }

    // ---- epilogue: + D*x, gate silu(z) ----
    float dsk = Dsk[h];
#pragma unroll
    for (int mt = 0; mt < 2; mt++) {
#pragma unroll
        for (int nt = 0; nt < 8; nt++) {
            int col = nt * 8 + tig * 2;
#pragma unroll
            for (int rr = 0; rr < 2; rr++) {
                int l = wid * 32 + mt * 16 + g + rr * 8;
                int t = tb + l;
                float2 xv = *(const float2*)&xbc[(long)t * CDIM + h * HD + col];
                float2 zv = *(const float2*)&zx[(long)t * DPROJ + h * HD + col];
                float o0 = (acc[mt][nt][rr * 2 + 0] + xv.x * dsk) * fsilu(zv.x);
                float o1 = (acc[mt][nt][rr * 2 + 1] + xv.y * dsk) * fsilu(zv.y);
                *(float2*)&y[(long)t * DINNER + h * HD + col] = make_float2(o0, o1);
            }
        }
    }
}

// ---------------- RMSNorm: reads y fp32, writes normalized fp16 ----------------
__global__ void k_rms(const float* __restrict__ y, const float* __restrict__ nw,
                      __half* __restrict__ yh)
{
    int t = blockIdx.x;
    const float4* row = (const float4*)(y + (long)t * DINNER);
    const float4* nw4 = (const float4*)nw;
    float ss = 0.f;
    for (int i = threadIdx.x; i < DINNER / 4; i += 256) {
        float4 v = row[i];
        ss = fmaf(v.x, v.x, ss); ss = fmaf(v.y, v.y, ss);
        ss = fmaf(v.z, v.z, ss); ss = fmaf(v.w, v.w, ss);
    }
    __shared__ float red[256];
    red[threadIdx.x] = ss; __syncthreads();
    for (int o = 128; o > 0; o >>= 1) {
        if (threadIdx.x < o) red[threadIdx.x] += red[threadIdx.x + o];
        __syncthreads();
    }
    float sc = rsqrtf(red[0] / (float)DINNER + 1e-5f);
    uint2* oh = (uint2*)(yh + (long)t * DINNER);
    for (int i = threadIdx.x; i < DINNER / 4; i += 256) {
        float4 v = row[i], n = nw4[i];
        oh[i] = make_uint2(f2h2(v.x * sc * n.x, v.y * sc * n.y),
                           f2h2(v.z * sc * n.z, v.w * sc * n.w));
    }
}

// ---------------- launch ----------------
extern "C" void kernel_launch(void* const* d_in, const int* in_sizes, int n_in,
                              void* d_out, int out_size)
{
    const float* u     = (const float*)d_in[0];
    const float* Win   = (const float*)d_in[1];
    const float* convw = (const float*)d_in[2];
    const float* convb = (const float*)d_in[3];
    const float* dtb   = (const float*)d_in[4];
    const float* Alog  = (const float*)d_in[5];
    const float* Dsk   = (const float*)d_in[6];
    const float* nw    = (const float*)d_in[7];
    const float* Wout  = (const float*)d_in[8];
    float* out = (float*)d_out;

    static float *zx = nullptr, *xbc, *dt, *dacs, *cb, *st, *pv, *y;
    static __half *uh, *winh, *wouth, *bch, *yh;
    if (!zx) {
        cudaGetSymbolAddress((void**)&xbc,   g_xbc);
        cudaGetSymbolAddress((void**)&dt,    g_dtv);
        cudaGetSymbolAddress((void**)&dacs,  g_dacs);
        cudaGetSymbolAddress((void**)&cb,    g_cb);
        cudaGetSymbolAddress((void**)&st,    g_st);
        cudaGetSymbolAddress((void**)&pv,    g_pv);
        cudaGetSymbolAddress((void**)&y,     g_y);
        cudaGetSymbolAddress((void**)&uh,    g_uh);
        cudaGetSymbolAddress((void**)&winh,  g_winh);
        cudaGetSymbolAddress((void**)&wouth, g_wouth);
        cudaGetSymbolAddress((void**)&bch,   g_bch);
        cudaGetSymbolAddress((void**)&yh,    g_yh);
        cudaGetSymbolAddress((void**)&zx,    g_zx);
    }

    // 0) fp16 conversions of GEMM operands
    k_cvt<<<(TOK * DMODEL / 4 + 255) / 256, 256>>>(u, uh, TOK * DMODEL / 4);
    k_cvt<<<(DPROJ * DMODEL / 4 + 255) / 256, 256>>>(Win, winh, DPROJ * DMODEL / 4);
    k_cvt<<<(DMODEL * DINNER / 4 + 255) / 256, 256>>>(Wout, wouth, DMODEL * DINNER / 4);

    // 1) in_proj: zx = u @ Win^T   (M=4096, N=8512, K=2048)
    gemm_h16n<<<dim3((DPROJ + 127) / 128, TOK / 128, 1), 256>>>(uh, winh, zx,
        DMODEL, DMODEL, DMODEL, DPROJ, DPROJ, 0, 0, 0);

    // 2) conv + silu (4 channels/thread, emits fp16 B|C slice)
    k_conv<<<(TOK * C4 + 255) / 256, 256>>>(zx, convw, convb, xbc, bch);

    // 3) softplus(dt) + dA cumsum (fused)
    k_dacs<<<NCC * NH, CK>>>(zx, dtb, Alog, dt, dacs);

    // 4) CB^T[cc][s][l] = B[s]·C[l]   (batched, fp16-native; M=256,N=256,K=128)
    gemm_h16n<<<dim3(CK / 128, CK / 128, NCC), 256>>>(bch, bch + NST, cb,
        NST, 2 * NST, 2 * NST, CK, CK, (long)CK * 2 * NST, (long)CK * 2 * NST, (long)CK * CK);

    // 5) chunk states (tensor-core)
    k_states_mma<<<NCC * NH, 256>>>(xbc, dt, dacs, st);

    // 6) inter-chunk scan (4x parallelism)
    k_scan<<<2 * NH * 4, 256>>>(st, dacs, pv);

    // 7) Y = Y_diag + Y_off + skip, gated  (tensor-core)
    k_y_mma<<<NCC * NH, 256>>>(xbc, zx, dt, dacs, cb, pv, Dsk, y);

    // 8) RMSNorm -> fp16
    k_rms<<<TOK, 256>>>(y, nw, yh);

    // 9) out_proj: out = yh @ Wout^T  (M=4096, N=2048, K=4096)
    gemm_h16n<<<dim3(DMODEL / 128, TOK / 128, 1), 256>>>(yh, wouth, out,
        DINNER, DINNER, DINNER, DMODEL, DMODEL, 0, 0, 0);
}